// round 2
// baseline (speedup 1.0000x reference)
#include <cuda_runtime.h>
#include <math.h>

// Problem constants
#define BV 4
#define TT 2048
#define CCH 1024
#define DA 1024
#define NH 16
#define HDM 64
#define MM (BV * TT)   // 8192 rows

// Scratch (allocations are forbidden; __device__ globals are the sanctioned path)
__device__ float g_qkv[(size_t)MM * 3 * DA];   // ~100.6 MB
__device__ float g_attn[(size_t)MM * DA];      // ~33.5 MB

// ---------------------------------------------------------------------------
// SGEMM: C[M,N] = A[M,K] * B[K,N] + bias[N]   (row-major, all dims % tile == 0)
// 128x128 block tile, BK=8, 256 threads, 8x8 register microtile.
// ---------------------------------------------------------------------------
__global__ __launch_bounds__(256) void sgemm_bias(
    const float* __restrict__ A, const float* __restrict__ Bm,
    const float* __restrict__ bias, float* __restrict__ C,
    int M, int N, int K)
{
    __shared__ float As[8][128];
    __shared__ float Bs[8][128];

    const int tid = threadIdx.x;
    const int bc = blockIdx.x, br = blockIdx.y;

    const float* Ag = A + (size_t)br * 128 * K;
    const float* Bg = Bm + (size_t)bc * 128;

    const int arow = tid >> 1, acol = (tid & 1) * 4;    // A tile 128x8
    const int brow = tid >> 5, bcol = (tid & 31) * 4;   // B tile 8x128
    const int trow = (tid >> 4) * 8, tcol = (tid & 15) * 8;

    float acc[8][8];
    #pragma unroll
    for (int i = 0; i < 8; i++)
        #pragma unroll
        for (int j = 0; j < 8; j++) acc[i][j] = 0.f;

    for (int k0 = 0; k0 < K; k0 += 8) {
        float4 a4 = *(const float4*)(Ag + (size_t)arow * K + k0 + acol);
        As[acol + 0][arow] = a4.x;
        As[acol + 1][arow] = a4.y;
        As[acol + 2][arow] = a4.z;
        As[acol + 3][arow] = a4.w;
        *(float4*)&Bs[brow][bcol] =
            *(const float4*)(Bg + (size_t)(k0 + brow) * N + bcol);
        __syncthreads();

        #pragma unroll
        for (int k = 0; k < 8; k++) {
            float ra[8], rb[8];
            // Batch the 4 LDS.128 up front, then the 64 FMAs
            *(float4*)&ra[0] = *(const float4*)&As[k][trow];
            *(float4*)&ra[4] = *(const float4*)&As[k][trow + 4];
            *(float4*)&rb[0] = *(const float4*)&Bs[k][tcol];
            *(float4*)&rb[4] = *(const float4*)&Bs[k][tcol + 4];
            #pragma unroll
            for (int i = 0; i < 8; i++)
                #pragma unroll
                for (int j = 0; j < 8; j++)
                    acc[i][j] = fmaf(ra[i], rb[j], acc[i][j]);
        }
        __syncthreads();
    }

    float* Cg = C + (size_t)(br * 128 + trow) * N + bc * 128 + tcol;
    const float* bp = bias + bc * 128 + tcol;
    #pragma unroll
    for (int i = 0; i < 8; i++) {
        #pragma unroll
        for (int j = 0; j < 8; j += 4) {
            float4 v;
            v.x = acc[i][j + 0] + bp[j + 0];
            v.y = acc[i][j + 1] + bp[j + 1];
            v.z = acc[i][j + 2] + bp[j + 2];
            v.w = acc[i][j + 3] + bp[j + 3];
            *(float4*)(Cg + (size_t)i * N + j) = v;
        }
    }
}

// ---------------------------------------------------------------------------
// Flash attention (causal), fp32. One block = (b, h, 64-row Q tile).
// 256 threads: thread -> qrow = tid/4, column group cg = tid%4 (cols cg+4*cc).
// Smem rows padded to 68 floats: float4 LDS with this mapping is conflict-free.
// ---------------------------------------------------------------------------
#define FPAD 68
#define FLASH_SMEM (4 * 64 * FPAD * sizeof(float))   // Q, K, P, Vt = 69632 B

__global__ __launch_bounds__(256) void flash_kernel(
    const float* __restrict__ qkv, float* __restrict__ out)
{
    extern __shared__ float sm[];
    float* Qs = sm;
    float* Ks = sm + 64 * FPAD;
    float* Ps = sm + 2 * 64 * FPAD;
    float* Vt = sm + 3 * 64 * FPAD;   // transposed: Vt[d][c]

    const int tid = threadIdx.x;
    const int qt = blockIdx.x;   // q tile index (0..31)
    const int h  = blockIdx.y;
    const int b  = blockIdx.z;
    const int qrow = tid >> 2;
    const int cg   = tid & 3;

    const size_t rstride = 3 * DA;
    const float* qbase = qkv + ((size_t)(b * TT + qt * 64)) * rstride + h * HDM;

    // Load Q tile, scale folded in (1/sqrt(64) = 0.125)
    #pragma unroll
    for (int i = 0; i < 16; i++) {
        int lin = i * 256 + tid;
        int r = lin >> 6, d = lin & 63;
        Qs[r * FPAD + d] = qbase[(size_t)r * rstride + d] * 0.125f;
    }

    float o[16];
    #pragma unroll
    for (int i = 0; i < 16; i++) o[i] = 0.f;
    float mrow = -INFINITY, lrow = 0.f;

    for (int j = 0; j <= qt; j++) {
        __syncthreads();   // protect Ks/Vt/Ps reuse from previous iteration
        const float* kbase = qkv + ((size_t)(b * TT + j * 64)) * rstride + DA + h * HDM;
        const float* vbase = kbase + DA;
        #pragma unroll
        for (int i = 0; i < 16; i++) {
            int lin = i * 256 + tid;
            int r = lin >> 6, d = lin & 63;
            Ks[r * FPAD + d] = kbase[(size_t)r * rstride + d];
            Vt[d * FPAD + r] = vbase[(size_t)r * rstride + d];
        }
        __syncthreads();

        // S = Q K^T for this thread's 16 columns (c = cg + 4*cc)
        float s[16];
        #pragma unroll
        for (int cc = 0; cc < 16; cc++) s[cc] = 0.f;
        #pragma unroll
        for (int d4 = 0; d4 < 16; d4++) {
            float4 q4 = *(const float4*)(Qs + qrow * FPAD + d4 * 4);
            #pragma unroll
            for (int cc = 0; cc < 16; cc++) {
                float4 k4 = *(const float4*)(Ks + (cg + 4 * cc) * FPAD + d4 * 4);
                s[cc] += q4.x * k4.x + q4.y * k4.y + q4.z * k4.z + q4.w * k4.w;
            }
        }

        // Causal mask on the diagonal tile
        if (j == qt) {
            #pragma unroll
            for (int cc = 0; cc < 16; cc++)
                if (cg + 4 * cc > qrow) s[cc] = -INFINITY;
        }

        // Online softmax stats (row split across 4 lanes = lane bits 0,1)
        float mloc = s[0];
        #pragma unroll
        for (int cc = 1; cc < 16; cc++) mloc = fmaxf(mloc, s[cc]);
        mloc = fmaxf(mloc, __shfl_xor_sync(0xffffffffu, mloc, 1));
        mloc = fmaxf(mloc, __shfl_xor_sync(0xffffffffu, mloc, 2));
        float mnew  = fmaxf(mrow, mloc);
        float alpha = __expf(mrow - mnew);   // first iter: exp(-inf)=0
        float psum = 0.f;
        #pragma unroll
        for (int cc = 0; cc < 16; cc++) {
            float p = __expf(s[cc] - mnew);
            s[cc] = p;
            psum += p;
        }
        psum += __shfl_xor_sync(0xffffffffu, psum, 1);
        psum += __shfl_xor_sync(0xffffffffu, psum, 2);
        lrow = lrow * alpha + psum;
        mrow = mnew;
        #pragma unroll
        for (int i = 0; i < 16; i++) o[i] *= alpha;

        // Stage P through smem so every thread sees the full row for PV
        #pragma unroll
        for (int cc = 0; cc < 16; cc++)
            Ps[qrow * FPAD + cg + 4 * cc] = s[cc];
        __syncthreads();

        // O += P V   (thread owns head-dims dc = cg + 4*jj)
        #pragma unroll
        for (int c4 = 0; c4 < 16; c4++) {
            float4 p4 = *(const float4*)(Ps + qrow * FPAD + c4 * 4);
            #pragma unroll
            for (int jj = 0; jj < 16; jj++) {
                float4 v4 = *(const float4*)(Vt + (cg + 4 * jj) * FPAD + c4 * 4);
                o[jj] += p4.x * v4.x + p4.y * v4.y + p4.z * v4.z + p4.w * v4.w;
            }
        }
    }

    const float inv = 1.f / lrow;
    float* obase = out + ((size_t)(b * TT + qt * 64 + qrow)) * DA + h * HDM + cg;
    #pragma unroll
    for (int jj = 0; jj < 16; jj++)
        obase[4 * jj] = o[jj] * inv;
}

// ---------------------------------------------------------------------------
// Launch: QKV GEMM -> flash attention -> output GEMM. All graph-capturable.
// Inputs (metadata order): x, mask (unused; causal applied analytically),
// W_qkv, b_qkv, W_out, b_out.
// ---------------------------------------------------------------------------
extern "C" void kernel_launch(void* const* d_in, const int* in_sizes, int n_in,
                              void* d_out, int out_size)
{
    const float* x    = (const float*)d_in[0];
    const float* Wqkv = (const float*)d_in[2];
    const float* bqkv = (const float*)d_in[3];
    const float* Wout = (const float*)d_in[4];
    const float* bout = (const float*)d_in[5];
    float* out = (float*)d_out;

    float *qkvbuf = nullptr, *attnbuf = nullptr;
    cudaGetSymbolAddress((void**)&qkvbuf, g_qkv);
    cudaGetSymbolAddress((void**)&attnbuf, g_attn);

    cudaFuncSetAttribute(flash_kernel,
                         cudaFuncAttributeMaxDynamicSharedMemorySize,
                         (int)FLASH_SMEM);

    dim3 g1(3 * DA / 128, MM / 128);
    sgemm_bias<<<g1, 256>>>(x, Wqkv, bqkv, qkvbuf, MM, 3 * DA, CCH);

    dim3 g2(TT / 64, NH, BV);
    flash_kernel<<<g2, 256, FLASH_SMEM>>>(qkvbuf, attnbuf);

    dim3 g3(CCH / 128, MM / 128);
    sgemm_bias<<<g3, 256>>>(attnbuf, Wout, bout, out, MM, CCH, DA);
}

// round 4
// speedup vs baseline: 1.2419x; 1.2419x over previous
#include <cuda_runtime.h>
#include <cuda_bf16.h>
#include <math.h>
#include <stdint.h>

// Problem constants
#define BV 4
#define TT 2048
#define CCH 1024
#define DA 1024
#define NH 16
#define HDM 64
#define MM (BV * TT)   // 8192 rows

// ---------------------------------------------------------------------------
// Device scratch (allocations forbidden; __device__ globals are sanctioned)
// ---------------------------------------------------------------------------
__device__ float g_qkv[(size_t)MM * 3 * DA];              // fp32 qkv
__device__ float g_attn[(size_t)MM * DA];                 // fp32 attn out
__device__ __nv_bfloat16 g_ah[(size_t)MM * CCH];          // A split hi
__device__ __nv_bfloat16 g_al[(size_t)MM * CCH];          // A split lo
__device__ __nv_bfloat16 g_bh[(size_t)CCH * 3 * DA];      // W^T split hi
__device__ __nv_bfloat16 g_bl[(size_t)CCH * 3 * DA];      // W^T split lo

__device__ __forceinline__ uint32_t smem_u32(const void* p) {
    uint32_t a;
    asm("{ .reg .u64 t; cvta.to.shared.u64 t, %1; cvt.u32.u64 %0, t; }"
        : "=r"(a) : "l"(p));
    return a;
}

#define LDSM_X4(r, addr) \
    asm volatile("ldmatrix.sync.aligned.m8n8.x4.shared.b16 {%0,%1,%2,%3}, [%4];" \
        : "=r"((r)[0]), "=r"((r)[1]), "=r"((r)[2]), "=r"((r)[3]) : "r"(addr))

#define MMA16816(c, a, b0, b1) \
    asm volatile("mma.sync.aligned.m16n8k16.row.col.f32.bf16.bf16.f32 " \
        "{%0,%1,%2,%3}, {%4,%5,%6,%7}, {%8,%9}, {%0,%1,%2,%3};" \
        : "+f"((c)[0]), "+f"((c)[1]), "+f"((c)[2]), "+f"((c)[3]) \
        : "r"((a)[0]), "r"((a)[1]), "r"((a)[2]), "r"((a)[3]), "r"(b0), "r"(b1))

// ---------------------------------------------------------------------------
// Split kernels: fp32 -> (bf16 hi, bf16 lo)
// ---------------------------------------------------------------------------
__global__ void split_f4(const float* __restrict__ src,
                         __nv_bfloat16* __restrict__ hi,
                         __nv_bfloat16* __restrict__ lo, int n4)
{
    int i = blockIdx.x * blockDim.x + threadIdx.x;
    if (i >= n4) return;
    float4 v = ((const float4*)src)[i];
    __nv_bfloat16 h0 = __float2bfloat16(v.x), h1 = __float2bfloat16(v.y);
    __nv_bfloat16 h2 = __float2bfloat16(v.z), h3 = __float2bfloat16(v.w);
    __nv_bfloat16 l0 = __float2bfloat16(v.x - __bfloat162float(h0));
    __nv_bfloat16 l1 = __float2bfloat16(v.y - __bfloat162float(h1));
    __nv_bfloat16 l2 = __float2bfloat16(v.z - __bfloat162float(h2));
    __nv_bfloat16 l3 = __float2bfloat16(v.w - __bfloat162float(h3));
    ((__nv_bfloat162*)hi)[2 * i]     = __nv_bfloat162(h0, h1);
    ((__nv_bfloat162*)hi)[2 * i + 1] = __nv_bfloat162(h2, h3);
    ((__nv_bfloat162*)lo)[2 * i]     = __nv_bfloat162(l0, l1);
    ((__nv_bfloat162*)lo)[2 * i + 1] = __nv_bfloat162(l2, l3);
}

// W[K][N] (row-major) -> Th/Tl[N][K] with split. 32x32 smem-tiled transpose.
__global__ void transpose_split(const float* __restrict__ W,
                                __nv_bfloat16* __restrict__ Th,
                                __nv_bfloat16* __restrict__ Tl, int K, int N)
{
    __shared__ float tile[32][33];
    int tx = threadIdx.x, ty = threadIdx.y;
    int n0 = blockIdx.x * 32, k0 = blockIdx.y * 32;
    #pragma unroll
    for (int j = 0; j < 32; j += 8)
        tile[ty + j][tx] = W[(size_t)(k0 + ty + j) * N + n0 + tx];
    __syncthreads();
    #pragma unroll
    for (int j = 0; j < 32; j += 8) {
        float v = tile[tx][ty + j];
        __nv_bfloat16 h = __float2bfloat16(v);
        __nv_bfloat16 l = __float2bfloat16(v - __bfloat162float(h));
        size_t o = (size_t)(n0 + ty + j) * K + k0 + tx;
        Th[o] = h;
        Tl[o] = l;
    }
}

// ---------------------------------------------------------------------------
// mma.sync split-bf16 GEMM: C[M,N] = A[M,K] @ B[N,K]^T + bias
// CTA 128x128, 8 warps (2x4), warp tile 64x32, KC=32, double-buffered smem.
// Smem pitch = 40 bf16 (80 B) so every ldmatrix row address is 16B-aligned.
// ---------------------------------------------------------------------------
#define KC 32
#define PP 40                               // smem pitch in bf16
#define MAT_B (128 * PP * 2)                // 10240 B per matrix tile
#define STAGE_B (4 * MAT_B)                 // Ah, Al, Bh, Bl
#define GEMM_DYN (2 * STAGE_B)              // 81920 B

static __device__ __forceinline__ void load_chunk(
    char* sm, const __nv_bfloat16* Ah, const __nv_bfloat16* Al,
    const __nv_bfloat16* Bh, const __nv_bfloat16* Bl,
    int arow0, int brow0, int K, int k0, int tid)
{
    const __nv_bfloat16* srcs[4] = {
        Ah + (size_t)arow0 * K, Al + (size_t)arow0 * K,
        Bh + (size_t)brow0 * K, Bl + (size_t)brow0 * K };
    #pragma unroll
    for (int t = 0; t < 4; t++) {
        const __nv_bfloat16* s = srcs[t];
        char* tb = sm + t * MAT_B;
        #pragma unroll
        for (int p = 0; p < 2; p++) {
            int idx = p * 256 + tid;
            int row = idx >> 2, c16 = idx & 3;      // 4 x 16B per 32-elem row
            uint4 v = *(const uint4*)(s + (size_t)row * K + k0 + c16 * 8);
            *(uint4*)(tb + row * (PP * 2) + c16 * 16) = v;
        }
    }
}

__global__ __launch_bounds__(256, 1) void gemm_mma(
    const __nv_bfloat16* __restrict__ Ah, const __nv_bfloat16* __restrict__ Al,
    const __nv_bfloat16* __restrict__ Bh, const __nv_bfloat16* __restrict__ Bl,
    const float* __restrict__ bias, float* __restrict__ C,
    int M, int N, int K)
{
    extern __shared__ char dyn[];
    const int tid = threadIdx.x;
    const int wid = tid >> 5, l = tid & 31;
    const int warp_m = wid & 1, warp_n = wid >> 1;   // 2 x 4 warp grid
    const int bc = blockIdx.x, br = blockIdx.y;
    const int arow0 = br * 128, bcol0 = bc * 128;

    // ldmatrix lane offset decomposition (non-trans, x4)
    const int mat = l >> 3;
    const int dr  = (mat & 1) * 8 + (l & 7);   // A: row offset
    const int dka = (mat >> 1) * 8;            // A: k offset
    const int dn  = (mat >> 1) * 8 + (l & 7);  // B: n offset
    const int dkb = (mat & 1) * 8;             // B: k offset

    float acc[4][4][4];
    #pragma unroll
    for (int i = 0; i < 4; i++)
        #pragma unroll
        for (int j = 0; j < 4; j++)
            #pragma unroll
            for (int q = 0; q < 4; q++) acc[i][j][q] = 0.f;

    const uint32_t sbase = smem_u32(dyn);
    const int NCH = K / KC;

    load_chunk(dyn, Ah, Al, Bh, Bl, arow0, bcol0, K, 0, tid);
    __syncthreads();

    for (int c = 0; c < NCH; c++) {
        const int b = c & 1;
        // Prefetch next chunk into the other buffer (LDG/STS overlap with MMA)
        if (c + 1 < NCH)
            load_chunk(dyn + (b ^ 1) * STAGE_B, Ah, Al, Bh, Bl,
                       arow0, bcol0, K, (c + 1) * KC, tid);

        const uint32_t st = sbase + (uint32_t)b * STAGE_B;
        const uint32_t aAh = st + 0 * MAT_B;
        const uint32_t aAl = st + 1 * MAT_B;
        const uint32_t aBh = st + 2 * MAT_B;
        const uint32_t aBl = st + 3 * MAT_B;

        #pragma unroll
        for (int ks = 0; ks < KC / 16; ks++) {
            const int k0 = ks * 16;
            uint32_t ahf[4][4], alf[4][4];
            uint32_t bhf[2][4], blf[2][4];
            #pragma unroll
            for (int mt = 0; mt < 4; mt++) {
                uint32_t ao = (uint32_t)((warp_m * 64 + mt * 16 + dr) * PP
                                         + k0 + dka) * 2;
                LDSM_X4(ahf[mt], aAh + ao);
                LDSM_X4(alf[mt], aAl + ao);
            }
            #pragma unroll
            for (int pr = 0; pr < 2; pr++) {
                uint32_t bo = (uint32_t)((warp_n * 32 + pr * 16 + dn) * PP
                                         + k0 + dkb) * 2;
                LDSM_X4(bhf[pr], aBh + bo);
                LDSM_X4(blf[pr], aBl + bo);
            }
            #pragma unroll
            for (int mt = 0; mt < 4; mt++)
                #pragma unroll
                for (int nt = 0; nt < 4; nt++) {
                    const int pr = nt >> 1, sb2 = (nt & 1) * 2;
                    MMA16816(acc[mt][nt], ahf[mt], bhf[pr][sb2], bhf[pr][sb2 + 1]);
                    MMA16816(acc[mt][nt], ahf[mt], blf[pr][sb2], blf[pr][sb2 + 1]);
                    MMA16816(acc[mt][nt], alf[mt], bhf[pr][sb2], bhf[pr][sb2 + 1]);
                }
        }
        __syncthreads();
    }

    // Epilogue: acc lane layout -> global
    const int rbase = arow0 + warp_m * 64 + (l >> 2);
    const int cbase = bcol0 + warp_n * 32 + (l & 3) * 2;
    #pragma unroll
    for (int mt = 0; mt < 4; mt++)
        #pragma unroll
        for (int nt = 0; nt < 4; nt++) {
            const int row = rbase + mt * 16;
            const int col = cbase + nt * 8;
            float2 v0, v1;
            v0.x = acc[mt][nt][0] + bias[col];
            v0.y = acc[mt][nt][1] + bias[col + 1];
            v1.x = acc[mt][nt][2] + bias[col];
            v1.y = acc[mt][nt][3] + bias[col + 1];
            *(float2*)(C + (size_t)row * N + col) = v0;
            *(float2*)(C + (size_t)(row + 8) * N + col) = v1;
        }
}

// ---------------------------------------------------------------------------
// Flash attention (causal), fp32 — unchanged from passing round 2.
// ---------------------------------------------------------------------------
#define FPAD 68
#define FLASH_SMEM (4 * 64 * FPAD * sizeof(float))   // 69632 B

__global__ __launch_bounds__(256) void flash_kernel(
    const float* __restrict__ qkv, float* __restrict__ out)
{
    extern __shared__ float sm[];
    float* Qs = sm;
    float* Ks = sm + 64 * FPAD;
    float* Ps = sm + 2 * 64 * FPAD;
    float* Vt = sm + 3 * 64 * FPAD;

    const int tid = threadIdx.x;
    const int qt = blockIdx.x;
    const int h  = blockIdx.y;
    const int b  = blockIdx.z;
    const int qrow = tid >> 2;
    const int cg   = tid & 3;

    const size_t rstride = 3 * DA;
    const float* qbase = qkv + ((size_t)(b * TT + qt * 64)) * rstride + h * HDM;

    #pragma unroll
    for (int i = 0; i < 16; i++) {
        int lin = i * 256 + tid;
        int r = lin >> 6, d = lin & 63;
        Qs[r * FPAD + d] = qbase[(size_t)r * rstride + d] * 0.125f;
    }

    float o[16];
    #pragma unroll
    for (int i = 0; i < 16; i++) o[i] = 0.f;
    float mrow = -INFINITY, lrow = 0.f;

    for (int j = 0; j <= qt; j++) {
        __syncthreads();
        const float* kbase = qkv + ((size_t)(b * TT + j * 64)) * rstride + DA + h * HDM;
        const float* vbase = kbase + DA;
        #pragma unroll
        for (int i = 0; i < 16; i++) {
            int lin = i * 256 + tid;
            int r = lin >> 6, d = lin & 63;
            Ks[r * FPAD + d] = kbase[(size_t)r * rstride + d];
            Vt[d * FPAD + r] = vbase[(size_t)r * rstride + d];
        }
        __syncthreads();

        float s[16];
        #pragma unroll
        for (int cc = 0; cc < 16; cc++) s[cc] = 0.f;
        #pragma unroll
        for (int d4 = 0; d4 < 16; d4++) {
            float4 q4 = *(const float4*)(Qs + qrow * FPAD + d4 * 4);
            #pragma unroll
            for (int cc = 0; cc < 16; cc++) {
                float4 k4 = *(const float4*)(Ks + (cg + 4 * cc) * FPAD + d4 * 4);
                s[cc] += q4.x * k4.x + q4.y * k4.y + q4.z * k4.z + q4.w * k4.w;
            }
        }

        if (j == qt) {
            #pragma unroll
            for (int cc = 0; cc < 16; cc++)
                if (cg + 4 * cc > qrow) s[cc] = -INFINITY;
        }

        float mloc = s[0];
        #pragma unroll
        for (int cc = 1; cc < 16; cc++) mloc = fmaxf(mloc, s[cc]);
        mloc = fmaxf(mloc, __shfl_xor_sync(0xffffffffu, mloc, 1));
        mloc = fmaxf(mloc, __shfl_xor_sync(0xffffffffu, mloc, 2));
        float mnew  = fmaxf(mrow, mloc);
        float alpha = __expf(mrow - mnew);
        float psum = 0.f;
        #pragma unroll
        for (int cc = 0; cc < 16; cc++) {
            float p = __expf(s[cc] - mnew);
            s[cc] = p;
            psum += p;
        }
        psum += __shfl_xor_sync(0xffffffffu, psum, 1);
        psum += __shfl_xor_sync(0xffffffffu, psum, 2);
        lrow = lrow * alpha + psum;
        mrow = mnew;
        #pragma unroll
        for (int i = 0; i < 16; i++) o[i] *= alpha;

        #pragma unroll
        for (int cc = 0; cc < 16; cc++)
            Ps[qrow * FPAD + cg + 4 * cc] = s[cc];
        __syncthreads();

        #pragma unroll
        for (int c4 = 0; c4 < 16; c4++) {
            float4 p4 = *(const float4*)(Ps + qrow * FPAD + c4 * 4);
            #pragma unroll
            for (int jj = 0; jj < 16; jj++) {
                float4 v4 = *(const float4*)(Vt + (cg + 4 * jj) * FPAD + c4 * 4);
                o[jj] += p4.x * v4.x + p4.y * v4.y + p4.z * v4.z + p4.w * v4.w;
            }
        }
    }

    const float inv = 1.f / lrow;
    float* obase = out + ((size_t)(b * TT + qt * 64 + qrow)) * DA + h * HDM + cg;
    #pragma unroll
    for (int jj = 0; jj < 16; jj++)
        obase[4 * jj] = o[jj] * inv;
}

// ---------------------------------------------------------------------------
// Launch: split(x, Wqkv) -> gemm_mma -> flash -> split(attn, Wout) -> gemm_mma
// Inputs: x, mask (unused; causal applied analytically), W_qkv, b_qkv, W_out, b_out
// ---------------------------------------------------------------------------
extern "C" void kernel_launch(void* const* d_in, const int* in_sizes, int n_in,
                              void* d_out, int out_size)
{
    const float* x    = (const float*)d_in[0];
    const float* Wqkv = (const float*)d_in[2];
    const float* bqkv = (const float*)d_in[3];
    const float* Wout = (const float*)d_in[4];
    const float* bout = (const float*)d_in[5];
    float* out = (float*)d_out;

    float *qkvbuf = nullptr, *attnbuf = nullptr;
    __nv_bfloat16 *ah, *al, *bh, *bl;
    cudaGetSymbolAddress((void**)&qkvbuf, g_qkv);
    cudaGetSymbolAddress((void**)&attnbuf, g_attn);
    cudaGetSymbolAddress((void**)&ah, g_ah);
    cudaGetSymbolAddress((void**)&al, g_al);
    cudaGetSymbolAddress((void**)&bh, g_bh);
    cudaGetSymbolAddress((void**)&bl, g_bl);

    cudaFuncSetAttribute(flash_kernel,
                         cudaFuncAttributeMaxDynamicSharedMemorySize, (int)FLASH_SMEM);
    cudaFuncSetAttribute(gemm_mma,
                         cudaFuncAttributeMaxDynamicSharedMemorySize, (int)GEMM_DYN);

    // Phase 1: QKV = x @ Wqkv + b
    split_f4<<<(MM * CCH / 4 + 255) / 256, 256>>>(x, ah, al, MM * CCH / 4);
    transpose_split<<<dim3(3 * DA / 32, CCH / 32), dim3(32, 8)>>>(Wqkv, bh, bl, CCH, 3 * DA);
    gemm_mma<<<dim3(3 * DA / 128, MM / 128), 256, GEMM_DYN>>>(
        ah, al, bh, bl, bqkv, qkvbuf, MM, 3 * DA, CCH);

    // Phase 2: attention
    flash_kernel<<<dim3(TT / 64, NH, BV), 256, FLASH_SMEM>>>(qkvbuf, attnbuf);

    // Phase 3: out = attn @ Wout + b
    split_f4<<<(MM * DA / 4 + 255) / 256, 256>>>(attnbuf, ah, al, MM * DA / 4);
    transpose_split<<<dim3(CCH / 32, DA / 32), dim3(32, 8)>>>(Wout, bh, bl, DA, CCH);
    gemm_mma<<<dim3(CCH / 128, MM / 128), 256, GEMM_DYN>>>(
        ah, al, bh, bl, bout, out, MM, CCH, DA);
}

// round 5
// speedup vs baseline: 3.1327x; 2.5225x over previous
#include <cuda_runtime.h>
#include <cuda_bf16.h>
#include <cuda_fp16.h>
#include <math.h>
#include <stdint.h>

// Problem constants
#define BV 4
#define TT 2048
#define CCH 1024
#define DA 1024
#define NH 16
#define HDM 64
#define MM (BV * TT)   // 8192 rows

// ---------------------------------------------------------------------------
// Device scratch (allocations forbidden; __device__ globals are sanctioned)
// ---------------------------------------------------------------------------
__device__ float g_qkv[(size_t)MM * 3 * DA];              // fp32 qkv
__device__ float g_attn[(size_t)MM * DA];                 // fp32 attn out
__device__ __nv_bfloat16 g_ah[(size_t)MM * CCH];          // A split hi
__device__ __nv_bfloat16 g_al[(size_t)MM * CCH];          // A split lo
__device__ __nv_bfloat16 g_bh[(size_t)CCH * 3 * DA];      // W^T split hi
__device__ __nv_bfloat16 g_bl[(size_t)CCH * 3 * DA];      // W^T split lo

__device__ __forceinline__ uint32_t smem_u32(const void* p) {
    uint32_t a;
    asm("{ .reg .u64 t; cvta.to.shared.u64 t, %1; cvt.u32.u64 %0, t; }"
        : "=r"(a) : "l"(p));
    return a;
}

#define LDSM_X4(r, addr) \
    asm volatile("ldmatrix.sync.aligned.m8n8.x4.shared.b16 {%0,%1,%2,%3}, [%4];" \
        : "=r"((r)[0]), "=r"((r)[1]), "=r"((r)[2]), "=r"((r)[3]) : "r"(addr))

#define LDSM_X4_T(r, addr) \
    asm volatile("ldmatrix.sync.aligned.m8n8.x4.trans.shared.b16 {%0,%1,%2,%3}, [%4];" \
        : "=r"((r)[0]), "=r"((r)[1]), "=r"((r)[2]), "=r"((r)[3]) : "r"(addr))

#define MMA16816(c, a, b0, b1) \
    asm volatile("mma.sync.aligned.m16n8k16.row.col.f32.bf16.bf16.f32 " \
        "{%0,%1,%2,%3}, {%4,%5,%6,%7}, {%8,%9}, {%0,%1,%2,%3};" \
        : "+f"((c)[0]), "+f"((c)[1]), "+f"((c)[2]), "+f"((c)[3]) \
        : "r"((a)[0]), "r"((a)[1]), "r"((a)[2]), "r"((a)[3]), "r"(b0), "r"(b1))

#define MMA16816H(c, a, b0, b1) \
    asm volatile("mma.sync.aligned.m16n8k16.row.col.f32.f16.f16.f32 " \
        "{%0,%1,%2,%3}, {%4,%5,%6,%7}, {%8,%9}, {%0,%1,%2,%3};" \
        : "+f"((c)[0]), "+f"((c)[1]), "+f"((c)[2]), "+f"((c)[3]) \
        : "r"((a)[0]), "r"((a)[1]), "r"((a)[2]), "r"((a)[3]), "r"(b0), "r"(b1))

__device__ __forceinline__ uint32_t packh2(float a, float b) {
    __half2 h = __floats2half2_rn(a, b);
    return *(uint32_t*)&h;
}

// ---------------------------------------------------------------------------
// Split kernels: fp32 -> (bf16 hi, bf16 lo)
// ---------------------------------------------------------------------------
__global__ void split_f4(const float* __restrict__ src,
                         __nv_bfloat16* __restrict__ hi,
                         __nv_bfloat16* __restrict__ lo, int n4)
{
    int i = blockIdx.x * blockDim.x + threadIdx.x;
    if (i >= n4) return;
    float4 v = ((const float4*)src)[i];
    __nv_bfloat16 h0 = __float2bfloat16(v.x), h1 = __float2bfloat16(v.y);
    __nv_bfloat16 h2 = __float2bfloat16(v.z), h3 = __float2bfloat16(v.w);
    __nv_bfloat16 l0 = __float2bfloat16(v.x - __bfloat162float(h0));
    __nv_bfloat16 l1 = __float2bfloat16(v.y - __bfloat162float(h1));
    __nv_bfloat16 l2 = __float2bfloat16(v.z - __bfloat162float(h2));
    __nv_bfloat16 l3 = __float2bfloat16(v.w - __bfloat162float(h3));
    ((__nv_bfloat162*)hi)[2 * i]     = __nv_bfloat162(h0, h1);
    ((__nv_bfloat162*)hi)[2 * i + 1] = __nv_bfloat162(h2, h3);
    ((__nv_bfloat162*)lo)[2 * i]     = __nv_bfloat162(l0, l1);
    ((__nv_bfloat162*)lo)[2 * i + 1] = __nv_bfloat162(l2, l3);
}

// W[K][N] (row-major) -> Th/Tl[N][K] with split. 32x32 smem-tiled transpose.
__global__ void transpose_split(const float* __restrict__ W,
                                __nv_bfloat16* __restrict__ Th,
                                __nv_bfloat16* __restrict__ Tl, int K, int N)
{
    __shared__ float tile[32][33];
    int tx = threadIdx.x, ty = threadIdx.y;
    int n0 = blockIdx.x * 32, k0 = blockIdx.y * 32;
    #pragma unroll
    for (int j = 0; j < 32; j += 8)
        tile[ty + j][tx] = W[(size_t)(k0 + ty + j) * N + n0 + tx];
    __syncthreads();
    #pragma unroll
    for (int j = 0; j < 32; j += 8) {
        float v = tile[tx][ty + j];
        __nv_bfloat16 h = __float2bfloat16(v);
        __nv_bfloat16 l = __float2bfloat16(v - __bfloat162float(h));
        size_t o = (size_t)(n0 + ty + j) * K + k0 + tx;
        Th[o] = h;
        Tl[o] = l;
    }
}

// ---------------------------------------------------------------------------
// mma.sync split-bf16 GEMM (unchanged from passing round 4)
// ---------------------------------------------------------------------------
#define KC 32
#define PP 40
#define MAT_B (128 * PP * 2)
#define STAGE_B (4 * MAT_B)
#define GEMM_DYN (2 * STAGE_B)

static __device__ __forceinline__ void load_chunk(
    char* sm, const __nv_bfloat16* Ah, const __nv_bfloat16* Al,
    const __nv_bfloat16* Bh, const __nv_bfloat16* Bl,
    int arow0, int brow0, int K, int k0, int tid)
{
    const __nv_bfloat16* srcs[4] = {
        Ah + (size_t)arow0 * K, Al + (size_t)arow0 * K,
        Bh + (size_t)brow0 * K, Bl + (size_t)brow0 * K };
    #pragma unroll
    for (int t = 0; t < 4; t++) {
        const __nv_bfloat16* s = srcs[t];
        char* tb = sm + t * MAT_B;
        #pragma unroll
        for (int p = 0; p < 2; p++) {
            int idx = p * 256 + tid;
            int row = idx >> 2, c16 = idx & 3;
            uint4 v = *(const uint4*)(s + (size_t)row * K + k0 + c16 * 8);
            *(uint4*)(tb + row * (PP * 2) + c16 * 16) = v;
        }
    }
}

__global__ __launch_bounds__(256, 1) void gemm_mma(
    const __nv_bfloat16* __restrict__ Ah, const __nv_bfloat16* __restrict__ Al,
    const __nv_bfloat16* __restrict__ Bh, const __nv_bfloat16* __restrict__ Bl,
    const float* __restrict__ bias, float* __restrict__ C,
    int M, int N, int K)
{
    extern __shared__ char dyn[];
    const int tid = threadIdx.x;
    const int wid = tid >> 5, l = tid & 31;
    const int warp_m = wid & 1, warp_n = wid >> 1;
    const int bc = blockIdx.x, br = blockIdx.y;
    const int arow0 = br * 128, bcol0 = bc * 128;

    const int mat = l >> 3;
    const int dr  = (mat & 1) * 8 + (l & 7);
    const int dka = (mat >> 1) * 8;
    const int dn  = (mat >> 1) * 8 + (l & 7);
    const int dkb = (mat & 1) * 8;

    float acc[4][4][4];
    #pragma unroll
    for (int i = 0; i < 4; i++)
        #pragma unroll
        for (int j = 0; j < 4; j++)
            #pragma unroll
            for (int q = 0; q < 4; q++) acc[i][j][q] = 0.f;

    const uint32_t sbase = smem_u32(dyn);
    const int NCH = K / KC;

    load_chunk(dyn, Ah, Al, Bh, Bl, arow0, bcol0, K, 0, tid);
    __syncthreads();

    for (int c = 0; c < NCH; c++) {
        const int b = c & 1;
        if (c + 1 < NCH)
            load_chunk(dyn + (b ^ 1) * STAGE_B, Ah, Al, Bh, Bl,
                       arow0, bcol0, K, (c + 1) * KC, tid);

        const uint32_t st = sbase + (uint32_t)b * STAGE_B;
        const uint32_t aAh = st + 0 * MAT_B;
        const uint32_t aAl = st + 1 * MAT_B;
        const uint32_t aBh = st + 2 * MAT_B;
        const uint32_t aBl = st + 3 * MAT_B;

        #pragma unroll
        for (int ks = 0; ks < KC / 16; ks++) {
            const int k0 = ks * 16;
            uint32_t ahf[4][4], alf[4][4];
            uint32_t bhf[2][4], blf[2][4];
            #pragma unroll
            for (int mt = 0; mt < 4; mt++) {
                uint32_t ao = (uint32_t)((warp_m * 64 + mt * 16 + dr) * PP
                                         + k0 + dka) * 2;
                LDSM_X4(ahf[mt], aAh + ao);
                LDSM_X4(alf[mt], aAl + ao);
            }
            #pragma unroll
            for (int pr = 0; pr < 2; pr++) {
                uint32_t bo = (uint32_t)((warp_n * 32 + pr * 16 + dn) * PP
                                         + k0 + dkb) * 2;
                LDSM_X4(bhf[pr], aBh + bo);
                LDSM_X4(blf[pr], aBl + bo);
            }
            #pragma unroll
            for (int mt = 0; mt < 4; mt++)
                #pragma unroll
                for (int nt = 0; nt < 4; nt++) {
                    const int pr = nt >> 1, sb2 = (nt & 1) * 2;
                    MMA16816(acc[mt][nt], ahf[mt], bhf[pr][sb2], bhf[pr][sb2 + 1]);
                    MMA16816(acc[mt][nt], ahf[mt], blf[pr][sb2], blf[pr][sb2 + 1]);
                    MMA16816(acc[mt][nt], alf[mt], bhf[pr][sb2], bhf[pr][sb2 + 1]);
                }
        }
        __syncthreads();
    }

    const int rbase = arow0 + warp_m * 64 + (l >> 2);
    const int cbase = bcol0 + warp_n * 32 + (l & 3) * 2;
    #pragma unroll
    for (int mt = 0; mt < 4; mt++)
        #pragma unroll
        for (int nt = 0; nt < 4; nt++) {
            const int row = rbase + mt * 16;
            const int col = cbase + nt * 8;
            float2 v0, v1;
            v0.x = acc[mt][nt][0] + bias[col];
            v0.y = acc[mt][nt][1] + bias[col + 1];
            v1.x = acc[mt][nt][2] + bias[col];
            v1.y = acc[mt][nt][3] + bias[col + 1];
            *(float2*)(C + (size_t)row * N + col) = v0;
            *(float2*)(C + (size_t)(row + 8) * N + col) = v1;
        }
}

// ---------------------------------------------------------------------------
// Tensor-core flash attention (causal).
// CTA = (qt, h, b): 128 q-rows, 8 warps x 16 rows. Key tiles of 64.
// S via split-bf16 (3 products), softmax in registers, P->fp16 A-frags
// in-register, V split fp16 hi/lo via ldmatrix.trans.
// ---------------------------------------------------------------------------
#define QPF 72                         // smem pitch in b16 elems (144B rows)
#define FL_SMEM (2 * 128 * QPF * 2)    // 36864 B (Q staging / K+V union)

__global__ __launch_bounds__(256, 1) void flash_mma(
    const float* __restrict__ qkv, float* __restrict__ out)
{
    __shared__ char fsm[FL_SMEM];
    __nv_bfloat16* QSh = (__nv_bfloat16*)fsm;            // 128 x QPF
    __nv_bfloat16* QSl = QSh + 128 * QPF;
    __nv_bfloat16* Ksh = (__nv_bfloat16*)fsm;            // 64 x QPF (overlays QS)
    __nv_bfloat16* Ksl = Ksh + 64 * QPF;
    __half* Vsh = (__half*)(Ksl + 64 * QPF);
    __half* Vsl = Vsh + 64 * QPF;

    const int tid = threadIdx.x;
    const int w = tid >> 5, l = tid & 31;
    const int qt = blockIdx.x, h = blockIdx.y, b = blockIdx.z;

    // Stage Q (scale 0.125 folded), split bf16 hi/lo
    {
        const float* qg = qkv + ((size_t)(b * TT + qt * 128)) * 3072 + h * 64;
        #pragma unroll
        for (int i = 0; i < 32; i++) {
            int idx = i * 256 + tid;
            int r = idx >> 6, d = idx & 63;
            float v = qg[(size_t)r * 3072 + d] * 0.125f;
            __nv_bfloat16 hh = __float2bfloat16(v);
            QSh[r * QPF + d] = hh;
            QSl[r * QPF + d] = __float2bfloat16(v - __bfloat162float(hh));
        }
    }
    __syncthreads();

    const int mat = l >> 3;
    const int dr  = (mat & 1) * 8 + (l & 7);
    const int dka = (mat >> 1) * 8;
    const int dn  = (mat >> 1) * 8 + (l & 7);
    const int dkb = (mat & 1) * 8;

    // Q fragments (held in registers for all key tiles)
    uint32_t qh[4][4], ql[4][4];
    const uint32_t aQh = smem_u32(QSh), aQl = smem_u32(QSl);
    #pragma unroll
    for (int t = 0; t < 4; t++) {
        uint32_t ao = (uint32_t)((w * 16 + dr) * QPF + t * 16 + dka) * 2;
        LDSM_X4(qh[t], aQh + ao);
        LDSM_X4(ql[t], aQl + ao);
    }

    float o[8][4];
    #pragma unroll
    for (int nt = 0; nt < 8; nt++)
        #pragma unroll
        for (int e = 0; e < 4; e++) o[nt][e] = 0.f;
    float m_a = -INFINITY, m_b = -INFINITY, l_a = 0.f, l_b = 0.f;

    const uint32_t aKh = smem_u32(Ksh), aKl = smem_u32(Ksl);
    const uint32_t aVh = smem_u32(Vsh), aVl = smem_u32(Vsl);
    const int jmax = 2 * qt + 1;

    for (int j = 0; j <= jmax; j++) {
        __syncthreads();   // prior tile reads (or Q frag loads) complete
        // Load + split K (bf16) and V (fp16) tiles: 64 rows x 64 dims
        {
            #pragma unroll
            for (int i = 0; i < 16; i++) {
                int idx = i * 256 + tid;
                int r = idx >> 6, d = idx & 63;
                const float* kg = qkv + ((size_t)(b * TT + j * 64 + r)) * 3072
                                  + 1024 + h * 64;
                float kv = kg[d];
                __nv_bfloat16 kh = __float2bfloat16(kv);
                Ksh[r * QPF + d] = kh;
                Ksl[r * QPF + d] = __float2bfloat16(kv - __bfloat162float(kh));
                float vv = kg[1024 + d];
                __half vh = __float2half_rn(vv);
                Vsh[r * QPF + d] = vh;
                Vsl[r * QPF + d] = __float2half_rn(vv - __half2float(vh));
            }
        }
        __syncthreads();

        // Warps whose q-rows are entirely below this key tile skip compute
        if (j * 64 > qt * 128 + w * 16 + 15) continue;

        // S = Q K^T (split bf16, 3 products)
        float c[8][4];
        #pragma unroll
        for (int nt = 0; nt < 8; nt++)
            #pragma unroll
            for (int e = 0; e < 4; e++) c[nt][e] = 0.f;

        #pragma unroll
        for (int t = 0; t < 4; t++) {
            #pragma unroll
            for (int p = 0; p < 4; p++) {
                uint32_t kb[4], kl2[4];
                uint32_t bo = (uint32_t)((p * 16 + dn) * QPF + t * 16 + dkb) * 2;
                LDSM_X4(kb, aKh + bo);
                LDSM_X4(kl2, aKl + bo);
                #pragma unroll
                for (int sub = 0; sub < 2; sub++) {
                    const int nt = 2 * p + sub;
                    MMA16816(c[nt], qh[t], kb[sub * 2], kb[sub * 2 + 1]);
                    MMA16816(c[nt], qh[t], kl2[sub * 2], kl2[sub * 2 + 1]);
                    MMA16816(c[nt], ql[t], kb[sub * 2], kb[sub * 2 + 1]);
                }
            }
        }

        // Causal mask (only diagonal 128x128 block needs it)
        if (j >= 2 * qt) {
            const int qa = qt * 128 + w * 16 + (l >> 2);
            const int kc0 = j * 64 + (l & 3) * 2;
            #pragma unroll
            for (int nt = 0; nt < 8; nt++) {
                int col = kc0 + nt * 8;
                if (col > qa)     c[nt][0] = -INFINITY;
                if (col + 1 > qa) c[nt][1] = -INFINITY;
                if (col > qa + 8)     c[nt][2] = -INFINITY;
                if (col + 1 > qa + 8) c[nt][3] = -INFINITY;
            }
        }

        // Online softmax (rows l/4 and l/4+8; cols spread over lane quads)
        float ma = -INFINITY, mb = -INFINITY;
        #pragma unroll
        for (int nt = 0; nt < 8; nt++) {
            ma = fmaxf(ma, fmaxf(c[nt][0], c[nt][1]));
            mb = fmaxf(mb, fmaxf(c[nt][2], c[nt][3]));
        }
        ma = fmaxf(ma, __shfl_xor_sync(0xffffffffu, ma, 1));
        ma = fmaxf(ma, __shfl_xor_sync(0xffffffffu, ma, 2));
        mb = fmaxf(mb, __shfl_xor_sync(0xffffffffu, mb, 1));
        mb = fmaxf(mb, __shfl_xor_sync(0xffffffffu, mb, 2));
        float mna = fmaxf(m_a, ma), mnb = fmaxf(m_b, mb);
        float aa = __expf(m_a - mna), ab = __expf(m_b - mnb);
        float sa = 0.f, sb = 0.f;
        #pragma unroll
        for (int nt = 0; nt < 8; nt++) {
            c[nt][0] = __expf(c[nt][0] - mna);
            c[nt][1] = __expf(c[nt][1] - mna);
            c[nt][2] = __expf(c[nt][2] - mnb);
            c[nt][3] = __expf(c[nt][3] - mnb);
            sa += c[nt][0] + c[nt][1];
            sb += c[nt][2] + c[nt][3];
        }
        sa += __shfl_xor_sync(0xffffffffu, sa, 1);
        sa += __shfl_xor_sync(0xffffffffu, sa, 2);
        sb += __shfl_xor_sync(0xffffffffu, sb, 1);
        sb += __shfl_xor_sync(0xffffffffu, sb, 2);
        l_a = l_a * aa + sa;
        l_b = l_b * ab + sb;
        m_a = mna; m_b = mnb;
        #pragma unroll
        for (int nt = 0; nt < 8; nt++) {
            o[nt][0] *= aa; o[nt][1] *= aa;
            o[nt][2] *= ab; o[nt][3] *= ab;
        }

        // O += P V  (P c-frags -> fp16 A-frags in-register; V via ldmatrix.trans)
        #pragma unroll
        for (int t = 0; t < 4; t++) {
            uint32_t pa[4];
            pa[0] = packh2(c[2 * t][0],     c[2 * t][1]);
            pa[1] = packh2(c[2 * t][2],     c[2 * t][3]);
            pa[2] = packh2(c[2 * t + 1][0], c[2 * t + 1][1]);
            pa[3] = packh2(c[2 * t + 1][2], c[2 * t + 1][3]);
            #pragma unroll
            for (int p = 0; p < 4; p++) {
                uint32_t vb[4], vl[4];
                uint32_t vo = (uint32_t)((t * 16 + (mat & 1) * 8 + (l & 7)) * QPF
                                         + p * 16 + (mat >> 1) * 8) * 2;
                LDSM_X4_T(vb, aVh + vo);
                LDSM_X4_T(vl, aVl + vo);
                MMA16816H(o[2 * p],     pa, vb[0], vb[1]);
                MMA16816H(o[2 * p + 1], pa, vb[2], vb[3]);
                MMA16816H(o[2 * p],     pa, vl[0], vl[1]);
                MMA16816H(o[2 * p + 1], pa, vl[2], vl[3]);
            }
        }
    }

    // Epilogue
    const float ia = 1.f / l_a, ib = 1.f / l_b;
    const int row = qt * 128 + w * 16 + (l >> 2);
    float* og = out + ((size_t)(b * TT + row)) * DA + h * 64 + (l & 3) * 2;
    #pragma unroll
    for (int nt = 0; nt < 8; nt++) {
        float2 v0 = { o[nt][0] * ia, o[nt][1] * ia };
        float2 v1 = { o[nt][2] * ib, o[nt][3] * ib };
        *(float2*)(og + nt * 8) = v0;
        *(float2*)(og + (size_t)8 * DA + nt * 8) = v1;
    }
}

// ---------------------------------------------------------------------------
// Launch
// ---------------------------------------------------------------------------
extern "C" void kernel_launch(void* const* d_in, const int* in_sizes, int n_in,
                              void* d_out, int out_size)
{
    const float* x    = (const float*)d_in[0];
    const float* Wqkv = (const float*)d_in[2];
    const float* bqkv = (const float*)d_in[3];
    const float* Wout = (const float*)d_in[4];
    const float* bout = (const float*)d_in[5];
    float* out = (float*)d_out;

    float *qkvbuf = nullptr, *attnbuf = nullptr;
    __nv_bfloat16 *ah, *al, *bh, *bl;
    cudaGetSymbolAddress((void**)&qkvbuf, g_qkv);
    cudaGetSymbolAddress((void**)&attnbuf, g_attn);
    cudaGetSymbolAddress((void**)&ah, g_ah);
    cudaGetSymbolAddress((void**)&al, g_al);
    cudaGetSymbolAddress((void**)&bh, g_bh);
    cudaGetSymbolAddress((void**)&bl, g_bl);

    cudaFuncSetAttribute(gemm_mma,
                         cudaFuncAttributeMaxDynamicSharedMemorySize, (int)GEMM_DYN);

    // Phase 1: QKV = x @ Wqkv + b
    split_f4<<<(MM * CCH / 4 + 255) / 256, 256>>>(x, ah, al, MM * CCH / 4);
    transpose_split<<<dim3(3 * DA / 32, CCH / 32), dim3(32, 8)>>>(Wqkv, bh, bl, CCH, 3 * DA);
    gemm_mma<<<dim3(3 * DA / 128, MM / 128), 256, GEMM_DYN>>>(
        ah, al, bh, bl, bqkv, qkvbuf, MM, 3 * DA, CCH);

    // Phase 2: attention (tensor-core flash)
    flash_mma<<<dim3(TT / 128, NH, BV), 256>>>(qkvbuf, attnbuf);

    // Phase 3: out = attn @ Wout + b
    split_f4<<<(MM * DA / 4 + 255) / 256, 256>>>(attnbuf, ah, al, MM * DA / 4);
    transpose_split<<<dim3(CCH / 32, DA / 32), dim3(32, 8)>>>(Wout, bh, bl, DA, CCH);
    gemm_mma<<<dim3(CCH / 128, MM / 128), 256, GEMM_DYN>>>(
        ah, al, bh, bl, bout, out, MM, CCH, DA);
}

// round 7
// speedup vs baseline: 3.7890x; 1.2095x over previous
#include <cuda_runtime.h>
#include <cuda_bf16.h>
#include <cuda_fp16.h>
#include <math.h>
#include <stdint.h>

// Problem constants
#define BV 4
#define TT 2048
#define CCH 1024
#define DA 1024
#define NH 16
#define HDM 64
#define MM (BV * TT)   // 8192 rows

// ---------------------------------------------------------------------------
// Device scratch (allocations forbidden; __device__ globals are sanctioned)
// ---------------------------------------------------------------------------
__device__ float g_qkv[(size_t)MM * 3 * DA];              // fp32 qkv
__device__ __nv_bfloat16 g_ah[(size_t)MM * CCH];          // A split hi (x / attn)
__device__ __nv_bfloat16 g_al[(size_t)MM * CCH];          // A split lo
__device__ __nv_bfloat16 g_bh[(size_t)CCH * 3 * DA];      // W^T split hi
__device__ __nv_bfloat16 g_bl[(size_t)CCH * 3 * DA];      // W^T split lo
// Head-major split K/V: [(b*NH+h)*TT + t][64]
__device__ __nv_bfloat16 g_kh[(size_t)MM * DA];
__device__ __nv_bfloat16 g_kl[(size_t)MM * DA];
__device__ __half        g_vh[(size_t)MM * DA];
__device__ __half        g_vl[(size_t)MM * DA];

__device__ __forceinline__ uint32_t smem_u32(const void* p) {
    uint32_t a;
    asm("{ .reg .u64 t; cvta.to.shared.u64 t, %1; cvt.u32.u64 %0, t; }"
        : "=r"(a) : "l"(p));
    return a;
}

#define LDSM_X4(r, addr) \
    asm volatile("ldmatrix.sync.aligned.m8n8.x4.shared.b16 {%0,%1,%2,%3}, [%4];" \
        : "=r"((r)[0]), "=r"((r)[1]), "=r"((r)[2]), "=r"((r)[3]) : "r"(addr))

#define LDSM_X4_T(r, addr) \
    asm volatile("ldmatrix.sync.aligned.m8n8.x4.trans.shared.b16 {%0,%1,%2,%3}, [%4];" \
        : "=r"((r)[0]), "=r"((r)[1]), "=r"((r)[2]), "=r"((r)[3]) : "r"(addr))

#define MMA16816(c, a, b0, b1) \
    asm volatile("mma.sync.aligned.m16n8k16.row.col.f32.bf16.bf16.f32 " \
        "{%0,%1,%2,%3}, {%4,%5,%6,%7}, {%8,%9}, {%0,%1,%2,%3};" \
        : "+f"((c)[0]), "+f"((c)[1]), "+f"((c)[2]), "+f"((c)[3]) \
        : "r"((a)[0]), "r"((a)[1]), "r"((a)[2]), "r"((a)[3]), "r"(b0), "r"(b1))

#define MMA16816H(c, a, b0, b1) \
    asm volatile("mma.sync.aligned.m16n8k16.row.col.f32.f16.f16.f32 " \
        "{%0,%1,%2,%3}, {%4,%5,%6,%7}, {%8,%9}, {%0,%1,%2,%3};" \
        : "+f"((c)[0]), "+f"((c)[1]), "+f"((c)[2]), "+f"((c)[3]) \
        : "r"((a)[0]), "r"((a)[1]), "r"((a)[2]), "r"((a)[3]), "r"(b0), "r"(b1))

#define CP_A16(dst, src) \
    asm volatile("cp.async.cg.shared.global [%0], [%1], 16;" \
                 :: "r"(dst), "l"(src) : "memory")
#define CP_COMMIT() asm volatile("cp.async.commit_group;" ::: "memory")
#define CP_WAIT1()  asm volatile("cp.async.wait_group 1;" ::: "memory")
#define CP_WAIT0()  asm volatile("cp.async.wait_group 0;" ::: "memory")

__device__ __forceinline__ uint32_t packh2(float a, float b) {
    __half2 h = __floats2half2_rn(a, b);
    return *(uint32_t*)&h;
}

// ---------------------------------------------------------------------------
// split_f4: fp32 -> (bf16 hi, bf16 lo), elementwise
// ---------------------------------------------------------------------------
__global__ void split_f4(const float* __restrict__ src,
                         __nv_bfloat16* __restrict__ hi,
                         __nv_bfloat16* __restrict__ lo, int n4)
{
    int i = blockIdx.x * blockDim.x + threadIdx.x;
    if (i >= n4) return;
    float4 v = ((const float4*)src)[i];
    __nv_bfloat16 h0 = __float2bfloat16(v.x), h1 = __float2bfloat16(v.y);
    __nv_bfloat16 h2 = __float2bfloat16(v.z), h3 = __float2bfloat16(v.w);
    __nv_bfloat16 l0 = __float2bfloat16(v.x - __bfloat162float(h0));
    __nv_bfloat16 l1 = __float2bfloat16(v.y - __bfloat162float(h1));
    __nv_bfloat16 l2 = __float2bfloat16(v.z - __bfloat162float(h2));
    __nv_bfloat16 l3 = __float2bfloat16(v.w - __bfloat162float(h3));
    ((__nv_bfloat162*)hi)[2 * i]     = __nv_bfloat162(h0, h1);
    ((__nv_bfloat162*)hi)[2 * i + 1] = __nv_bfloat162(h2, h3);
    ((__nv_bfloat162*)lo)[2 * i]     = __nv_bfloat162(l0, l1);
    ((__nv_bfloat162*)lo)[2 * i + 1] = __nv_bfloat162(l2, l3);
}

// W[K][N] -> Th/Tl[N][K] with split. 32x32 smem-tiled transpose.
__global__ void transpose_split(const float* __restrict__ W,
                                __nv_bfloat16* __restrict__ Th,
                                __nv_bfloat16* __restrict__ Tl, int K, int N)
{
    __shared__ float tile[32][33];
    int tx = threadIdx.x, ty = threadIdx.y;
    int n0 = blockIdx.x * 32, k0 = blockIdx.y * 32;
    #pragma unroll
    for (int j = 0; j < 32; j += 8)
        tile[ty + j][tx] = W[(size_t)(k0 + ty + j) * N + n0 + tx];
    __syncthreads();
    #pragma unroll
    for (int j = 0; j < 32; j += 8) {
        float v = tile[tx][ty + j];
        __nv_bfloat16 h = __float2bfloat16(v);
        __nv_bfloat16 l = __float2bfloat16(v - __bfloat162float(h));
        size_t o = (size_t)(n0 + ty + j) * K + k0 + tx;
        Th[o] = h;
        Tl[o] = l;
    }
}

// ---------------------------------------------------------------------------
// split_kv: qkv fp32 -> head-major split K (bf16 hi/lo), V (fp16 hi/lo)
// One warp per (b,h,t) row; lane covers 2 dims.
// ---------------------------------------------------------------------------
__global__ void split_kv(const float* __restrict__ qkv,
                         __nv_bfloat16* __restrict__ kh, __nv_bfloat16* __restrict__ kl,
                         __half* __restrict__ vh, __half* __restrict__ vl)
{
    int r = blockIdx.x * 8 + (threadIdx.x >> 5);   // (b*NH+h)*TT + t
    int l = threadIdx.x & 31;
    int t = r & (TT - 1);
    int h = (r >> 11) & (NH - 1);
    int b = r >> 15;
    const float* kp = qkv + ((size_t)(b * TT + t)) * 3072 + 1024 + h * 64 + 2 * l;
    float2 k2 = *(const float2*)kp;
    float2 v2 = *(const float2*)(kp + 1024);
    size_t o = (size_t)r * 64 + 2 * l;
    __nv_bfloat16 kh0 = __float2bfloat16(k2.x), kh1 = __float2bfloat16(k2.y);
    *(__nv_bfloat162*)(kh + o) = __nv_bfloat162(kh0, kh1);
    *(__nv_bfloat162*)(kl + o) = __nv_bfloat162(
        __float2bfloat16(k2.x - __bfloat162float(kh0)),
        __float2bfloat16(k2.y - __bfloat162float(kh1)));
    __half vh0 = __float2half_rn(v2.x), vh1 = __float2half_rn(v2.y);
    *(__half2*)(vh + o) = __half2(vh0, vh1);
    *(__half2*)(vl + o) = __half2(
        __float2half_rn(v2.x - __half2float(vh0)),
        __float2half_rn(v2.y - __half2float(vh1)));
}

// ---------------------------------------------------------------------------
// mma.sync split-bf16 GEMM with cp.async double-buffering.
// CTA 128x128, 8 warps (2x4), warp tile 64x32, KC=32.
// ---------------------------------------------------------------------------
#define KC 32
#define PP 40
#define MAT_B (128 * PP * 2)                // 10240 B
#define STAGE_B (4 * MAT_B)                 // 40960 B
#define GEMM_DYN (2 * STAGE_B)              // 81920 B

static __device__ __forceinline__ void gemm_issue(
    uint32_t stage, const char* a0, const char* a1,
    const char* a2, const char* a3, int Kb, int k0b, int tid)
{
    const char* srcs[4] = {a0, a1, a2, a3};
    #pragma unroll
    for (int i = 0; i < 8; i++) {
        int idx = i * 256 + tid;
        int arr = idx >> 9, rem = idx & 511;
        int row = rem >> 2, c = rem & 3;
        CP_A16(stage + arr * MAT_B + row * (PP * 2) + c * 16,
               srcs[arr] + (size_t)row * Kb + k0b + c * 16);
    }
}

__global__ __launch_bounds__(256, 1) void gemm_mma(
    const __nv_bfloat16* __restrict__ Ah, const __nv_bfloat16* __restrict__ Al,
    const __nv_bfloat16* __restrict__ Bh, const __nv_bfloat16* __restrict__ Bl,
    const float* __restrict__ bias, float* __restrict__ C,
    int M, int N, int K)
{
    extern __shared__ char dyn[];
    const int tid = threadIdx.x;
    const int wid = tid >> 5, l = tid & 31;
    const int warp_m = wid & 1, warp_n = wid >> 1;
    const int bc = blockIdx.x, br = blockIdx.y;
    const int arow0 = br * 128, bcol0 = bc * 128;

    const int mat = l >> 3;
    const int dr  = (mat & 1) * 8 + (l & 7);
    const int dka = (mat >> 1) * 8;
    const int dn  = (mat >> 1) * 8 + (l & 7);
    const int dkb = (mat & 1) * 8;

    float acc[4][4][4];
    #pragma unroll
    for (int i = 0; i < 4; i++)
        #pragma unroll
        for (int j = 0; j < 4; j++)
            #pragma unroll
            for (int q = 0; q < 4; q++) acc[i][j][q] = 0.f;

    const uint32_t sbase = smem_u32(dyn);
    const int NCH = K / KC;
    const int Kb = K * 2;
    const char* a0 = (const char*)(Ah + (size_t)arow0 * K);
    const char* a1 = (const char*)(Al + (size_t)arow0 * K);
    const char* a2 = (const char*)(Bh + (size_t)bcol0 * K);
    const char* a3 = (const char*)(Bl + (size_t)bcol0 * K);

    gemm_issue(sbase, a0, a1, a2, a3, Kb, 0, tid);
    CP_COMMIT();

    for (int c = 0; c < NCH; c++) {
        const int b = c & 1;
        if (c + 1 < NCH) {
            gemm_issue(sbase + (uint32_t)(b ^ 1) * STAGE_B,
                       a0, a1, a2, a3, Kb, (c + 1) * KC * 2, tid);
            CP_COMMIT();
            CP_WAIT1();
        } else {
            CP_WAIT0();
        }
        __syncthreads();

        const uint32_t st = sbase + (uint32_t)b * STAGE_B;
        const uint32_t aAh = st + 0 * MAT_B;
        const uint32_t aAl = st + 1 * MAT_B;
        const uint32_t aBh = st + 2 * MAT_B;
        const uint32_t aBl = st + 3 * MAT_B;

        #pragma unroll
        for (int ks = 0; ks < KC / 16; ks++) {
            const int k0 = ks * 16;
            uint32_t ahf[4][4], alf[4][4];
            uint32_t bhf[2][4], blf[2][4];
            #pragma unroll
            for (int mt = 0; mt < 4; mt++) {
                uint32_t ao = (uint32_t)((warp_m * 64 + mt * 16 + dr) * PP
                                         + k0 + dka) * 2;
                LDSM_X4(ahf[mt], aAh + ao);
                LDSM_X4(alf[mt], aAl + ao);
            }
            #pragma unroll
            for (int pr = 0; pr < 2; pr++) {
                uint32_t bo = (uint32_t)((warp_n * 32 + pr * 16 + dn) * PP
                                         + k0 + dkb) * 2;
                LDSM_X4(bhf[pr], aBh + bo);
                LDSM_X4(blf[pr], aBl + bo);
            }
            #pragma unroll
            for (int mt = 0; mt < 4; mt++)
                #pragma unroll
                for (int nt = 0; nt < 4; nt++) {
                    const int pr = nt >> 1, sb2 = (nt & 1) * 2;
                    MMA16816(acc[mt][nt], ahf[mt], bhf[pr][sb2], bhf[pr][sb2 + 1]);
                    MMA16816(acc[mt][nt], ahf[mt], blf[pr][sb2], blf[pr][sb2 + 1]);
                    MMA16816(acc[mt][nt], alf[mt], bhf[pr][sb2], bhf[pr][sb2 + 1]);
                }
        }
        __syncthreads();
    }

    const int rbase = arow0 + warp_m * 64 + (l >> 2);
    const int cbase = bcol0 + warp_n * 32 + (l & 3) * 2;
    #pragma unroll
    for (int mt = 0; mt < 4; mt++)
        #pragma unroll
        for (int nt = 0; nt < 4; nt++) {
            const int row = rbase + mt * 16;
            const int col = cbase + nt * 8;
            float2 v0, v1;
            v0.x = acc[mt][nt][0] + bias[col];
            v0.y = acc[mt][nt][1] + bias[col + 1];
            v1.x = acc[mt][nt][2] + bias[col];
            v1.y = acc[mt][nt][3] + bias[col + 1];
            *(float2*)(C + (size_t)row * N + col) = v0;
            *(float2*)(C + (size_t)(row + 8) * N + col) = v1;
        }
}

// ---------------------------------------------------------------------------
// Tensor-core flash attention v2 (causal), cp.async double-buffered K/V.
// CTA = (qt, h, b): 128 q-rows, 8 warps x 16 rows. Key tiles of 64.
// Writes attn output directly as split bf16 (ah/al).
// ---------------------------------------------------------------------------
#define QPF 72                              // smem pitch in b16 elems
#define KVT_B (64 * QPF * 2)                // 9216 B per array tile
#define KV_STAGE (4 * KVT_B)                // Kh,Kl,Vh,Vl = 36864 B
#define FL_DYN (2 * KV_STAGE)               // 73728 B (stage0 overlays Q staging)

static __device__ __forceinline__ void flash_issue(
    uint32_t stage, const char* kh, const char* kl,
    const char* vh, const char* vl, size_t tile_off, int tid)
{
    const char* srcs[4] = {kh + tile_off, kl + tile_off, vh + tile_off, vl + tile_off};
    #pragma unroll
    for (int i = 0; i < 8; i++) {
        int idx = i * 256 + tid;
        int arr = idx >> 9, rem = idx & 511;
        int r = rem >> 3, c = rem & 7;
        CP_A16(stage + arr * KVT_B + r * (QPF * 2) + c * 16,
               srcs[arr] + r * 128 + c * 16);
    }
}

__global__ __launch_bounds__(256, 1) void flash_mma(
    const float* __restrict__ qkv,
    const __nv_bfloat16* __restrict__ kh_g, const __nv_bfloat16* __restrict__ kl_g,
    const __half* __restrict__ vh_g, const __half* __restrict__ vl_g,
    __nv_bfloat16* __restrict__ oh, __nv_bfloat16* __restrict__ ol)
{
    extern __shared__ char fsm[];
    __nv_bfloat16* QSh = (__nv_bfloat16*)fsm;            // 128 x QPF (overlays stage0)
    __nv_bfloat16* QSl = QSh + 128 * QPF;

    const int tid = threadIdx.x;
    const int w = tid >> 5, l = tid & 31;
    const int qt = blockIdx.x, h = blockIdx.y, b = blockIdx.z;

    // Stage Q (scale 0.125 folded), split bf16 hi/lo
    {
        const float* qg = qkv + ((size_t)(b * TT + qt * 128)) * 3072 + h * 64;
        #pragma unroll
        for (int i = 0; i < 32; i++) {
            int idx = i * 256 + tid;
            int r = idx >> 6, d = idx & 63;
            float v = qg[(size_t)r * 3072 + d] * 0.125f;
            __nv_bfloat16 hh = __float2bfloat16(v);
            QSh[r * QPF + d] = hh;
            QSl[r * QPF + d] = __float2bfloat16(v - __bfloat162float(hh));
        }
    }
    __syncthreads();

    const int mat = l >> 3;
    const int dr  = (mat & 1) * 8 + (l & 7);
    const int dka = (mat >> 1) * 8;
    const int dn  = (mat >> 1) * 8 + (l & 7);
    const int dkb = (mat & 1) * 8;

    uint32_t qh[4][4], ql[4][4];
    const uint32_t aQh = smem_u32(QSh), aQl = smem_u32(QSl);
    #pragma unroll
    for (int t = 0; t < 4; t++) {
        uint32_t ao = (uint32_t)((w * 16 + dr) * QPF + t * 16 + dka) * 2;
        LDSM_X4(qh[t], aQh + ao);
        LDSM_X4(ql[t], aQl + ao);
    }
    __syncthreads();   // all Q frags read before stage0 overwrite

    float o[8][4];
    #pragma unroll
    for (int nt = 0; nt < 8; nt++)
        #pragma unroll
        for (int e = 0; e < 4; e++) o[nt][e] = 0.f;
    float m_a = -INFINITY, m_b = -INFINITY, l_a = 0.f, l_b = 0.f;

    const uint32_t sbase = smem_u32(fsm);
    const size_t headoff = ((size_t)(b * NH + h) * TT) * 64 * 2;  // bytes
    const char* kh_c = (const char*)kh_g + headoff;
    const char* kl_c = (const char*)kl_g + headoff;
    const char* vh_c = (const char*)vh_g + headoff;
    const char* vl_c = (const char*)vl_g + headoff;
    const int jmax = 2 * qt + 1;

    flash_issue(sbase, kh_c, kl_c, vh_c, vl_c, 0, tid);
    CP_COMMIT();

    for (int j = 0; j <= jmax; j++) {
        const int st = j & 1;
        if (j < jmax) {
            flash_issue(sbase + (uint32_t)(st ^ 1) * KV_STAGE,
                        kh_c, kl_c, vh_c, vl_c, (size_t)(j + 1) * 8192, tid);
            CP_COMMIT();
            CP_WAIT1();
        } else {
            CP_WAIT0();
        }
        __syncthreads();

        const bool active = (j * 64 <= qt * 128 + w * 16 + 15);
        if (active) {
            const uint32_t sb = sbase + (uint32_t)st * KV_STAGE;
            const uint32_t aKh = sb, aKl = sb + KVT_B;
            const uint32_t aVh = sb + 2 * KVT_B, aVl = sb + 3 * KVT_B;

            float c[8][4];
            #pragma unroll
            for (int nt = 0; nt < 8; nt++)
                #pragma unroll
                for (int e = 0; e < 4; e++) c[nt][e] = 0.f;

            #pragma unroll
            for (int t = 0; t < 4; t++) {
                #pragma unroll
                for (int p = 0; p < 4; p++) {
                    uint32_t kb[4], kl2[4];
                    uint32_t bo = (uint32_t)((p * 16 + dn) * QPF + t * 16 + dkb) * 2;
                    LDSM_X4(kb, aKh + bo);
                    LDSM_X4(kl2, aKl + bo);
                    #pragma unroll
                    for (int sub = 0; sub < 2; sub++) {
                        const int nt = 2 * p + sub;
                        MMA16816(c[nt], qh[t], kb[sub * 2], kb[sub * 2 + 1]);
                        MMA16816(c[nt], qh[t], kl2[sub * 2], kl2[sub * 2 + 1]);
                        MMA16816(c[nt], ql[t], kb[sub * 2], kb[sub * 2 + 1]);
                    }
                }
            }

            if (j >= 2 * qt) {
                const int qa = qt * 128 + w * 16 + (l >> 2);
                const int kc0 = j * 64 + (l & 3) * 2;
                #pragma unroll
                for (int nt = 0; nt < 8; nt++) {
                    int col = kc0 + nt * 8;
                    if (col > qa)     c[nt][0] = -INFINITY;
                    if (col + 1 > qa) c[nt][1] = -INFINITY;
                    if (col > qa + 8)     c[nt][2] = -INFINITY;
                    if (col + 1 > qa + 8) c[nt][3] = -INFINITY;
                }
            }

            float ma = -INFINITY, mb = -INFINITY;
            #pragma unroll
            for (int nt = 0; nt < 8; nt++) {
                ma = fmaxf(ma, fmaxf(c[nt][0], c[nt][1]));
                mb = fmaxf(mb, fmaxf(c[nt][2], c[nt][3]));
            }
            ma = fmaxf(ma, __shfl_xor_sync(0xffffffffu, ma, 1));
            ma = fmaxf(ma, __shfl_xor_sync(0xffffffffu, ma, 2));
            mb = fmaxf(mb, __shfl_xor_sync(0xffffffffu, mb, 1));
            mb = fmaxf(mb, __shfl_xor_sync(0xffffffffu, mb, 2));
            float mna = fmaxf(m_a, ma), mnb = fmaxf(m_b, mb);
            float aa = __expf(m_a - mna), ab = __expf(m_b - mnb);
            float sa = 0.f, sb2 = 0.f;
            #pragma unroll
            for (int nt = 0; nt < 8; nt++) {
                c[nt][0] = __expf(c[nt][0] - mna);
                c[nt][1] = __expf(c[nt][1] - mna);
                c[nt][2] = __expf(c[nt][2] - mnb);
                c[nt][3] = __expf(c[nt][3] - mnb);
                sa += c[nt][0] + c[nt][1];
                sb2 += c[nt][2] + c[nt][3];
            }
            sa += __shfl_xor_sync(0xffffffffu, sa, 1);
            sa += __shfl_xor_sync(0xffffffffu, sa, 2);
            sb2 += __shfl_xor_sync(0xffffffffu, sb2, 1);
            sb2 += __shfl_xor_sync(0xffffffffu, sb2, 2);
            l_a = l_a * aa + sa;
            l_b = l_b * ab + sb2;
            m_a = mna; m_b = mnb;
            #pragma unroll
            for (int nt = 0; nt < 8; nt++) {
                o[nt][0] *= aa; o[nt][1] *= aa;
                o[nt][2] *= ab; o[nt][3] *= ab;
            }

            #pragma unroll
            for (int t = 0; t < 4; t++) {
                uint32_t pa[4];
                pa[0] = packh2(c[2 * t][0],     c[2 * t][1]);
                pa[1] = packh2(c[2 * t][2],     c[2 * t][3]);
                pa[2] = packh2(c[2 * t + 1][0], c[2 * t + 1][1]);
                pa[3] = packh2(c[2 * t + 1][2], c[2 * t + 1][3]);
                #pragma unroll
                for (int p = 0; p < 4; p++) {
                    uint32_t vb[4], vl2[4];
                    uint32_t vo = (uint32_t)((t * 16 + (mat & 1) * 8 + (l & 7)) * QPF
                                             + p * 16 + (mat >> 1) * 8) * 2;
                    LDSM_X4_T(vb, aVh + vo);
                    LDSM_X4_T(vl2, aVl + vo);
                    MMA16816H(o[2 * p],     pa, vb[0], vb[1]);
                    MMA16816H(o[2 * p + 1], pa, vb[2], vb[3]);
                    MMA16816H(o[2 * p],     pa, vl2[0], vl2[1]);
                    MMA16816H(o[2 * p + 1], pa, vl2[2], vl2[3]);
                }
            }
        }
        __syncthreads();
    }

    // Epilogue: write split bf16 directly (feeds gemm2)
    const float ia = 1.f / l_a, ib = 1.f / l_b;
    const int row = (b * TT + qt * 128 + w * 16 + (l >> 2));
    const int col = h * 64 + (l & 3) * 2;
    #pragma unroll
    for (int nt = 0; nt < 8; nt++) {
        float v0 = o[nt][0] * ia, v1 = o[nt][1] * ia;
        float v2 = o[nt][2] * ib, v3 = o[nt][3] * ib;
        __nv_bfloat16 h0 = __float2bfloat16(v0), h1 = __float2bfloat16(v1);
        __nv_bfloat16 h2 = __float2bfloat16(v2), h3 = __float2bfloat16(v3);
        size_t o0 = (size_t)row * DA + col + nt * 8;
        size_t o1 = (size_t)(row + 8) * DA + col + nt * 8;
        *(__nv_bfloat162*)(oh + o0) = __nv_bfloat162(h0, h1);
        *(__nv_bfloat162*)(ol + o0) = __nv_bfloat162(
            __float2bfloat16(v0 - __bfloat162float(h0)),
            __float2bfloat16(v1 - __bfloat162float(h1)));
        *(__nv_bfloat162*)(oh + o1) = __nv_bfloat162(h2, h3);
        *(__nv_bfloat162*)(ol + o1) = __nv_bfloat162(
            __float2bfloat16(v2 - __bfloat162float(h2)),
            __float2bfloat16(v3 - __bfloat162float(h3)));
    }
}

// ---------------------------------------------------------------------------
// Launch
// ---------------------------------------------------------------------------
extern "C" void kernel_launch(void* const* d_in, const int* in_sizes, int n_in,
                              void* d_out, int out_size)
{
    const float* x    = (const float*)d_in[0];
    const float* Wqkv = (const float*)d_in[2];
    const float* bqkv = (const float*)d_in[3];
    const float* Wout = (const float*)d_in[4];
    const float* bout = (const float*)d_in[5];
    float* out = (float*)d_out;

    float* qkvbuf = nullptr;
    __nv_bfloat16 *ah, *al, *bh, *bl, *kh, *kl;
    __half *vh, *vl;
    cudaGetSymbolAddress((void**)&qkvbuf, g_qkv);
    cudaGetSymbolAddress((void**)&ah, g_ah);
    cudaGetSymbolAddress((void**)&al, g_al);
    cudaGetSymbolAddress((void**)&bh, g_bh);
    cudaGetSymbolAddress((void**)&bl, g_bl);
    cudaGetSymbolAddress((void**)&kh, g_kh);
    cudaGetSymbolAddress((void**)&kl, g_kl);
    cudaGetSymbolAddress((void**)&vh, g_vh);
    cudaGetSymbolAddress((void**)&vl, g_vl);

    cudaFuncSetAttribute(gemm_mma,
                         cudaFuncAttributeMaxDynamicSharedMemorySize, (int)GEMM_DYN);
    cudaFuncSetAttribute(flash_mma,
                         cudaFuncAttributeMaxDynamicSharedMemorySize, (int)FL_DYN);

    // Phase 1: QKV = x @ Wqkv + b
    split_f4<<<(MM * CCH / 4 + 255) / 256, 256>>>(x, ah, al, MM * CCH / 4);
    transpose_split<<<dim3(3 * DA / 32, CCH / 32), dim3(32, 8)>>>(Wqkv, bh, bl, CCH, 3 * DA);
    gemm_mma<<<dim3(3 * DA / 128, MM / 128), 256, GEMM_DYN>>>(
        ah, al, bh, bl, bqkv, qkvbuf, MM, 3 * DA, CCH);

    // Phase 2: split K/V, then tensor-core flash (writes split attn to ah/al)
    split_kv<<<MM * NH / 8, 256>>>(qkvbuf, kh, kl, vh, vl);
    flash_mma<<<dim3(TT / 128, NH, BV), 256, FL_DYN>>>(
        qkvbuf, kh, kl, vh, vl, ah, al);

    // Phase 3: out = attn @ Wout + b
    transpose_split<<<dim3(CCH / 32, DA / 32), dim3(32, 8)>>>(Wout, bh, bl, DA, CCH);
    gemm_mma<<<dim3(CCH / 128, MM / 128), 256, GEMM_DYN>>>(
        ah, al, bh, bl, bout, out, MM, CCH, DA);
}

// round 8
// speedup vs baseline: 3.8028x; 1.0036x over previous
#include <cuda_runtime.h>
#include <cuda_bf16.h>
#include <cuda_fp16.h>
#include <math.h>
#include <stdint.h>

// Problem constants
#define BV 4
#define TT 2048
#define CCH 1024
#define DA 1024
#define NH 16
#define HDM 64
#define MM (BV * TT)   // 8192 rows

// ---------------------------------------------------------------------------
// Device scratch (allocations forbidden; __device__ globals are sanctioned)
// ---------------------------------------------------------------------------
__device__ __nv_bfloat16 g_ah[(size_t)MM * CCH];          // A split hi (x / attn)
__device__ __nv_bfloat16 g_al[(size_t)MM * CCH];          // A split lo
__device__ __nv_bfloat16 g_bh[(size_t)CCH * 3 * DA];      // W^T split hi
__device__ __nv_bfloat16 g_bl[(size_t)CCH * 3 * DA];      // W^T split lo
// Q split (token-major, scale folded): [b*TT+t][1024]
__device__ __nv_bfloat16 g_qh[(size_t)MM * DA];
__device__ __nv_bfloat16 g_ql[(size_t)MM * DA];
// Head-major split K/V: [(b*NH+h)*TT + t][64]
__device__ __nv_bfloat16 g_kh[(size_t)MM * DA];
__device__ __nv_bfloat16 g_kl[(size_t)MM * DA];
__device__ __half        g_vh[(size_t)MM * DA];
__device__ __half        g_vl[(size_t)MM * DA];

__device__ __forceinline__ uint32_t smem_u32(const void* p) {
    uint32_t a;
    asm("{ .reg .u64 t; cvta.to.shared.u64 t, %1; cvt.u32.u64 %0, t; }"
        : "=r"(a) : "l"(p));
    return a;
}

#define LDSM_X4(r, addr) \
    asm volatile("ldmatrix.sync.aligned.m8n8.x4.shared.b16 {%0,%1,%2,%3}, [%4];" \
        : "=r"((r)[0]), "=r"((r)[1]), "=r"((r)[2]), "=r"((r)[3]) : "r"(addr))

#define LDSM_X4_T(r, addr) \
    asm volatile("ldmatrix.sync.aligned.m8n8.x4.trans.shared.b16 {%0,%1,%2,%3}, [%4];" \
        : "=r"((r)[0]), "=r"((r)[1]), "=r"((r)[2]), "=r"((r)[3]) : "r"(addr))

#define MMA16816(c, a, b0, b1) \
    asm volatile("mma.sync.aligned.m16n8k16.row.col.f32.bf16.bf16.f32 " \
        "{%0,%1,%2,%3}, {%4,%5,%6,%7}, {%8,%9}, {%0,%1,%2,%3};" \
        : "+f"((c)[0]), "+f"((c)[1]), "+f"((c)[2]), "+f"((c)[3]) \
        : "r"((a)[0]), "r"((a)[1]), "r"((a)[2]), "r"((a)[3]), "r"(b0), "r"(b1))

#define MMA16816H(c, a, b0, b1) \
    asm volatile("mma.sync.aligned.m16n8k16.row.col.f32.f16.f16.f32 " \
        "{%0,%1,%2,%3}, {%4,%5,%6,%7}, {%8,%9}, {%0,%1,%2,%3};" \
        : "+f"((c)[0]), "+f"((c)[1]), "+f"((c)[2]), "+f"((c)[3]) \
        : "r"((a)[0]), "r"((a)[1]), "r"((a)[2]), "r"((a)[3]), "r"(b0), "r"(b1))

#define CP_A16(dst, src) \
    asm volatile("cp.async.cg.shared.global [%0], [%1], 16;" \
                 :: "r"(dst), "l"(src) : "memory")
#define CP_COMMIT() asm volatile("cp.async.commit_group;" ::: "memory")
#define CP_WAIT2()  asm volatile("cp.async.wait_group 2;" ::: "memory")
#define CP_WAIT1()  asm volatile("cp.async.wait_group 1;" ::: "memory")
#define CP_WAIT0()  asm volatile("cp.async.wait_group 0;" ::: "memory")

__device__ __forceinline__ uint32_t packh2(float a, float b) {
    __half2 h = __floats2half2_rn(a, b);
    return *(uint32_t*)&h;
}

// ---------------------------------------------------------------------------
// split_f4: fp32 -> (bf16 hi, bf16 lo), elementwise  (input x only)
// ---------------------------------------------------------------------------
__global__ void split_f4(const float* __restrict__ src,
                         __nv_bfloat16* __restrict__ hi,
                         __nv_bfloat16* __restrict__ lo, int n4)
{
    int i = blockIdx.x * blockDim.x + threadIdx.x;
    if (i >= n4) return;
    float4 v = ((const float4*)src)[i];
    __nv_bfloat16 h0 = __float2bfloat16(v.x), h1 = __float2bfloat16(v.y);
    __nv_bfloat16 h2 = __float2bfloat16(v.z), h3 = __float2bfloat16(v.w);
    __nv_bfloat16 l0 = __float2bfloat16(v.x - __bfloat162float(h0));
    __nv_bfloat16 l1 = __float2bfloat16(v.y - __bfloat162float(h1));
    __nv_bfloat16 l2 = __float2bfloat16(v.z - __bfloat162float(h2));
    __nv_bfloat16 l3 = __float2bfloat16(v.w - __bfloat162float(h3));
    ((__nv_bfloat162*)hi)[2 * i]     = __nv_bfloat162(h0, h1);
    ((__nv_bfloat162*)hi)[2 * i + 1] = __nv_bfloat162(h2, h3);
    ((__nv_bfloat162*)lo)[2 * i]     = __nv_bfloat162(l0, l1);
    ((__nv_bfloat162*)lo)[2 * i + 1] = __nv_bfloat162(l2, l3);
}

// W[K][N] -> Th/Tl[N][K] with split. 32x32 smem-tiled transpose.
__global__ void transpose_split(const float* __restrict__ W,
                                __nv_bfloat16* __restrict__ Th,
                                __nv_bfloat16* __restrict__ Tl, int K, int N)
{
    __shared__ float tile[32][33];
    int tx = threadIdx.x, ty = threadIdx.y;
    int n0 = blockIdx.x * 32, k0 = blockIdx.y * 32;
    #pragma unroll
    for (int j = 0; j < 32; j += 8)
        tile[ty + j][tx] = W[(size_t)(k0 + ty + j) * N + n0 + tx];
    __syncthreads();
    #pragma unroll
    for (int j = 0; j < 32; j += 8) {
        float v = tile[tx][ty + j];
        __nv_bfloat16 h = __float2bfloat16(v);
        __nv_bfloat16 l = __float2bfloat16(v - __bfloat162float(h));
        size_t o = (size_t)(n0 + ty + j) * K + k0 + tx;
        Th[o] = h;
        Tl[o] = l;
    }
}

// ---------------------------------------------------------------------------
// Shared GEMM mainloop pieces (CTA 128x128, 8 warps 2x4, KC=32, 3-stage)
// ---------------------------------------------------------------------------
#define KC 32
#define PP 40
#define MAT_B (128 * PP * 2)                // 10240 B
#define STAGE_B (4 * MAT_B)                 // 40960 B
#define GEMM_DYN (3 * STAGE_B)              // 122880 B

static __device__ __forceinline__ void gemm_issue(
    uint32_t stage, const char* a0, const char* a1,
    const char* a2, const char* a3, int Kb, int k0b, int tid)
{
    const char* srcs[4] = {a0, a1, a2, a3};
    #pragma unroll
    for (int i = 0; i < 8; i++) {
        int idx = i * 256 + tid;
        int arr = idx >> 9, rem = idx & 511;
        int row = rem >> 2, c = rem & 3;
        CP_A16(stage + arr * MAT_B + row * (PP * 2) + c * 16,
               srcs[arr] + (size_t)row * Kb + k0b + c * 16);
    }
}

// Mainloop macro body: computes acc[4][4][4] for this CTA tile.
#define GEMM_MAINLOOP(Ah, Al, Bh, Bl, K)                                      \
    const uint32_t sbase = smem_u32(dyn);                                     \
    const int NCH = (K) / KC;                                                 \
    const int Kb = (K) * 2;                                                   \
    const char* a0 = (const char*)((Ah) + (size_t)arow0 * (K));               \
    const char* a1 = (const char*)((Al) + (size_t)arow0 * (K));               \
    const char* a2 = (const char*)((Bh) + (size_t)bcol0 * (K));               \
    const char* a3 = (const char*)((Bl) + (size_t)bcol0 * (K));               \
    gemm_issue(sbase, a0, a1, a2, a3, Kb, 0, tid); CP_COMMIT();               \
    gemm_issue(sbase + STAGE_B, a0, a1, a2, a3, Kb, KC * 2, tid); CP_COMMIT();\
    for (int c = 0; c < NCH; c++) {                                           \
        const int st3 = c % 3;                                                \
        if (c + 2 < NCH) {                                                    \
            gemm_issue(sbase + (uint32_t)((c + 2) % 3) * STAGE_B,             \
                       a0, a1, a2, a3, Kb, (c + 2) * KC * 2, tid);            \
            CP_COMMIT(); CP_WAIT2();                                          \
        } else if (c + 1 < NCH) { CP_WAIT1(); } else { CP_WAIT0(); }          \
        __syncthreads();                                                      \
        const uint32_t stb = sbase + (uint32_t)st3 * STAGE_B;                 \
        const uint32_t aAh = stb + 0 * MAT_B;                                 \
        const uint32_t aAl = stb + 1 * MAT_B;                                 \
        const uint32_t aBh = stb + 2 * MAT_B;                                 \
        const uint32_t aBl = stb + 3 * MAT_B;                                 \
        _Pragma("unroll")                                                     \
        for (int ks = 0; ks < KC / 16; ks++) {                                \
            const int k0 = ks * 16;                                           \
            uint32_t ahf[4][4], alf[4][4];                                    \
            uint32_t bhf[2][4], blf[2][4];                                    \
            _Pragma("unroll")                                                 \
            for (int mt = 0; mt < 4; mt++) {                                  \
                uint32_t ao = (uint32_t)((warp_m * 64 + mt * 16 + dr) * PP    \
                                         + k0 + dka) * 2;                     \
                LDSM_X4(ahf[mt], aAh + ao);                                   \
                LDSM_X4(alf[mt], aAl + ao);                                   \
            }                                                                 \
            _Pragma("unroll")                                                 \
            for (int pr = 0; pr < 2; pr++) {                                  \
                uint32_t bo = (uint32_t)((warp_n * 32 + pr * 16 + dn) * PP    \
                                         + k0 + dkb) * 2;                     \
                LDSM_X4(bhf[pr], aBh + bo);                                   \
                LDSM_X4(blf[pr], aBl + bo);                                   \
            }                                                                 \
            _Pragma("unroll")                                                 \
            for (int mt = 0; mt < 4; mt++)                                    \
                _Pragma("unroll")                                             \
                for (int nt = 0; nt < 4; nt++) {                              \
                    const int pr = nt >> 1, sb2 = (nt & 1) * 2;               \
                    MMA16816(acc[mt][nt], ahf[mt], bhf[pr][sb2], bhf[pr][sb2 + 1]); \
                    MMA16816(acc[mt][nt], ahf[mt], blf[pr][sb2], blf[pr][sb2 + 1]); \
                    MMA16816(acc[mt][nt], alf[mt], bhf[pr][sb2], bhf[pr][sb2 + 1]); \
                }                                                             \
        }                                                                     \
        __syncthreads();                                                      \
    }

// ---------------------------------------------------------------------------
// gemm_mma: generic fp32 output + bias (used for the output projection)
// ---------------------------------------------------------------------------
__global__ __launch_bounds__(256, 1) void gemm_mma(
    const __nv_bfloat16* __restrict__ Ah, const __nv_bfloat16* __restrict__ Al,
    const __nv_bfloat16* __restrict__ Bh, const __nv_bfloat16* __restrict__ Bl,
    const float* __restrict__ bias, float* __restrict__ C,
    int M, int N, int K)
{
    extern __shared__ char dyn[];
    const int tid = threadIdx.x;
    const int wid = tid >> 5, l = tid & 31;
    const int warp_m = wid & 1, warp_n = wid >> 1;
    const int bc = blockIdx.x, br = blockIdx.y;
    const int arow0 = br * 128, bcol0 = bc * 128;

    const int mat = l >> 3;
    const int dr  = (mat & 1) * 8 + (l & 7);
    const int dka = (mat >> 1) * 8;
    const int dn  = (mat >> 1) * 8 + (l & 7);
    const int dkb = (mat & 1) * 8;

    float acc[4][4][4];
    #pragma unroll
    for (int i = 0; i < 4; i++)
        #pragma unroll
        for (int j = 0; j < 4; j++)
            #pragma unroll
            for (int q = 0; q < 4; q++) acc[i][j][q] = 0.f;

    GEMM_MAINLOOP(Ah, Al, Bh, Bl, K)

    const int rbase = arow0 + warp_m * 64 + (l >> 2);
    const int cbase = bcol0 + warp_n * 32 + (l & 3) * 2;
    #pragma unroll
    for (int mt = 0; mt < 4; mt++)
        #pragma unroll
        for (int nt = 0; nt < 4; nt++) {
            const int row = rbase + mt * 16;
            const int col = cbase + nt * 8;
            float2 v0, v1;
            v0.x = acc[mt][nt][0] + bias[col];
            v0.y = acc[mt][nt][1] + bias[col + 1];
            v1.x = acc[mt][nt][2] + bias[col];
            v1.y = acc[mt][nt][3] + bias[col + 1];
            *(float2*)(C + (size_t)row * N + col) = v0;
            *(float2*)(C + (size_t)(row + 8) * N + col) = v1;
        }
}

// ---------------------------------------------------------------------------
// gemm_qkv: QKV projection with fused split epilogue.
// Q cols (bc<8)  -> qh/ql bf16 split, 0.125 scale folded, token-major.
// K cols (bc<16) -> kh/kl bf16 split, head-major.
// V cols         -> vh/vl fp16 split, head-major.
// ---------------------------------------------------------------------------
__global__ __launch_bounds__(256, 1) void gemm_qkv(
    const __nv_bfloat16* __restrict__ Ah, const __nv_bfloat16* __restrict__ Al,
    const __nv_bfloat16* __restrict__ Bh, const __nv_bfloat16* __restrict__ Bl,
    const float* __restrict__ bias,
    __nv_bfloat16* __restrict__ qh, __nv_bfloat16* __restrict__ ql,
    __nv_bfloat16* __restrict__ kh, __nv_bfloat16* __restrict__ kl,
    __half* __restrict__ vh, __half* __restrict__ vl)
{
    extern __shared__ char dyn[];
    const int tid = threadIdx.x;
    const int wid = tid >> 5, l = tid & 31;
    const int warp_m = wid & 1, warp_n = wid >> 1;
    const int bc = blockIdx.x, br = blockIdx.y;
    const int arow0 = br * 128, bcol0 = bc * 128;
    const int K = CCH;

    const int mat = l >> 3;
    const int dr  = (mat & 1) * 8 + (l & 7);
    const int dka = (mat >> 1) * 8;
    const int dn  = (mat >> 1) * 8 + (l & 7);
    const int dkb = (mat & 1) * 8;

    float acc[4][4][4];
    #pragma unroll
    for (int i = 0; i < 4; i++)
        #pragma unroll
        for (int j = 0; j < 4; j++)
            #pragma unroll
            for (int q = 0; q < 4; q++) acc[i][j][q] = 0.f;

    GEMM_MAINLOOP(Ah, Al, Bh, Bl, K)

    const int rbase = arow0 + warp_m * 64 + (l >> 2);
    const int cbase = bcol0 + warp_n * 32 + (l & 3) * 2;
    #pragma unroll
    for (int mt = 0; mt < 4; mt++)
        #pragma unroll
        for (int nt = 0; nt < 4; nt++) {
            #pragma unroll
            for (int half2i = 0; half2i < 2; half2i++) {
                const int row = rbase + mt * 16 + half2i * 8;
                const int col = cbase + nt * 8;
                float v0 = acc[mt][nt][half2i * 2 + 0] + bias[col];
                float v1 = acc[mt][nt][half2i * 2 + 1] + bias[col + 1];
                if (bc < 8) {
                    // Q: scale fold + bf16 split, token-major
                    v0 *= 0.125f; v1 *= 0.125f;
                    __nv_bfloat16 h0 = __float2bfloat16(v0);
                    __nv_bfloat16 h1 = __float2bfloat16(v1);
                    size_t o = (size_t)row * DA + col;
                    *(__nv_bfloat162*)(qh + o) = __nv_bfloat162(h0, h1);
                    *(__nv_bfloat162*)(ql + o) = __nv_bfloat162(
                        __float2bfloat16(v0 - __bfloat162float(h0)),
                        __float2bfloat16(v1 - __bfloat162float(h1)));
                } else {
                    const int cg = col - (bc < 16 ? 1024 : 2048);
                    const int head = cg >> 6, d = cg & 63;
                    const int t = row & (TT - 1), bb = row >> 11;
                    size_t o = ((size_t)(bb * NH + head) * TT + t) * 64 + d;
                    if (bc < 16) {
                        __nv_bfloat16 h0 = __float2bfloat16(v0);
                        __nv_bfloat16 h1 = __float2bfloat16(v1);
                        *(__nv_bfloat162*)(kh + o) = __nv_bfloat162(h0, h1);
                        *(__nv_bfloat162*)(kl + o) = __nv_bfloat162(
                            __float2bfloat16(v0 - __bfloat162float(h0)),
                            __float2bfloat16(v1 - __bfloat162float(h1)));
                    } else {
                        __half h0 = __float2half_rn(v0);
                        __half h1 = __float2half_rn(v1);
                        *(__half2*)(vh + o) = __half2(h0, h1);
                        *(__half2*)(vl + o) = __half2(
                            __float2half_rn(v0 - __half2float(h0)),
                            __float2half_rn(v1 - __half2float(h1)));
                    }
                }
            }
        }
}

// ---------------------------------------------------------------------------
// Tensor-core flash attention v3 (causal), 3-stage cp.async K/V pipeline.
// CTA = (qt, h, b): 128 q-rows, 8 warps x 16 rows. Key tiles of 64.
// Q read from pre-split qh/ql. Writes split bf16 (ah/al) for phase-3 GEMM.
// ---------------------------------------------------------------------------
#define QPF 72                              // smem pitch in b16 elems
#define KVT_B (64 * QPF * 2)                // 9216 B per array tile
#define KV_STAGE (4 * KVT_B)                // 36864 B
#define FL_DYN (3 * KV_STAGE)               // 110592 B

static __device__ __forceinline__ void flash_issue(
    uint32_t stage, const char* kh, const char* kl,
    const char* vh, const char* vl, size_t tile_off, int tid)
{
    const char* srcs[4] = {kh + tile_off, kl + tile_off, vh + tile_off, vl + tile_off};
    #pragma unroll
    for (int i = 0; i < 8; i++) {
        int idx = i * 256 + tid;
        int arr = idx >> 9, rem = idx & 511;
        int r = rem >> 3, c = rem & 7;
        CP_A16(stage + arr * KVT_B + r * (QPF * 2) + c * 16,
               srcs[arr] + r * 128 + c * 16);
    }
}

__global__ __launch_bounds__(256, 1) void flash_mma(
    const __nv_bfloat16* __restrict__ qh_g, const __nv_bfloat16* __restrict__ ql_g,
    const __nv_bfloat16* __restrict__ kh_g, const __nv_bfloat16* __restrict__ kl_g,
    const __half* __restrict__ vh_g, const __half* __restrict__ vl_g,
    __nv_bfloat16* __restrict__ oh, __nv_bfloat16* __restrict__ ol)
{
    extern __shared__ char fsm[];
    const int tid = threadIdx.x;
    const int w = tid >> 5, l = tid & 31;
    const int qt = blockIdx.x, h = blockIdx.y, b = blockIdx.z;

    const uint32_t sbase = smem_u32(fsm);

    // Stage Q (pre-split, 128 rows x 64 dims per array) into stage-0 buffer
    {
        const char* q0 = (const char*)qh_g
            + ((size_t)(b * TT + qt * 128) * DA + h * 64) * 2;
        const char* q1 = (const char*)ql_g
            + ((size_t)(b * TT + qt * 128) * DA + h * 64) * 2;
        const char* srcs[2] = {q0, q1};
        #pragma unroll
        for (int i = 0; i < 8; i++) {
            int idx = i * 256 + tid;
            int arr = idx >> 10, rem = idx & 1023;
            int r = rem >> 3, c = rem & 7;
            CP_A16(sbase + arr * (128 * QPF * 2) + r * (QPF * 2) + c * 16,
                   srcs[arr] + (size_t)r * (DA * 2) + c * 16);
        }
    }
    CP_COMMIT();
    CP_WAIT0();
    __syncthreads();

    const int mat = l >> 3;
    const int dr  = (mat & 1) * 8 + (l & 7);
    const int dka = (mat >> 1) * 8;
    const int dn  = (mat >> 1) * 8 + (l & 7);
    const int dkb = (mat & 1) * 8;

    uint32_t qh[4][4], ql[4][4];
    #pragma unroll
    for (int t = 0; t < 4; t++) {
        uint32_t ao = (uint32_t)((w * 16 + dr) * QPF + t * 16 + dka) * 2;
        LDSM_X4(qh[t], sbase + ao);
        LDSM_X4(ql[t], sbase + 128 * QPF * 2 + ao);
    }
    __syncthreads();   // all Q frags read before stage0 reuse

    float o[8][4];
    #pragma unroll
    for (int nt = 0; nt < 8; nt++)
        #pragma unroll
        for (int e = 0; e < 4; e++) o[nt][e] = 0.f;
    float m_a = -INFINITY, m_b = -INFINITY, l_a = 0.f, l_b = 0.f;

    const size_t headoff = ((size_t)(b * NH + h) * TT) * 64 * 2;  // bytes
    const char* kh_c = (const char*)kh_g + headoff;
    const char* kl_c = (const char*)kl_g + headoff;
    const char* vh_c = (const char*)vh_g + headoff;
    const char* vl_c = (const char*)vl_g + headoff;
    const int jmax = 2 * qt + 1;

    flash_issue(sbase, kh_c, kl_c, vh_c, vl_c, 0, tid);
    CP_COMMIT();
    flash_issue(sbase + KV_STAGE, kh_c, kl_c, vh_c, vl_c, 8192, tid);
    CP_COMMIT();

    for (int j = 0; j <= jmax; j++) {
        const int st = j % 3;
        if (j + 2 <= jmax) {
            flash_issue(sbase + (uint32_t)((j + 2) % 3) * KV_STAGE,
                        kh_c, kl_c, vh_c, vl_c, (size_t)(j + 2) * 8192, tid);
            CP_COMMIT(); CP_WAIT2();
        } else if (j + 1 <= jmax) { CP_WAIT1(); } else { CP_WAIT0(); }
        __syncthreads();

        const bool active = (j * 64 <= qt * 128 + w * 16 + 15);
        if (active) {
            const uint32_t sb = sbase + (uint32_t)st * KV_STAGE;
            const uint32_t aKh = sb, aKl = sb + KVT_B;
            const uint32_t aVh = sb + 2 * KVT_B, aVl = sb + 3 * KVT_B;

            float c[8][4];
            #pragma unroll
            for (int nt = 0; nt < 8; nt++)
                #pragma unroll
                for (int e = 0; e < 4; e++) c[nt][e] = 0.f;

            #pragma unroll
            for (int t = 0; t < 4; t++) {
                #pragma unroll
                for (int p = 0; p < 4; p++) {
                    uint32_t kb[4], kl2[4];
                    uint32_t bo = (uint32_t)((p * 16 + dn) * QPF + t * 16 + dkb) * 2;
                    LDSM_X4(kb, aKh + bo);
                    LDSM_X4(kl2, aKl + bo);
                    #pragma unroll
                    for (int sub = 0; sub < 2; sub++) {
                        const int nt = 2 * p + sub;
                        MMA16816(c[nt], qh[t], kb[sub * 2], kb[sub * 2 + 1]);
                        MMA16816(c[nt], qh[t], kl2[sub * 2], kl2[sub * 2 + 1]);
                        MMA16816(c[nt], ql[t], kb[sub * 2], kb[sub * 2 + 1]);
                    }
                }
            }

            if (j >= 2 * qt) {
                const int qa = qt * 128 + w * 16 + (l >> 2);
                const int kc0 = j * 64 + (l & 3) * 2;
                #pragma unroll
                for (int nt = 0; nt < 8; nt++) {
                    int col = kc0 + nt * 8;
                    if (col > qa)     c[nt][0] = -INFINITY;
                    if (col + 1 > qa) c[nt][1] = -INFINITY;
                    if (col > qa + 8)     c[nt][2] = -INFINITY;
                    if (col + 1 > qa + 8) c[nt][3] = -INFINITY;
                }
            }

            float ma = -INFINITY, mb = -INFINITY;
            #pragma unroll
            for (int nt = 0; nt < 8; nt++) {
                ma = fmaxf(ma, fmaxf(c[nt][0], c[nt][1]));
                mb = fmaxf(mb, fmaxf(c[nt][2], c[nt][3]));
            }
            ma = fmaxf(ma, __shfl_xor_sync(0xffffffffu, ma, 1));
            ma = fmaxf(ma, __shfl_xor_sync(0xffffffffu, ma, 2));
            mb = fmaxf(mb, __shfl_xor_sync(0xffffffffu, mb, 1));
            mb = fmaxf(mb, __shfl_xor_sync(0xffffffffu, mb, 2));
            float mna = fmaxf(m_a, ma), mnb = fmaxf(m_b, mb);
            float aa = __expf(m_a - mna), ab = __expf(m_b - mnb);
            float sa = 0.f, sb2 = 0.f;
            #pragma unroll
            for (int nt = 0; nt < 8; nt++) {
                c[nt][0] = __expf(c[nt][0] - mna);
                c[nt][1] = __expf(c[nt][1] - mna);
                c[nt][2] = __expf(c[nt][2] - mnb);
                c[nt][3] = __expf(c[nt][3] - mnb);
                sa += c[nt][0] + c[nt][1];
                sb2 += c[nt][2] + c[nt][3];
            }
            sa += __shfl_xor_sync(0xffffffffu, sa, 1);
            sa += __shfl_xor_sync(0xffffffffu, sa, 2);
            sb2 += __shfl_xor_sync(0xffffffffu, sb2, 1);
            sb2 += __shfl_xor_sync(0xffffffffu, sb2, 2);
            l_a = l_a * aa + sa;
            l_b = l_b * ab + sb2;
            m_a = mna; m_b = mnb;
            #pragma unroll
            for (int nt = 0; nt < 8; nt++) {
                o[nt][0] *= aa; o[nt][1] *= aa;
                o[nt][2] *= ab; o[nt][3] *= ab;
            }

            #pragma unroll
            for (int t = 0; t < 4; t++) {
                uint32_t pa[4];
                pa[0] = packh2(c[2 * t][0],     c[2 * t][1]);
                pa[1] = packh2(c[2 * t][2],     c[2 * t][3]);
                pa[2] = packh2(c[2 * t + 1][0], c[2 * t + 1][1]);
                pa[3] = packh2(c[2 * t + 1][2], c[2 * t + 1][3]);
                #pragma unroll
                for (int p = 0; p < 4; p++) {
                    uint32_t vb[4], vl2[4];
                    uint32_t vo = (uint32_t)((t * 16 + (mat & 1) * 8 + (l & 7)) * QPF
                                             + p * 16 + (mat >> 1) * 8) * 2;
                    LDSM_X4_T(vb, aVh + vo);
                    LDSM_X4_T(vl2, aVl + vo);
                    MMA16816H(o[2 * p],     pa, vb[0], vb[1]);
                    MMA16816H(o[2 * p + 1], pa, vb[2], vb[3]);
                    MMA16816H(o[2 * p],     pa, vl2[0], vl2[1]);
                    MMA16816H(o[2 * p + 1], pa, vl2[2], vl2[3]);
                }
            }
        }
        __syncthreads();
    }

    // Epilogue: write split bf16 directly (feeds phase-3 GEMM)
    const float ia = 1.f / l_a, ib = 1.f / l_b;
    const int row = (b * TT + qt * 128 + w * 16 + (l >> 2));
    const int col = h * 64 + (l & 3) * 2;
    #pragma unroll
    for (int nt = 0; nt < 8; nt++) {
        float v0 = o[nt][0] * ia, v1 = o[nt][1] * ia;
        float v2 = o[nt][2] * ib, v3 = o[nt][3] * ib;
        __nv_bfloat16 h0 = __float2bfloat16(v0), h1 = __float2bfloat16(v1);
        __nv_bfloat16 h2 = __float2bfloat16(v2), h3 = __float2bfloat16(v3);
        size_t o0 = (size_t)row * DA + col + nt * 8;
        size_t o1 = (size_t)(row + 8) * DA + col + nt * 8;
        *(__nv_bfloat162*)(oh + o0) = __nv_bfloat162(h0, h1);
        *(__nv_bfloat162*)(ol + o0) = __nv_bfloat162(
            __float2bfloat16(v0 - __bfloat162float(h0)),
            __float2bfloat16(v1 - __bfloat162float(h1)));
        *(__nv_bfloat162*)(oh + o1) = __nv_bfloat162(h2, h3);
        *(__nv_bfloat162*)(ol + o1) = __nv_bfloat162(
            __float2bfloat16(v2 - __bfloat162float(h2)),
            __float2bfloat16(v3 - __bfloat162float(h3)));
    }
}

// ---------------------------------------------------------------------------
// Launch
// ---------------------------------------------------------------------------
extern "C" void kernel_launch(void* const* d_in, const int* in_sizes, int n_in,
                              void* d_out, int out_size)
{
    const float* x    = (const float*)d_in[0];
    const float* Wqkv = (const float*)d_in[2];
    const float* bqkv = (const float*)d_in[3];
    const float* Wout = (const float*)d_in[4];
    const float* bout = (const float*)d_in[5];
    float* out = (float*)d_out;

    __nv_bfloat16 *ah, *al, *bh, *bl, *qh, *ql, *kh, *kl;
    __half *vh, *vl;
    cudaGetSymbolAddress((void**)&ah, g_ah);
    cudaGetSymbolAddress((void**)&al, g_al);
    cudaGetSymbolAddress((void**)&bh, g_bh);
    cudaGetSymbolAddress((void**)&bl, g_bl);
    cudaGetSymbolAddress((void**)&qh, g_qh);
    cudaGetSymbolAddress((void**)&ql, g_ql);
    cudaGetSymbolAddress((void**)&kh, g_kh);
    cudaGetSymbolAddress((void**)&kl, g_kl);
    cudaGetSymbolAddress((void**)&vh, g_vh);
    cudaGetSymbolAddress((void**)&vl, g_vl);

    cudaFuncSetAttribute(gemm_mma,
                         cudaFuncAttributeMaxDynamicSharedMemorySize, (int)GEMM_DYN);
    cudaFuncSetAttribute(gemm_qkv,
                         cudaFuncAttributeMaxDynamicSharedMemorySize, (int)GEMM_DYN);
    cudaFuncSetAttribute(flash_mma,
                         cudaFuncAttributeMaxDynamicSharedMemorySize, (int)FL_DYN);

    // Phase 1: QKV projection with fused split epilogue
    split_f4<<<(MM * CCH / 4 + 255) / 256, 256>>>(x, ah, al, MM * CCH / 4);
    transpose_split<<<dim3(3 * DA / 32, CCH / 32), dim3(32, 8)>>>(Wqkv, bh, bl, CCH, 3 * DA);
    gemm_qkv<<<dim3(3 * DA / 128, MM / 128), 256, GEMM_DYN>>>(
        ah, al, bh, bl, bqkv, qh, ql, kh, kl, vh, vl);

    // Phase 2: tensor-core flash (writes split attn to ah/al)
    flash_mma<<<dim3(TT / 128, NH, BV), 256, FL_DYN>>>(
        qh, ql, kh, kl, vh, vl, ah, al);

    // Phase 3: out = attn @ Wout + b
    transpose_split<<<dim3(CCH / 32, DA / 32), dim3(32, 8)>>>(Wout, bh, bl, DA, CCH);
    gemm_mma<<<dim3(CCH / 128, MM / 128), 256, GEMM_DYN>>>(
        ah, al, bh, bl, bout, out, MM, CCH, DA);
}

// round 9
// speedup vs baseline: 4.1768x; 1.0984x over previous
#include <cuda_runtime.h>
#include <cuda_bf16.h>
#include <cuda_fp16.h>
#include <math.h>
#include <stdint.h>

// Problem constants
#define BV 4
#define TT 2048
#define CCH 1024
#define DA 1024
#define NH 16
#define HDM 64
#define MM (BV * TT)   // 8192 rows

// ---------------------------------------------------------------------------
// Device scratch (allocations forbidden; __device__ globals are sanctioned)
// ---------------------------------------------------------------------------
__device__ __nv_bfloat16 g_ah[(size_t)MM * CCH];          // A split hi (x / attn)
__device__ __nv_bfloat16 g_al[(size_t)MM * CCH];          // A split lo
__device__ __nv_bfloat16 g_bh[(size_t)CCH * 3 * DA];      // W^T split hi
__device__ __nv_bfloat16 g_bl[(size_t)CCH * 3 * DA];      // W^T split lo
__device__ __nv_bfloat16 g_qh[(size_t)MM * DA];           // Q split (scaled)
__device__ __nv_bfloat16 g_ql[(size_t)MM * DA];
__device__ __nv_bfloat16 g_kh[(size_t)MM * DA];           // head-major K split
__device__ __nv_bfloat16 g_kl[(size_t)MM * DA];
__device__ __half        g_vh[(size_t)MM * DA];           // head-major V split
__device__ __half        g_vl[(size_t)MM * DA];

__device__ __forceinline__ uint32_t smem_u32(const void* p) {
    uint32_t a;
    asm("{ .reg .u64 t; cvta.to.shared.u64 t, %1; cvt.u32.u64 %0, t; }"
        : "=r"(a) : "l"(p));
    return a;
}

#define LDSM_X4(r, addr) \
    asm volatile("ldmatrix.sync.aligned.m8n8.x4.shared.b16 {%0,%1,%2,%3}, [%4];" \
        : "=r"((r)[0]), "=r"((r)[1]), "=r"((r)[2]), "=r"((r)[3]) : "r"(addr))

#define LDSM_X4_T(r, addr) \
    asm volatile("ldmatrix.sync.aligned.m8n8.x4.trans.shared.b16 {%0,%1,%2,%3}, [%4];" \
        : "=r"((r)[0]), "=r"((r)[1]), "=r"((r)[2]), "=r"((r)[3]) : "r"(addr))

#define MMA16816(c, a, b0, b1) \
    asm volatile("mma.sync.aligned.m16n8k16.row.col.f32.bf16.bf16.f32 " \
        "{%0,%1,%2,%3}, {%4,%5,%6,%7}, {%8,%9}, {%0,%1,%2,%3};" \
        : "+f"((c)[0]), "+f"((c)[1]), "+f"((c)[2]), "+f"((c)[3]) \
        : "r"((a)[0]), "r"((a)[1]), "r"((a)[2]), "r"((a)[3]), "r"(b0), "r"(b1))

#define MMA16816H(c, a, b0, b1) \
    asm volatile("mma.sync.aligned.m16n8k16.row.col.f32.f16.f16.f32 " \
        "{%0,%1,%2,%3}, {%4,%5,%6,%7}, {%8,%9}, {%0,%1,%2,%3};" \
        : "+f"((c)[0]), "+f"((c)[1]), "+f"((c)[2]), "+f"((c)[3]) \
        : "r"((a)[0]), "r"((a)[1]), "r"((a)[2]), "r"((a)[3]), "r"(b0), "r"(b1))

#define CP_A16(dst, src) \
    asm volatile("cp.async.cg.shared.global [%0], [%1], 16;" \
                 :: "r"(dst), "l"(src) : "memory")
#define CP_COMMIT() asm volatile("cp.async.commit_group;" ::: "memory")
#define CP_WAIT1()  asm volatile("cp.async.wait_group 1;" ::: "memory")
#define CP_WAIT0()  asm volatile("cp.async.wait_group 0;" ::: "memory")

__device__ __forceinline__ uint32_t packh2(float a, float b) {
    __half2 h = __floats2half2_rn(a, b);
    return *(uint32_t*)&h;
}

// ---------------------------------------------------------------------------
// split_f4: fp32 -> (bf16 hi, bf16 lo), elementwise  (input x only)
// ---------------------------------------------------------------------------
__global__ void split_f4(const float* __restrict__ src,
                         __nv_bfloat16* __restrict__ hi,
                         __nv_bfloat16* __restrict__ lo, int n4)
{
    int i = blockIdx.x * blockDim.x + threadIdx.x;
    if (i >= n4) return;
    float4 v = ((const float4*)src)[i];
    __nv_bfloat16 h0 = __float2bfloat16(v.x), h1 = __float2bfloat16(v.y);
    __nv_bfloat16 h2 = __float2bfloat16(v.z), h3 = __float2bfloat16(v.w);
    __nv_bfloat16 l0 = __float2bfloat16(v.x - __bfloat162float(h0));
    __nv_bfloat16 l1 = __float2bfloat16(v.y - __bfloat162float(h1));
    __nv_bfloat16 l2 = __float2bfloat16(v.z - __bfloat162float(h2));
    __nv_bfloat16 l3 = __float2bfloat16(v.w - __bfloat162float(h3));
    ((__nv_bfloat162*)hi)[2 * i]     = __nv_bfloat162(h0, h1);
    ((__nv_bfloat162*)hi)[2 * i + 1] = __nv_bfloat162(h2, h3);
    ((__nv_bfloat162*)lo)[2 * i]     = __nv_bfloat162(l0, l1);
    ((__nv_bfloat162*)lo)[2 * i + 1] = __nv_bfloat162(l2, l3);
}

// W[K][N] -> Th/Tl[N][K] with split. 32x32 smem-tiled transpose.
__global__ void transpose_split(const float* __restrict__ W,
                                __nv_bfloat16* __restrict__ Th,
                                __nv_bfloat16* __restrict__ Tl, int K, int N)
{
    __shared__ float tile[32][33];
    int tx = threadIdx.x, ty = threadIdx.y;
    int n0 = blockIdx.x * 32, k0 = blockIdx.y * 32;
    #pragma unroll
    for (int j = 0; j < 32; j += 8)
        tile[ty + j][tx] = W[(size_t)(k0 + ty + j) * N + n0 + tx];
    __syncthreads();
    #pragma unroll
    for (int j = 0; j < 32; j += 8) {
        float v = tile[tx][ty + j];
        __nv_bfloat16 h = __float2bfloat16(v);
        __nv_bfloat16 l = __float2bfloat16(v - __bfloat162float(h));
        size_t o = (size_t)(n0 + ty + j) * K + k0 + tx;
        Th[o] = h;
        Tl[o] = l;
    }
}

// ---------------------------------------------------------------------------
// Shared GEMM mainloop (CTA 128x128, 8 warps 2x4, KC=64, 3-stage, 1 barrier)
// ---------------------------------------------------------------------------
#define KC 64
#define PP 72                               // smem pitch in bf16 (144 B rows)
#define MAT_B (128 * PP * 2)                // 18432 B
#define STAGE_B (4 * MAT_B)                 // 73728 B
#define GEMM_DYN (3 * STAGE_B)              // 221184 B

static __device__ __forceinline__ void gemm_issue(
    uint32_t stage, const char* a0, const char* a1,
    const char* a2, const char* a3, int Kb, int k0b, int tid)
{
    const char* srcs[4] = {a0, a1, a2, a3};
    #pragma unroll
    for (int i = 0; i < 16; i++) {
        int idx = i * 256 + tid;
        int arr = idx >> 10, rem = idx & 1023;
        int row = rem >> 3, c = rem & 7;
        CP_A16(stage + arr * MAT_B + row * (PP * 2) + c * 16,
               srcs[arr] + (size_t)row * Kb + k0b + c * 16);
    }
}

// Mainloop macro body: computes acc[4][4][4] for this CTA tile.
#define GEMM_MAINLOOP(Ah, Al, Bh, Bl, K)                                      \
    const uint32_t sbase = smem_u32(dyn);                                     \
    const int NCH = (K) / KC;                                                 \
    const int Kb = (K) * 2;                                                   \
    const char* a0 = (const char*)((Ah) + (size_t)arow0 * (K));               \
    const char* a1 = (const char*)((Al) + (size_t)arow0 * (K));               \
    const char* a2 = (const char*)((Bh) + (size_t)bcol0 * (K));               \
    const char* a3 = (const char*)((Bl) + (size_t)bcol0 * (K));               \
    gemm_issue(sbase, a0, a1, a2, a3, Kb, 0, tid); CP_COMMIT();               \
    gemm_issue(sbase + STAGE_B, a0, a1, a2, a3, Kb, KC * 2, tid); CP_COMMIT();\
    for (int c = 0; c < NCH; c++) {                                           \
        if (c < NCH - 1) { CP_WAIT1(); } else { CP_WAIT0(); }                 \
        __syncthreads();                                                      \
        if (c + 2 < NCH) {                                                    \
            gemm_issue(sbase + (uint32_t)((c + 2) % 3) * STAGE_B,             \
                       a0, a1, a2, a3, Kb, (c + 2) * KC * 2, tid);            \
            CP_COMMIT();                                                      \
        }                                                                     \
        const uint32_t stb = sbase + (uint32_t)(c % 3) * STAGE_B;             \
        const uint32_t aAh = stb + 0 * MAT_B;                                 \
        const uint32_t aAl = stb + 1 * MAT_B;                                 \
        const uint32_t aBh = stb + 2 * MAT_B;                                 \
        const uint32_t aBl = stb + 3 * MAT_B;                                 \
        _Pragma("unroll")                                                     \
        for (int ks = 0; ks < KC / 16; ks++) {                                \
            const int k0 = ks * 16;                                           \
            uint32_t ahf[4][4], alf[4][4];                                    \
            uint32_t bhf[2][4], blf[2][4];                                    \
            _Pragma("unroll")                                                 \
            for (int mt = 0; mt < 4; mt++) {                                  \
                uint32_t ao = (uint32_t)((warp_m * 64 + mt * 16 + dr) * PP    \
                                         + k0 + dka) * 2;                     \
                LDSM_X4(ahf[mt], aAh + ao);                                   \
                LDSM_X4(alf[mt], aAl + ao);                                   \
            }                                                                 \
            _Pragma("unroll")                                                 \
            for (int pr = 0; pr < 2; pr++) {                                  \
                uint32_t bo = (uint32_t)((warp_n * 32 + pr * 16 + dn) * PP    \
                                         + k0 + dkb) * 2;                     \
                LDSM_X4(bhf[pr], aBh + bo);                                   \
                LDSM_X4(blf[pr], aBl + bo);                                   \
            }                                                                 \
            _Pragma("unroll")                                                 \
            for (int mt = 0; mt < 4; mt++)                                    \
                _Pragma("unroll")                                             \
                for (int nt = 0; nt < 4; nt++) {                              \
                    const int pr = nt >> 1, sb2 = (nt & 1) * 2;               \
                    MMA16816(acc[mt][nt], ahf[mt], bhf[pr][sb2], bhf[pr][sb2 + 1]); \
                    MMA16816(acc[mt][nt], ahf[mt], blf[pr][sb2], blf[pr][sb2 + 1]); \
                    MMA16816(acc[mt][nt], alf[mt], bhf[pr][sb2], bhf[pr][sb2 + 1]); \
                }                                                             \
        }                                                                     \
        __syncthreads();                                                      \
    }

// ---------------------------------------------------------------------------
// gemm_mma: generic fp32 output + bias (output projection)
// ---------------------------------------------------------------------------
__global__ __launch_bounds__(256, 1) void gemm_mma(
    const __nv_bfloat16* __restrict__ Ah, const __nv_bfloat16* __restrict__ Al,
    const __nv_bfloat16* __restrict__ Bh, const __nv_bfloat16* __restrict__ Bl,
    const float* __restrict__ bias, float* __restrict__ C,
    int M, int N, int K)
{
    extern __shared__ char dyn[];
    const int tid = threadIdx.x;
    const int wid = tid >> 5, l = tid & 31;
    const int warp_m = wid & 1, warp_n = wid >> 1;
    const int bc = blockIdx.x, br = blockIdx.y;
    const int arow0 = br * 128, bcol0 = bc * 128;

    const int mat = l >> 3;
    const int dr  = (mat & 1) * 8 + (l & 7);
    const int dka = (mat >> 1) * 8;
    const int dn  = (mat >> 1) * 8 + (l & 7);
    const int dkb = (mat & 1) * 8;

    float acc[4][4][4];
    #pragma unroll
    for (int i = 0; i < 4; i++)
        #pragma unroll
        for (int j = 0; j < 4; j++)
            #pragma unroll
            for (int q = 0; q < 4; q++) acc[i][j][q] = 0.f;

    GEMM_MAINLOOP(Ah, Al, Bh, Bl, K)

    const int rbase = arow0 + warp_m * 64 + (l >> 2);
    const int cbase = bcol0 + warp_n * 32 + (l & 3) * 2;
    #pragma unroll
    for (int mt = 0; mt < 4; mt++)
        #pragma unroll
        for (int nt = 0; nt < 4; nt++) {
            const int row = rbase + mt * 16;
            const int col = cbase + nt * 8;
            float2 v0, v1;
            v0.x = acc[mt][nt][0] + bias[col];
            v0.y = acc[mt][nt][1] + bias[col + 1];
            v1.x = acc[mt][nt][2] + bias[col];
            v1.y = acc[mt][nt][3] + bias[col + 1];
            *(float2*)(C + (size_t)row * N + col) = v0;
            *(float2*)(C + (size_t)(row + 8) * N + col) = v1;
        }
}

// ---------------------------------------------------------------------------
// gemm_qkv: QKV projection with fused split epilogue (Q/K/V consumer formats)
// ---------------------------------------------------------------------------
__global__ __launch_bounds__(256, 1) void gemm_qkv(
    const __nv_bfloat16* __restrict__ Ah, const __nv_bfloat16* __restrict__ Al,
    const __nv_bfloat16* __restrict__ Bh, const __nv_bfloat16* __restrict__ Bl,
    const float* __restrict__ bias,
    __nv_bfloat16* __restrict__ qh, __nv_bfloat16* __restrict__ ql,
    __nv_bfloat16* __restrict__ kh, __nv_bfloat16* __restrict__ kl,
    __half* __restrict__ vh, __half* __restrict__ vl)
{
    extern __shared__ char dyn[];
    const int tid = threadIdx.x;
    const int wid = tid >> 5, l = tid & 31;
    const int warp_m = wid & 1, warp_n = wid >> 1;
    const int bc = blockIdx.x, br = blockIdx.y;
    const int arow0 = br * 128, bcol0 = bc * 128;
    const int K = CCH;

    const int mat = l >> 3;
    const int dr  = (mat & 1) * 8 + (l & 7);
    const int dka = (mat >> 1) * 8;
    const int dn  = (mat >> 1) * 8 + (l & 7);
    const int dkb = (mat & 1) * 8;

    float acc[4][4][4];
    #pragma unroll
    for (int i = 0; i < 4; i++)
        #pragma unroll
        for (int j = 0; j < 4; j++)
            #pragma unroll
            for (int q = 0; q < 4; q++) acc[i][j][q] = 0.f;

    GEMM_MAINLOOP(Ah, Al, Bh, Bl, K)

    const int rbase = arow0 + warp_m * 64 + (l >> 2);
    const int cbase = bcol0 + warp_n * 32 + (l & 3) * 2;
    #pragma unroll
    for (int mt = 0; mt < 4; mt++)
        #pragma unroll
        for (int nt = 0; nt < 4; nt++) {
            #pragma unroll
            for (int half2i = 0; half2i < 2; half2i++) {
                const int row = rbase + mt * 16 + half2i * 8;
                const int col = cbase + nt * 8;
                float v0 = acc[mt][nt][half2i * 2 + 0] + bias[col];
                float v1 = acc[mt][nt][half2i * 2 + 1] + bias[col + 1];
                if (bc < 8) {
                    v0 *= 0.125f; v1 *= 0.125f;
                    __nv_bfloat16 h0 = __float2bfloat16(v0);
                    __nv_bfloat16 h1 = __float2bfloat16(v1);
                    size_t o = (size_t)row * DA + col;
                    *(__nv_bfloat162*)(qh + o) = __nv_bfloat162(h0, h1);
                    *(__nv_bfloat162*)(ql + o) = __nv_bfloat162(
                        __float2bfloat16(v0 - __bfloat162float(h0)),
                        __float2bfloat16(v1 - __bfloat162float(h1)));
                } else {
                    const int cg = col - (bc < 16 ? 1024 : 2048);
                    const int head = cg >> 6, d = cg & 63;
                    const int t = row & (TT - 1), bb = row >> 11;
                    size_t o = ((size_t)(bb * NH + head) * TT + t) * 64 + d;
                    if (bc < 16) {
                        __nv_bfloat16 h0 = __float2bfloat16(v0);
                        __nv_bfloat16 h1 = __float2bfloat16(v1);
                        *(__nv_bfloat162*)(kh + o) = __nv_bfloat162(h0, h1);
                        *(__nv_bfloat162*)(kl + o) = __nv_bfloat162(
                            __float2bfloat16(v0 - __bfloat162float(h0)),
                            __float2bfloat16(v1 - __bfloat162float(h1)));
                    } else {
                        __half h0 = __float2half_rn(v0);
                        __half h1 = __float2half_rn(v1);
                        *(__half2*)(vh + o) = __half2(h0, h1);
                        *(__half2*)(vl + o) = __half2(
                            __float2half_rn(v0 - __half2float(h0)),
                            __float2half_rn(v1 - __half2float(h1)));
                    }
                }
            }
        }
}

// ---------------------------------------------------------------------------
// Tensor-core flash attention v4 (causal), 3-stage cp.async, 1 barrier/iter,
// LPT scheduling (largest q-tiles launch first).
// ---------------------------------------------------------------------------
#define QPF 72                              // smem pitch in b16 elems
#define KVT_B (64 * QPF * 2)                // 9216 B per array tile
#define KV_STAGE (4 * KVT_B)                // 36864 B
#define FL_DYN (3 * KV_STAGE)               // 110592 B

static __device__ __forceinline__ void flash_issue(
    uint32_t stage, const char* kh, const char* kl,
    const char* vh, const char* vl, size_t tile_off, int tid)
{
    const char* srcs[4] = {kh + tile_off, kl + tile_off, vh + tile_off, vl + tile_off};
    #pragma unroll
    for (int i = 0; i < 8; i++) {
        int idx = i * 256 + tid;
        int arr = idx >> 9, rem = idx & 511;
        int r = rem >> 3, c = rem & 7;
        CP_A16(stage + arr * KVT_B + r * (QPF * 2) + c * 16,
               srcs[arr] + r * 128 + c * 16);
    }
}

__global__ __launch_bounds__(256, 1) void flash_mma(
    const __nv_bfloat16* __restrict__ qh_g, const __nv_bfloat16* __restrict__ ql_g,
    const __nv_bfloat16* __restrict__ kh_g, const __nv_bfloat16* __restrict__ kl_g,
    const __half* __restrict__ vh_g, const __half* __restrict__ vl_g,
    __nv_bfloat16* __restrict__ oh, __nv_bfloat16* __restrict__ ol)
{
    extern __shared__ char fsm[];
    const int tid = threadIdx.x;
    const int w = tid >> 5, l = tid & 31;
    const int qt = (int)gridDim.x - 1 - (int)blockIdx.x;   // LPT: big tiles first
    const int h = blockIdx.y, b = blockIdx.z;

    const uint32_t sbase = smem_u32(fsm);

    // Stage Q (pre-split, 128 rows x 64 dims per array) into stage-0 buffer
    {
        const char* q0 = (const char*)qh_g
            + ((size_t)(b * TT + qt * 128) * DA + h * 64) * 2;
        const char* q1 = (const char*)ql_g
            + ((size_t)(b * TT + qt * 128) * DA + h * 64) * 2;
        const char* srcs[2] = {q0, q1};
        #pragma unroll
        for (int i = 0; i < 8; i++) {
            int idx = i * 256 + tid;
            int arr = idx >> 10, rem = idx & 1023;
            int r = rem >> 3, c = rem & 7;
            CP_A16(sbase + arr * (128 * QPF * 2) + r * (QPF * 2) + c * 16,
                   srcs[arr] + (size_t)r * (DA * 2) + c * 16);
        }
    }
    CP_COMMIT();
    CP_WAIT0();
    __syncthreads();

    const int mat = l >> 3;
    const int dr  = (mat & 1) * 8 + (l & 7);
    const int dka = (mat >> 1) * 8;
    const int dn  = (mat >> 1) * 8 + (l & 7);
    const int dkb = (mat & 1) * 8;

    uint32_t qh[4][4], ql[4][4];
    #pragma unroll
    for (int t = 0; t < 4; t++) {
        uint32_t ao = (uint32_t)((w * 16 + dr) * QPF + t * 16 + dka) * 2;
        LDSM_X4(qh[t], sbase + ao);
        LDSM_X4(ql[t], sbase + 128 * QPF * 2 + ao);
    }
    __syncthreads();   // all Q frags read before stage0 reuse

    float o[8][4];
    #pragma unroll
    for (int nt = 0; nt < 8; nt++)
        #pragma unroll
        for (int e = 0; e < 4; e++) o[nt][e] = 0.f;
    float m_a = -INFINITY, m_b = -INFINITY, l_a = 0.f, l_b = 0.f;

    const size_t headoff = ((size_t)(b * NH + h) * TT) * 64 * 2;  // bytes
    const char* kh_c = (const char*)kh_g + headoff;
    const char* kl_c = (const char*)kl_g + headoff;
    const char* vh_c = (const char*)vh_g + headoff;
    const char* vl_c = (const char*)vl_g + headoff;
    const int jmax = 2 * qt + 1;

    flash_issue(sbase, kh_c, kl_c, vh_c, vl_c, 0, tid);
    CP_COMMIT();
    flash_issue(sbase + KV_STAGE, kh_c, kl_c, vh_c, vl_c, 8192, tid);
    CP_COMMIT();

    for (int j = 0; j <= jmax; j++) {
        if (j < jmax) { CP_WAIT1(); } else { CP_WAIT0(); }
        __syncthreads();   // stage j%3 published; stage (j+2)%3 free to refill
        if (j + 2 <= jmax) {
            flash_issue(sbase + (uint32_t)((j + 2) % 3) * KV_STAGE,
                        kh_c, kl_c, vh_c, vl_c, (size_t)(j + 2) * 8192, tid);
            CP_COMMIT();
        }

        const bool active = (j * 64 <= qt * 128 + w * 16 + 15);
        if (active) {
            const uint32_t sb = sbase + (uint32_t)(j % 3) * KV_STAGE;
            const uint32_t aKh = sb, aKl = sb + KVT_B;
            const uint32_t aVh = sb + 2 * KVT_B, aVl = sb + 3 * KVT_B;

            float c[8][4];
            #pragma unroll
            for (int nt = 0; nt < 8; nt++)
                #pragma unroll
                for (int e = 0; e < 4; e++) c[nt][e] = 0.f;

            #pragma unroll
            for (int t = 0; t < 4; t++) {
                #pragma unroll
                for (int p = 0; p < 4; p++) {
                    uint32_t kb[4], kl2[4];
                    uint32_t bo = (uint32_t)((p * 16 + dn) * QPF + t * 16 + dkb) * 2;
                    LDSM_X4(kb, aKh + bo);
                    LDSM_X4(kl2, aKl + bo);
                    #pragma unroll
                    for (int sub = 0; sub < 2; sub++) {
                        const int nt = 2 * p + sub;
                        MMA16816(c[nt], qh[t], kb[sub * 2], kb[sub * 2 + 1]);
                        MMA16816(c[nt], qh[t], kl2[sub * 2], kl2[sub * 2 + 1]);
                        MMA16816(c[nt], ql[t], kb[sub * 2], kb[sub * 2 + 1]);
                    }
                }
            }

            if (j >= 2 * qt) {
                const int qa = qt * 128 + w * 16 + (l >> 2);
                const int kc0 = j * 64 + (l & 3) * 2;
                #pragma unroll
                for (int nt = 0; nt < 8; nt++) {
                    int col = kc0 + nt * 8;
                    if (col > qa)     c[nt][0] = -INFINITY;
                    if (col + 1 > qa) c[nt][1] = -INFINITY;
                    if (col > qa + 8)     c[nt][2] = -INFINITY;
                    if (col + 1 > qa + 8) c[nt][3] = -INFINITY;
                }
            }

            float ma = -INFINITY, mb = -INFINITY;
            #pragma unroll
            for (int nt = 0; nt < 8; nt++) {
                ma = fmaxf(ma, fmaxf(c[nt][0], c[nt][1]));
                mb = fmaxf(mb, fmaxf(c[nt][2], c[nt][3]));
            }
            ma = fmaxf(ma, __shfl_xor_sync(0xffffffffu, ma, 1));
            ma = fmaxf(ma, __shfl_xor_sync(0xffffffffu, ma, 2));
            mb = fmaxf(mb, __shfl_xor_sync(0xffffffffu, mb, 1));
            mb = fmaxf(mb, __shfl_xor_sync(0xffffffffu, mb, 2));
            float mna = fmaxf(m_a, ma), mnb = fmaxf(m_b, mb);
            float aa = __expf(m_a - mna), ab = __expf(m_b - mnb);
            float sa = 0.f, sb2 = 0.f;
            #pragma unroll
            for (int nt = 0; nt < 8; nt++) {
                c[nt][0] = __expf(c[nt][0] - mna);
                c[nt][1] = __expf(c[nt][1] - mna);
                c[nt][2] = __expf(c[nt][2] - mnb);
                c[nt][3] = __expf(c[nt][3] - mnb);
                sa += c[nt][0] + c[nt][1];
                sb2 += c[nt][2] + c[nt][3];
            }
            sa += __shfl_xor_sync(0xffffffffu, sa, 1);
            sa += __shfl_xor_sync(0xffffffffu, sa, 2);
            sb2 += __shfl_xor_sync(0xffffffffu, sb2, 1);
            sb2 += __shfl_xor_sync(0xffffffffu, sb2, 2);
            l_a = l_a * aa + sa;
            l_b = l_b * ab + sb2;
            m_a = mna; m_b = mnb;
            #pragma unroll
            for (int nt = 0; nt < 8; nt++) {
                o[nt][0] *= aa; o[nt][1] *= aa;
                o[nt][2] *= ab; o[nt][3] *= ab;
            }

            #pragma unroll
            for (int t = 0; t < 4; t++) {
                uint32_t pa[4];
                pa[0] = packh2(c[2 * t][0],     c[2 * t][1]);
                pa[1] = packh2(c[2 * t][2],     c[2 * t][3]);
                pa[2] = packh2(c[2 * t + 1][0], c[2 * t + 1][1]);
                pa[3] = packh2(c[2 * t + 1][2], c[2 * t + 1][3]);
                #pragma unroll
                for (int p = 0; p < 4; p++) {
                    uint32_t vb[4], vl2[4];
                    uint32_t vo = (uint32_t)((t * 16 + (mat & 1) * 8 + (l & 7)) * QPF
                                             + p * 16 + (mat >> 1) * 8) * 2;
                    LDSM_X4_T(vb, aVh + vo);
                    LDSM_X4_T(vl2, aVl + vo);
                    MMA16816H(o[2 * p],     pa, vb[0], vb[1]);
                    MMA16816H(o[2 * p + 1], pa, vb[2], vb[3]);
                    MMA16816H(o[2 * p],     pa, vl2[0], vl2[1]);
                    MMA16816H(o[2 * p + 1], pa, vl2[2], vl2[3]);
                }
            }
        }
    }

    // Epilogue: write split bf16 directly (feeds phase-3 GEMM)
    const float ia = 1.f / l_a, ib = 1.f / l_b;
    const int row = (b * TT + qt * 128 + w * 16 + (l >> 2));
    const int col = h * 64 + (l & 3) * 2;
    #pragma unroll
    for (int nt = 0; nt < 8; nt++) {
        float v0 = o[nt][0] * ia, v1 = o[nt][1] * ia;
        float v2 = o[nt][2] * ib, v3 = o[nt][3] * ib;
        __nv_bfloat16 h0 = __float2bfloat16(v0), h1 = __float2bfloat16(v1);
        __nv_bfloat16 h2 = __float2bfloat16(v2), h3 = __float2bfloat16(v3);
        size_t o0 = (size_t)row * DA + col + nt * 8;
        size_t o1 = (size_t)(row + 8) * DA + col + nt * 8;
        *(__nv_bfloat162*)(oh + o0) = __nv_bfloat162(h0, h1);
        *(__nv_bfloat162*)(ol + o0) = __nv_bfloat162(
            __float2bfloat16(v0 - __bfloat162float(h0)),
            __float2bfloat16(v1 - __bfloat162float(h1)));
        *(__nv_bfloat162*)(oh + o1) = __nv_bfloat162(h2, h3);
        *(__nv_bfloat162*)(ol + o1) = __nv_bfloat162(
            __float2bfloat16(v2 - __bfloat162float(h2)),
            __float2bfloat16(v3 - __bfloat162float(h3)));
    }
}

// ---------------------------------------------------------------------------
// Launch
// ---------------------------------------------------------------------------
extern "C" void kernel_launch(void* const* d_in, const int* in_sizes, int n_in,
                              void* d_out, int out_size)
{
    const float* x    = (const float*)d_in[0];
    const float* Wqkv = (const float*)d_in[2];
    const float* bqkv = (const float*)d_in[3];
    const float* Wout = (const float*)d_in[4];
    const float* bout = (const float*)d_in[5];
    float* out = (float*)d_out;

    __nv_bfloat16 *ah, *al, *bh, *bl, *qh, *ql, *kh, *kl;
    __half *vh, *vl;
    cudaGetSymbolAddress((void**)&ah, g_ah);
    cudaGetSymbolAddress((void**)&al, g_al);
    cudaGetSymbolAddress((void**)&bh, g_bh);
    cudaGetSymbolAddress((void**)&bl, g_bl);
    cudaGetSymbolAddress((void**)&qh, g_qh);
    cudaGetSymbolAddress((void**)&ql, g_ql);
    cudaGetSymbolAddress((void**)&kh, g_kh);
    cudaGetSymbolAddress((void**)&kl, g_kl);
    cudaGetSymbolAddress((void**)&vh, g_vh);
    cudaGetSymbolAddress((void**)&vl, g_vl);

    cudaFuncSetAttribute(gemm_mma,
                         cudaFuncAttributeMaxDynamicSharedMemorySize, (int)GEMM_DYN);
    cudaFuncSetAttribute(gemm_qkv,
                         cudaFuncAttributeMaxDynamicSharedMemorySize, (int)GEMM_DYN);
    cudaFuncSetAttribute(flash_mma,
                         cudaFuncAttributeMaxDynamicSharedMemorySize, (int)FL_DYN);

    // Phase 1: QKV projection with fused split epilogue
    split_f4<<<(MM * CCH / 4 + 255) / 256, 256>>>(x, ah, al, MM * CCH / 4);
    transpose_split<<<dim3(3 * DA / 32, CCH / 32), dim3(32, 8)>>>(Wqkv, bh, bl, CCH, 3 * DA);
    gemm_qkv<<<dim3(3 * DA / 128, MM / 128), 256, GEMM_DYN>>>(
        ah, al, bh, bl, bqkv, qh, ql, kh, kl, vh, vl);

    // Phase 2: tensor-core flash (writes split attn to ah/al)
    flash_mma<<<dim3(TT / 128, NH, BV), 256, FL_DYN>>>(
        qh, ql, kh, kl, vh, vl, ah, al);

    // Phase 3: out = attn @ Wout + b
    transpose_split<<<dim3(CCH / 32, DA / 32), dim3(32, 8)>>>(Wout, bh, bl, DA, CCH);
    gemm_mma<<<dim3(CCH / 128, MM / 128), 256, GEMM_DYN>>>(
        ah, al, bh, bl, bout, out, MM, CCH, DA);
}

// round 10
// speedup vs baseline: 4.2475x; 1.0169x over previous
#include <cuda_runtime.h>
#include <cuda_bf16.h>
#include <cuda_fp16.h>
#include <math.h>
#include <stdint.h>

// Problem constants
#define BV 4
#define TT 2048
#define CCH 1024
#define DA 1024
#define NH 16
#define HDM 64
#define MM (BV * TT)   // 8192 rows

// ---------------------------------------------------------------------------
// Device scratch (allocations forbidden; __device__ globals are sanctioned)
// ---------------------------------------------------------------------------
__device__ __nv_bfloat16 g_ah[(size_t)MM * CCH];          // A split hi (x / attn)
__device__ __nv_bfloat16 g_al[(size_t)MM * CCH];          // A split lo
__device__ __nv_bfloat16 g_bh[(size_t)CCH * 3 * DA];      // W^T split hi
__device__ __nv_bfloat16 g_bl[(size_t)CCH * 3 * DA];      // W^T split lo
__device__ __nv_bfloat16 g_qh[(size_t)MM * DA];           // Q split (scaled)
__device__ __nv_bfloat16 g_ql[(size_t)MM * DA];
__device__ __nv_bfloat16 g_kh[(size_t)MM * DA];           // head-major K split
__device__ __nv_bfloat16 g_kl[(size_t)MM * DA];
__device__ __half        g_vh[(size_t)MM * DA];           // head-major V split
__device__ __half        g_vl[(size_t)MM * DA];

__device__ __forceinline__ uint32_t smem_u32(const void* p) {
    uint32_t a;
    asm("{ .reg .u64 t; cvta.to.shared.u64 t, %1; cvt.u32.u64 %0, t; }"
        : "=r"(a) : "l"(p));
    return a;
}

#define LDSM_X4(r, addr) \
    asm volatile("ldmatrix.sync.aligned.m8n8.x4.shared.b16 {%0,%1,%2,%3}, [%4];" \
        : "=r"((r)[0]), "=r"((r)[1]), "=r"((r)[2]), "=r"((r)[3]) : "r"(addr))

#define LDSM_X4_T(r, addr) \
    asm volatile("ldmatrix.sync.aligned.m8n8.x4.trans.shared.b16 {%0,%1,%2,%3}, [%4];" \
        : "=r"((r)[0]), "=r"((r)[1]), "=r"((r)[2]), "=r"((r)[3]) : "r"(addr))

#define MMA16816(c, a, b0, b1) \
    asm volatile("mma.sync.aligned.m16n8k16.row.col.f32.bf16.bf16.f32 " \
        "{%0,%1,%2,%3}, {%4,%5,%6,%7}, {%8,%9}, {%0,%1,%2,%3};" \
        : "+f"((c)[0]), "+f"((c)[1]), "+f"((c)[2]), "+f"((c)[3]) \
        : "r"((a)[0]), "r"((a)[1]), "r"((a)[2]), "r"((a)[3]), "r"(b0), "r"(b1))

#define MMA16816H(c, a, b0, b1) \
    asm volatile("mma.sync.aligned.m16n8k16.row.col.f32.f16.f16.f32 " \
        "{%0,%1,%2,%3}, {%4,%5,%6,%7}, {%8,%9}, {%0,%1,%2,%3};" \
        : "+f"((c)[0]), "+f"((c)[1]), "+f"((c)[2]), "+f"((c)[3]) \
        : "r"((a)[0]), "r"((a)[1]), "r"((a)[2]), "r"((a)[3]), "r"(b0), "r"(b1))

#define CP_A16(dst, src) \
    asm volatile("cp.async.cg.shared.global [%0], [%1], 16;" \
                 :: "r"(dst), "l"(src) : "memory")
#define CP_COMMIT() asm volatile("cp.async.commit_group;" ::: "memory")
#define CP_WAIT2()  asm volatile("cp.async.wait_group 2;" ::: "memory")
#define CP_WAIT1()  asm volatile("cp.async.wait_group 1;" ::: "memory")
#define CP_WAIT0()  asm volatile("cp.async.wait_group 0;" ::: "memory")

__device__ __forceinline__ uint32_t packh2(float a, float b) {
    __half2 h = __floats2half2_rn(a, b);
    return *(uint32_t*)&h;
}

// ---------------------------------------------------------------------------
// split_f4: fp32 -> (bf16 hi, bf16 lo), elementwise  (input x only)
// ---------------------------------------------------------------------------
__global__ void split_f4(const float* __restrict__ src,
                         __nv_bfloat16* __restrict__ hi,
                         __nv_bfloat16* __restrict__ lo, int n4)
{
    int i = blockIdx.x * blockDim.x + threadIdx.x;
    if (i >= n4) return;
    float4 v = ((const float4*)src)[i];
    __nv_bfloat16 h0 = __float2bfloat16(v.x), h1 = __float2bfloat16(v.y);
    __nv_bfloat16 h2 = __float2bfloat16(v.z), h3 = __float2bfloat16(v.w);
    __nv_bfloat16 l0 = __float2bfloat16(v.x - __bfloat162float(h0));
    __nv_bfloat16 l1 = __float2bfloat16(v.y - __bfloat162float(h1));
    __nv_bfloat16 l2 = __float2bfloat16(v.z - __bfloat162float(h2));
    __nv_bfloat16 l3 = __float2bfloat16(v.w - __bfloat162float(h3));
    ((__nv_bfloat162*)hi)[2 * i]     = __nv_bfloat162(h0, h1);
    ((__nv_bfloat162*)hi)[2 * i + 1] = __nv_bfloat162(h2, h3);
    ((__nv_bfloat162*)lo)[2 * i]     = __nv_bfloat162(l0, l1);
    ((__nv_bfloat162*)lo)[2 * i + 1] = __nv_bfloat162(l2, l3);
}

// W[K][N] -> Th/Tl[N][K] with split. 32x32 smem-tiled transpose.
__global__ void transpose_split(const float* __restrict__ W,
                                __nv_bfloat16* __restrict__ Th,
                                __nv_bfloat16* __restrict__ Tl, int K, int N)
{
    __shared__ float tile[32][33];
    int tx = threadIdx.x, ty = threadIdx.y;
    int n0 = blockIdx.x * 32, k0 = blockIdx.y * 32;
    #pragma unroll
    for (int j = 0; j < 32; j += 8)
        tile[ty + j][tx] = W[(size_t)(k0 + ty + j) * N + n0 + tx];
    __syncthreads();
    #pragma unroll
    for (int j = 0; j < 32; j += 8) {
        float v = tile[tx][ty + j];
        __nv_bfloat16 h = __float2bfloat16(v);
        __nv_bfloat16 l = __float2bfloat16(v - __bfloat162float(h));
        size_t o = (size_t)(n0 + ty + j) * K + k0 + tx;
        Th[o] = h;
        Tl[o] = l;
    }
}

// ---------------------------------------------------------------------------
// Shared GEMM mainloop (CTA 128x128, 8 warps 2x4, KC=64, 3-stage, 1 barrier)
// ---------------------------------------------------------------------------
#define KC 64
#define PP 72                               // smem pitch in bf16 (144 B rows)
#define MAT_B (128 * PP * 2)                // 18432 B
#define STAGE_B (4 * MAT_B)                 // 73728 B
#define GEMM_DYN (3 * STAGE_B)              // 221184 B

static __device__ __forceinline__ void gemm_issue(
    uint32_t stage, const char* a0, const char* a1,
    const char* a2, const char* a3, int Kb, int k0b, int tid)
{
    const char* srcs[4] = {a0, a1, a2, a3};
    #pragma unroll
    for (int i = 0; i < 16; i++) {
        int idx = i * 256 + tid;
        int arr = idx >> 10, rem = idx & 1023;
        int row = rem >> 3, c = rem & 7;
        CP_A16(stage + arr * MAT_B + row * (PP * 2) + c * 16,
               srcs[arr] + (size_t)row * Kb + k0b + c * 16);
    }
}

// Mainloop: single barrier per chunk (refill target = stage last read one
// iteration ago; the entry barrier already orders all its readers).
#define GEMM_MAINLOOP(Ah, Al, Bh, Bl, K)                                      \
    const uint32_t sbase = smem_u32(dyn);                                     \
    const int NCH = (K) / KC;                                                 \
    const int Kb = (K) * 2;                                                   \
    const char* a0 = (const char*)((Ah) + (size_t)arow0 * (K));               \
    const char* a1 = (const char*)((Al) + (size_t)arow0 * (K));               \
    const char* a2 = (const char*)((Bh) + (size_t)bcol0 * (K));               \
    const char* a3 = (const char*)((Bl) + (size_t)bcol0 * (K));               \
    gemm_issue(sbase, a0, a1, a2, a3, Kb, 0, tid); CP_COMMIT();               \
    gemm_issue(sbase + STAGE_B, a0, a1, a2, a3, Kb, KC * 2, tid); CP_COMMIT();\
    for (int c = 0; c < NCH; c++) {                                           \
        if (c < NCH - 1) { CP_WAIT1(); } else { CP_WAIT0(); }                 \
        __syncthreads();                                                      \
        if (c + 2 < NCH) {                                                    \
            gemm_issue(sbase + (uint32_t)((c + 2) % 3) * STAGE_B,             \
                       a0, a1, a2, a3, Kb, (c + 2) * KC * 2, tid);            \
            CP_COMMIT();                                                      \
        }                                                                     \
        const uint32_t stb = sbase + (uint32_t)(c % 3) * STAGE_B;             \
        const uint32_t aAh = stb + 0 * MAT_B;                                 \
        const uint32_t aAl = stb + 1 * MAT_B;                                 \
        const uint32_t aBh = stb + 2 * MAT_B;                                 \
        const uint32_t aBl = stb + 3 * MAT_B;                                 \
        _Pragma("unroll")                                                     \
        for (int ks = 0; ks < KC / 16; ks++) {                                \
            const int k0 = ks * 16;                                           \
            uint32_t ahf[4][4], alf[4][4];                                    \
            uint32_t bhf[2][4], blf[2][4];                                    \
            _Pragma("unroll")                                                 \
            for (int mt = 0; mt < 4; mt++) {                                  \
                uint32_t ao = (uint32_t)((warp_m * 64 + mt * 16 + dr) * PP    \
                                         + k0 + dka) * 2;                     \
                LDSM_X4(ahf[mt], aAh + ao);                                   \
                LDSM_X4(alf[mt], aAl + ao);                                   \
            }                                                                 \
            _Pragma("unroll")                                                 \
            for (int pr = 0; pr < 2; pr++) {                                  \
                uint32_t bo = (uint32_t)((warp_n * 32 + pr * 16 + dn) * PP    \
                                         + k0 + dkb) * 2;                     \
                LDSM_X4(bhf[pr], aBh + bo);                                   \
                LDSM_X4(blf[pr], aBl + bo);                                   \
            }                                                                 \
            _Pragma("unroll")                                                 \
            for (int mt = 0; mt < 4; mt++)                                    \
                _Pragma("unroll")                                             \
                for (int nt = 0; nt < 4; nt++) {                              \
                    const int pr = nt >> 1, sb2 = (nt & 1) * 2;               \
                    MMA16816(acc[mt][nt], ahf[mt], bhf[pr][sb2], bhf[pr][sb2 + 1]); \
                    MMA16816(acc[mt][nt], ahf[mt], blf[pr][sb2], blf[pr][sb2 + 1]); \
                    MMA16816(acc[mt][nt], alf[mt], bhf[pr][sb2], bhf[pr][sb2 + 1]); \
                }                                                             \
        }                                                                     \
    }

// ---------------------------------------------------------------------------
// gemm_mma: generic fp32 output + bias (output projection)
// ---------------------------------------------------------------------------
__global__ __launch_bounds__(256, 1) void gemm_mma(
    const __nv_bfloat16* __restrict__ Ah, const __nv_bfloat16* __restrict__ Al,
    const __nv_bfloat16* __restrict__ Bh, const __nv_bfloat16* __restrict__ Bl,
    const float* __restrict__ bias, float* __restrict__ C,
    int M, int N, int K)
{
    extern __shared__ char dyn[];
    const int tid = threadIdx.x;
    const int wid = tid >> 5, l = tid & 31;
    const int warp_m = wid & 1, warp_n = wid >> 1;
    const int bc = blockIdx.x, br = blockIdx.y;
    const int arow0 = br * 128, bcol0 = bc * 128;

    const int mat = l >> 3;
    const int dr  = (mat & 1) * 8 + (l & 7);
    const int dka = (mat >> 1) * 8;
    const int dn  = (mat >> 1) * 8 + (l & 7);
    const int dkb = (mat & 1) * 8;

    float acc[4][4][4];
    #pragma unroll
    for (int i = 0; i < 4; i++)
        #pragma unroll
        for (int j = 0; j < 4; j++)
            #pragma unroll
            for (int q = 0; q < 4; q++) acc[i][j][q] = 0.f;

    GEMM_MAINLOOP(Ah, Al, Bh, Bl, K)

    const int rbase = arow0 + warp_m * 64 + (l >> 2);
    const int cbase = bcol0 + warp_n * 32 + (l & 3) * 2;
    #pragma unroll
    for (int mt = 0; mt < 4; mt++)
        #pragma unroll
        for (int nt = 0; nt < 4; nt++) {
            const int row = rbase + mt * 16;
            const int col = cbase + nt * 8;
            float2 v0, v1;
            v0.x = acc[mt][nt][0] + bias[col];
            v0.y = acc[mt][nt][1] + bias[col + 1];
            v1.x = acc[mt][nt][2] + bias[col];
            v1.y = acc[mt][nt][3] + bias[col + 1];
            *(float2*)(C + (size_t)row * N + col) = v0;
            *(float2*)(C + (size_t)(row + 8) * N + col) = v1;
        }
}

// ---------------------------------------------------------------------------
// gemm_qkv: QKV projection with fused split epilogue (Q/K/V consumer formats)
// ---------------------------------------------------------------------------
__global__ __launch_bounds__(256, 1) void gemm_qkv(
    const __nv_bfloat16* __restrict__ Ah, const __nv_bfloat16* __restrict__ Al,
    const __nv_bfloat16* __restrict__ Bh, const __nv_bfloat16* __restrict__ Bl,
    const float* __restrict__ bias,
    __nv_bfloat16* __restrict__ qh, __nv_bfloat16* __restrict__ ql,
    __nv_bfloat16* __restrict__ kh, __nv_bfloat16* __restrict__ kl,
    __half* __restrict__ vh, __half* __restrict__ vl)
{
    extern __shared__ char dyn[];
    const int tid = threadIdx.x;
    const int wid = tid >> 5, l = tid & 31;
    const int warp_m = wid & 1, warp_n = wid >> 1;
    const int bc = blockIdx.x, br = blockIdx.y;
    const int arow0 = br * 128, bcol0 = bc * 128;
    const int K = CCH;

    const int mat = l >> 3;
    const int dr  = (mat & 1) * 8 + (l & 7);
    const int dka = (mat >> 1) * 8;
    const int dn  = (mat >> 1) * 8 + (l & 7);
    const int dkb = (mat & 1) * 8;

    float acc[4][4][4];
    #pragma unroll
    for (int i = 0; i < 4; i++)
        #pragma unroll
        for (int j = 0; j < 4; j++)
            #pragma unroll
            for (int q = 0; q < 4; q++) acc[i][j][q] = 0.f;

    GEMM_MAINLOOP(Ah, Al, Bh, Bl, K)

    const int rbase = arow0 + warp_m * 64 + (l >> 2);
    const int cbase = bcol0 + warp_n * 32 + (l & 3) * 2;
    #pragma unroll
    for (int mt = 0; mt < 4; mt++)
        #pragma unroll
        for (int nt = 0; nt < 4; nt++) {
            #pragma unroll
            for (int half2i = 0; half2i < 2; half2i++) {
                const int row = rbase + mt * 16 + half2i * 8;
                const int col = cbase + nt * 8;
                float v0 = acc[mt][nt][half2i * 2 + 0] + bias[col];
                float v1 = acc[mt][nt][half2i * 2 + 1] + bias[col + 1];
                if (bc < 8) {
                    v0 *= 0.125f; v1 *= 0.125f;
                    __nv_bfloat16 h0 = __float2bfloat16(v0);
                    __nv_bfloat16 h1 = __float2bfloat16(v1);
                    size_t o = (size_t)row * DA + col;
                    *(__nv_bfloat162*)(qh + o) = __nv_bfloat162(h0, h1);
                    *(__nv_bfloat162*)(ql + o) = __nv_bfloat162(
                        __float2bfloat16(v0 - __bfloat162float(h0)),
                        __float2bfloat16(v1 - __bfloat162float(h1)));
                } else {
                    const int cg = col - (bc < 16 ? 1024 : 2048);
                    const int head = cg >> 6, d = cg & 63;
                    const int t = row & (TT - 1), bb = row >> 11;
                    size_t o = ((size_t)(bb * NH + head) * TT + t) * 64 + d;
                    if (bc < 16) {
                        __nv_bfloat16 h0 = __float2bfloat16(v0);
                        __nv_bfloat16 h1 = __float2bfloat16(v1);
                        *(__nv_bfloat162*)(kh + o) = __nv_bfloat162(h0, h1);
                        *(__nv_bfloat162*)(kl + o) = __nv_bfloat162(
                            __float2bfloat16(v0 - __bfloat162float(h0)),
                            __float2bfloat16(v1 - __bfloat162float(h1)));
                    } else {
                        __half h0 = __float2half_rn(v0);
                        __half h1 = __float2half_rn(v1);
                        *(__half2*)(vh + o) = __half2(h0, h1);
                        *(__half2*)(vl + o) = __half2(
                            __float2half_rn(v0 - __half2float(h0)),
                            __float2half_rn(v1 - __half2float(h1)));
                    }
                }
            }
        }
}

// ---------------------------------------------------------------------------
// Tensor-core flash attention v5 (causal):
//  - 2 CTAs/SM (regs capped at 128 via launch_bounds; Q frags live in smem)
//  - dedicated Q smem region + 2-stage cp.async KV pipeline
//  - LPT scheduling (largest q-tiles launch first)
// ---------------------------------------------------------------------------
#define QPF 72                              // smem pitch in b16 elems
#define KVT_B (64 * QPF * 2)                // 9216 B per array tile
#define KV_STAGE (4 * KVT_B)                // 36864 B
#define Q_OFF (2 * KV_STAGE)                // 73728
#define QARR_B (128 * QPF * 2)              // 18432 B per Q array
#define FL_DYN (2 * KV_STAGE + 2 * QARR_B)  // 110592 B  (x2 CTAs = 216 KB/SM)

static __device__ __forceinline__ void flash_issue(
    uint32_t stage, const char* kh, const char* kl,
    const char* vh, const char* vl, size_t tile_off, int tid)
{
    const char* srcs[4] = {kh + tile_off, kl + tile_off, vh + tile_off, vl + tile_off};
    #pragma unroll
    for (int i = 0; i < 8; i++) {
        int idx = i * 256 + tid;
        int arr = idx >> 9, rem = idx & 511;
        int r = rem >> 3, c = rem & 7;
        CP_A16(stage + arr * KVT_B + r * (QPF * 2) + c * 16,
               srcs[arr] + r * 128 + c * 16);
    }
}

__global__ __launch_bounds__(256, 2) void flash_mma(
    const __nv_bfloat16* __restrict__ qh_g, const __nv_bfloat16* __restrict__ ql_g,
    const __nv_bfloat16* __restrict__ kh_g, const __nv_bfloat16* __restrict__ kl_g,
    const __half* __restrict__ vh_g, const __half* __restrict__ vl_g,
    __nv_bfloat16* __restrict__ oh, __nv_bfloat16* __restrict__ ol)
{
    extern __shared__ char fsm[];
    const int tid = threadIdx.x;
    const int w = tid >> 5, l = tid & 31;
    const int qt = (int)gridDim.x - 1 - (int)blockIdx.x;   // LPT: big tiles first
    const int h = blockIdx.y, b = blockIdx.z;

    const uint32_t sbase = smem_u32(fsm);
    const size_t headoff = ((size_t)(b * NH + h) * TT) * 64 * 2;  // bytes
    const char* kh_c = (const char*)kh_g + headoff;
    const char* kl_c = (const char*)kl_g + headoff;
    const char* vh_c = (const char*)vh_g + headoff;
    const char* vl_c = (const char*)vl_g + headoff;
    const int jmax = 2 * qt + 1;

    // Prologue: Q region (group 0), KV stage 0 (group 1), KV stage 1 (group 2)
    {
        const char* q0 = (const char*)qh_g
            + ((size_t)(b * TT + qt * 128) * DA + h * 64) * 2;
        const char* q1 = (const char*)ql_g
            + ((size_t)(b * TT + qt * 128) * DA + h * 64) * 2;
        const char* srcs[2] = {q0, q1};
        #pragma unroll
        for (int i = 0; i < 8; i++) {
            int idx = i * 256 + tid;
            int arr = idx >> 10, rem = idx & 1023;
            int r = rem >> 3, c = rem & 7;
            CP_A16(sbase + Q_OFF + arr * QARR_B + r * (QPF * 2) + c * 16,
                   srcs[arr] + (size_t)r * (DA * 2) + c * 16);
        }
    }
    CP_COMMIT();
    flash_issue(sbase, kh_c, kl_c, vh_c, vl_c, 0, tid);
    CP_COMMIT();
    flash_issue(sbase + KV_STAGE, kh_c, kl_c, vh_c, vl_c, 8192, tid);
    CP_COMMIT();
    CP_WAIT2();        // Q region complete
    __syncthreads();

    const int mat = l >> 3;
    const int dr  = (mat & 1) * 8 + (l & 7);
    const int dka = (mat >> 1) * 8;
    const int dn  = (mat >> 1) * 8 + (l & 7);
    const int dkb = (mat & 1) * 8;
    const uint32_t aQh = sbase + Q_OFF, aQl = aQh + QARR_B;

    float o[8][4];
    #pragma unroll
    for (int nt = 0; nt < 8; nt++)
        #pragma unroll
        for (int e = 0; e < 4; e++) o[nt][e] = 0.f;
    float m_a = -INFINITY, m_b = -INFINITY, l_a = 0.f, l_b = 0.f;

    for (int j = 0; j <= jmax; j++) {
        if (j < jmax) { CP_WAIT1(); } else { CP_WAIT0(); }
        __syncthreads();   // stage j&1 published to all warps

        const bool active = (j * 64 <= qt * 128 + w * 16 + 15);
        if (active) {
            const uint32_t sb = sbase + (uint32_t)(j & 1) * KV_STAGE;
            const uint32_t aKh = sb, aKl = sb + KVT_B;
            const uint32_t aVh = sb + 2 * KVT_B, aVl = sb + 3 * KVT_B;

            float c[8][4];
            #pragma unroll
            for (int nt = 0; nt < 8; nt++)
                #pragma unroll
                for (int e = 0; e < 4; e++) c[nt][e] = 0.f;

            #pragma unroll
            for (int t = 0; t < 4; t++) {
                uint32_t qhf[4], qlf[4];
                uint32_t qo = (uint32_t)((w * 16 + dr) * QPF + t * 16 + dka) * 2;
                LDSM_X4(qhf, aQh + qo);
                LDSM_X4(qlf, aQl + qo);
                #pragma unroll
                for (int p = 0; p < 4; p++) {
                    uint32_t kb[4], kl2[4];
                    uint32_t bo = (uint32_t)((p * 16 + dn) * QPF + t * 16 + dkb) * 2;
                    LDSM_X4(kb, aKh + bo);
                    LDSM_X4(kl2, aKl + bo);
                    #pragma unroll
                    for (int sub = 0; sub < 2; sub++) {
                        const int nt = 2 * p + sub;
                        MMA16816(c[nt], qhf, kb[sub * 2], kb[sub * 2 + 1]);
                        MMA16816(c[nt], qhf, kl2[sub * 2], kl2[sub * 2 + 1]);
                        MMA16816(c[nt], qlf, kb[sub * 2], kb[sub * 2 + 1]);
                    }
                }
            }

            if (j >= 2 * qt) {
                const int qa = qt * 128 + w * 16 + (l >> 2);
                const int kc0 = j * 64 + (l & 3) * 2;
                #pragma unroll
                for (int nt = 0; nt < 8; nt++) {
                    int col = kc0 + nt * 8;
                    if (col > qa)     c[nt][0] = -INFINITY;
                    if (col + 1 > qa) c[nt][1] = -INFINITY;
                    if (col > qa + 8)     c[nt][2] = -INFINITY;
                    if (col + 1 > qa + 8) c[nt][3] = -INFINITY;
                }
            }

            float ma = -INFINITY, mb = -INFINITY;
            #pragma unroll
            for (int nt = 0; nt < 8; nt++) {
                ma = fmaxf(ma, fmaxf(c[nt][0], c[nt][1]));
                mb = fmaxf(mb, fmaxf(c[nt][2], c[nt][3]));
            }
            ma = fmaxf(ma, __shfl_xor_sync(0xffffffffu, ma, 1));
            ma = fmaxf(ma, __shfl_xor_sync(0xffffffffu, ma, 2));
            mb = fmaxf(mb, __shfl_xor_sync(0xffffffffu, mb, 1));
            mb = fmaxf(mb, __shfl_xor_sync(0xffffffffu, mb, 2));
            float mna = fmaxf(m_a, ma), mnb = fmaxf(m_b, mb);
            float aa = __expf(m_a - mna), ab = __expf(m_b - mnb);
            float sa = 0.f, sb2 = 0.f;
            #pragma unroll
            for (int nt = 0; nt < 8; nt++) {
                c[nt][0] = __expf(c[nt][0] - mna);
                c[nt][1] = __expf(c[nt][1] - mna);
                c[nt][2] = __expf(c[nt][2] - mnb);
                c[nt][3] = __expf(c[nt][3] - mnb);
                sa += c[nt][0] + c[nt][1];
                sb2 += c[nt][2] + c[nt][3];
            }
            sa += __shfl_xor_sync(0xffffffffu, sa, 1);
            sa += __shfl_xor_sync(0xffffffffu, sa, 2);
            sb2 += __shfl_xor_sync(0xffffffffu, sb2, 1);
            sb2 += __shfl_xor_sync(0xffffffffu, sb2, 2);
            l_a = l_a * aa + sa;
            l_b = l_b * ab + sb2;
            m_a = mna; m_b = mnb;
            #pragma unroll
            for (int nt = 0; nt < 8; nt++) {
                o[nt][0] *= aa; o[nt][1] *= aa;
                o[nt][2] *= ab; o[nt][3] *= ab;
            }

            #pragma unroll
            for (int t = 0; t < 4; t++) {
                uint32_t pa[4];
                pa[0] = packh2(c[2 * t][0],     c[2 * t][1]);
                pa[1] = packh2(c[2 * t][2],     c[2 * t][3]);
                pa[2] = packh2(c[2 * t + 1][0], c[2 * t + 1][1]);
                pa[3] = packh2(c[2 * t + 1][2], c[2 * t + 1][3]);
                #pragma unroll
                for (int p = 0; p < 4; p++) {
                    uint32_t vb[4], vl2[4];
                    uint32_t vo = (uint32_t)((t * 16 + (mat & 1) * 8 + (l & 7)) * QPF
                                             + p * 16 + (mat >> 1) * 8) * 2;
                    LDSM_X4_T(vb, aVh + vo);
                    LDSM_X4_T(vl2, aVl + vo);
                    MMA16816H(o[2 * p],     pa, vb[0], vb[1]);
                    MMA16816H(o[2 * p + 1], pa, vb[2], vb[3]);
                    MMA16816H(o[2 * p],     pa, vl2[0], vl2[1]);
                    MMA16816H(o[2 * p + 1], pa, vl2[2], vl2[3]);
                }
            }
        }
        __syncthreads();   // all warps done reading stage j&1
        if (j + 2 <= jmax) {
            flash_issue(sbase + (uint32_t)(j & 1) * KV_STAGE,
                        kh_c, kl_c, vh_c, vl_c, (size_t)(j + 2) * 8192, tid);
            CP_COMMIT();
        }
    }

    // Epilogue: write split bf16 directly (feeds phase-3 GEMM)
    const float ia = 1.f / l_a, ib = 1.f / l_b;
    const int row = (b * TT + qt * 128 + w * 16 + (l >> 2));
    const int col = h * 64 + (l & 3) * 2;
    #pragma unroll
    for (int nt = 0; nt < 8; nt++) {
        float v0 = o[nt][0] * ia, v1 = o[nt][1] * ia;
        float v2 = o[nt][2] * ib, v3 = o[nt][3] * ib;
        __nv_bfloat16 h0 = __float2bfloat16(v0), h1 = __float2bfloat16(v1);
        __nv_bfloat16 h2 = __float2bfloat16(v2), h3 = __float2bfloat16(v3);
        size_t o0 = (size_t)row * DA + col + nt * 8;
        size_t o1 = (size_t)(row + 8) * DA + col + nt * 8;
        *(__nv_bfloat162*)(oh + o0) = __nv_bfloat162(h0, h1);
        *(__nv_bfloat162*)(ol + o0) = __nv_bfloat162(
            __float2bfloat16(v0 - __bfloat162float(h0)),
            __float2bfloat16(v1 - __bfloat162float(h1)));
        *(__nv_bfloat162*)(oh + o1) = __nv_bfloat162(h2, h3);
        *(__nv_bfloat162*)(ol + o1) = __nv_bfloat162(
            __float2bfloat16(v2 - __bfloat162float(h2)),
            __float2bfloat16(v3 - __bfloat162float(h3)));
    }
}

// ---------------------------------------------------------------------------
// Launch
// ---------------------------------------------------------------------------
extern "C" void kernel_launch(void* const* d_in, const int* in_sizes, int n_in,
                              void* d_out, int out_size)
{
    const float* x    = (const float*)d_in[0];
    const float* Wqkv = (const float*)d_in[2];
    const float* bqkv = (const float*)d_in[3];
    const float* Wout = (const float*)d_in[4];
    const float* bout = (const float*)d_in[5];
    float* out = (float*)d_out;

    __nv_bfloat16 *ah, *al, *bh, *bl, *qh, *ql, *kh, *kl;
    __half *vh, *vl;
    cudaGetSymbolAddress((void**)&ah, g_ah);
    cudaGetSymbolAddress((void**)&al, g_al);
    cudaGetSymbolAddress((void**)&bh, g_bh);
    cudaGetSymbolAddress((void**)&bl, g_bl);
    cudaGetSymbolAddress((void**)&qh, g_qh);
    cudaGetSymbolAddress((void**)&ql, g_ql);
    cudaGetSymbolAddress((void**)&kh, g_kh);
    cudaGetSymbolAddress((void**)&kl, g_kl);
    cudaGetSymbolAddress((void**)&vh, g_vh);
    cudaGetSymbolAddress((void**)&vl, g_vl);

    cudaFuncSetAttribute(gemm_mma,
                         cudaFuncAttributeMaxDynamicSharedMemorySize, (int)GEMM_DYN);
    cudaFuncSetAttribute(gemm_qkv,
                         cudaFuncAttributeMaxDynamicSharedMemorySize, (int)GEMM_DYN);
    cudaFuncSetAttribute(flash_mma,
                         cudaFuncAttributeMaxDynamicSharedMemorySize, (int)FL_DYN);

    // Phase 1: QKV projection with fused split epilogue
    split_f4<<<(MM * CCH / 4 + 255) / 256, 256>>>(x, ah, al, MM * CCH / 4);
    transpose_split<<<dim3(3 * DA / 32, CCH / 32), dim3(32, 8)>>>(Wqkv, bh, bl, CCH, 3 * DA);
    gemm_qkv<<<dim3(3 * DA / 128, MM / 128), 256, GEMM_DYN>>>(
        ah, al, bh, bl, bqkv, qh, ql, kh, kl, vh, vl);

    // Phase 2: tensor-core flash (writes split attn to ah/al)
    flash_mma<<<dim3(TT / 128, NH, BV), 256, FL_DYN>>>(
        qh, ql, kh, kl, vh, vl, ah, al);

    // Phase 3: out = attn @ Wout + b
    transpose_split<<<dim3(CCH / 32, DA / 32), dim3(32, 8)>>>(Wout, bh, bl, DA, CCH);
    gemm_mma<<<dim3(CCH / 128, MM / 128), 256, GEMM_DYN>>>(
        ah, al, bh, bl, bout, out, MM, CCH, DA);
}

// round 11
// speedup vs baseline: 4.4718x; 1.0528x over previous
#include <cuda_runtime.h>
#include <cuda_bf16.h>
#include <cuda_fp16.h>
#include <math.h>
#include <stdint.h>

// Problem constants
#define BV 4
#define TT 2048
#define CCH 1024
#define DA 1024
#define NH 16
#define HDM 64
#define MM (BV * TT)   // 8192 rows

// ---------------------------------------------------------------------------
// Device scratch (allocations forbidden; __device__ globals are sanctioned)
// ---------------------------------------------------------------------------
__device__ __nv_bfloat16 g_ah[(size_t)MM * CCH];          // A split hi (x / attn)
__device__ __nv_bfloat16 g_al[(size_t)MM * CCH];          // A split lo
__device__ __nv_bfloat16 g_bh[(size_t)CCH * 3 * DA];      // W^T split hi
__device__ __nv_bfloat16 g_bl[(size_t)CCH * 3 * DA];      // W^T split lo
__device__ __nv_bfloat16 g_qh[(size_t)MM * DA];           // Q split (scaled)
__device__ __nv_bfloat16 g_ql[(size_t)MM * DA];
__device__ __nv_bfloat16 g_kh[(size_t)MM * DA];           // head-major K split
__device__ __nv_bfloat16 g_kl[(size_t)MM * DA];
__device__ __half        g_vh[(size_t)MM * DA];           // head-major V (fp16)

__device__ __forceinline__ uint32_t smem_u32(const void* p) {
    uint32_t a;
    asm("{ .reg .u64 t; cvta.to.shared.u64 t, %1; cvt.u32.u64 %0, t; }"
        : "=r"(a) : "l"(p));
    return a;
}

#define LDSM_X4(r, addr) \
    asm volatile("ldmatrix.sync.aligned.m8n8.x4.shared.b16 {%0,%1,%2,%3}, [%4];" \
        : "=r"((r)[0]), "=r"((r)[1]), "=r"((r)[2]), "=r"((r)[3]) : "r"(addr))

#define LDSM_X4_T(r, addr) \
    asm volatile("ldmatrix.sync.aligned.m8n8.x4.trans.shared.b16 {%0,%1,%2,%3}, [%4];" \
        : "=r"((r)[0]), "=r"((r)[1]), "=r"((r)[2]), "=r"((r)[3]) : "r"(addr))

#define MMA16816(c, a, b0, b1) \
    asm volatile("mma.sync.aligned.m16n8k16.row.col.f32.bf16.bf16.f32 " \
        "{%0,%1,%2,%3}, {%4,%5,%6,%7}, {%8,%9}, {%0,%1,%2,%3};" \
        : "+f"((c)[0]), "+f"((c)[1]), "+f"((c)[2]), "+f"((c)[3]) \
        : "r"((a)[0]), "r"((a)[1]), "r"((a)[2]), "r"((a)[3]), "r"(b0), "r"(b1))

#define MMA16816H(c, a, b0, b1) \
    asm volatile("mma.sync.aligned.m16n8k16.row.col.f32.f16.f16.f32 " \
        "{%0,%1,%2,%3}, {%4,%5,%6,%7}, {%8,%9}, {%0,%1,%2,%3};" \
        : "+f"((c)[0]), "+f"((c)[1]), "+f"((c)[2]), "+f"((c)[3]) \
        : "r"((a)[0]), "r"((a)[1]), "r"((a)[2]), "r"((a)[3]), "r"(b0), "r"(b1))

#define CP_A16(dst, src) \
    asm volatile("cp.async.cg.shared.global [%0], [%1], 16;" \
                 :: "r"(dst), "l"(src) : "memory")
#define CP_COMMIT() asm volatile("cp.async.commit_group;" ::: "memory")
#define CP_WAIT2()  asm volatile("cp.async.wait_group 2;" ::: "memory")
#define CP_WAIT1()  asm volatile("cp.async.wait_group 1;" ::: "memory")
#define CP_WAIT0()  asm volatile("cp.async.wait_group 0;" ::: "memory")

__device__ __forceinline__ uint32_t packh2(float a, float b) {
    __half2 h = __floats2half2_rn(a, b);
    return *(uint32_t*)&h;
}

// ---------------------------------------------------------------------------
// split_f4: fp32 -> (bf16 hi, bf16 lo), elementwise  (input x only)
// ---------------------------------------------------------------------------
__global__ void split_f4(const float* __restrict__ src,
                         __nv_bfloat16* __restrict__ hi,
                         __nv_bfloat16* __restrict__ lo, int n4)
{
    int i = blockIdx.x * blockDim.x + threadIdx.x;
    if (i >= n4) return;
    float4 v = ((const float4*)src)[i];
    __nv_bfloat16 h0 = __float2bfloat16(v.x), h1 = __float2bfloat16(v.y);
    __nv_bfloat16 h2 = __float2bfloat16(v.z), h3 = __float2bfloat16(v.w);
    __nv_bfloat16 l0 = __float2bfloat16(v.x - __bfloat162float(h0));
    __nv_bfloat16 l1 = __float2bfloat16(v.y - __bfloat162float(h1));
    __nv_bfloat16 l2 = __float2bfloat16(v.z - __bfloat162float(h2));
    __nv_bfloat16 l3 = __float2bfloat16(v.w - __bfloat162float(h3));
    ((__nv_bfloat162*)hi)[2 * i]     = __nv_bfloat162(h0, h1);
    ((__nv_bfloat162*)hi)[2 * i + 1] = __nv_bfloat162(h2, h3);
    ((__nv_bfloat162*)lo)[2 * i]     = __nv_bfloat162(l0, l1);
    ((__nv_bfloat162*)lo)[2 * i + 1] = __nv_bfloat162(l2, l3);
}

// W[K][N] -> Th/Tl[N][K] with split. 32x32 smem-tiled transpose.
__global__ void transpose_split(const float* __restrict__ W,
                                __nv_bfloat16* __restrict__ Th,
                                __nv_bfloat16* __restrict__ Tl, int K, int N)
{
    __shared__ float tile[32][33];
    int tx = threadIdx.x, ty = threadIdx.y;
    int n0 = blockIdx.x * 32, k0 = blockIdx.y * 32;
    #pragma unroll
    for (int j = 0; j < 32; j += 8)
        tile[ty + j][tx] = W[(size_t)(k0 + ty + j) * N + n0 + tx];
    __syncthreads();
    #pragma unroll
    for (int j = 0; j < 32; j += 8) {
        float v = tile[tx][ty + j];
        __nv_bfloat16 h = __float2bfloat16(v);
        __nv_bfloat16 l = __float2bfloat16(v - __bfloat162float(h));
        size_t o = (size_t)(n0 + ty + j) * K + k0 + tx;
        Th[o] = h;
        Tl[o] = l;
    }
}

// ---------------------------------------------------------------------------
// Shared GEMM mainloop: CTA 128x128, 512 threads (16 warps, 4x4 grid,
// 32x32 warp tile), KC=64, 3-stage cp.async, 1 barrier per chunk.
// ---------------------------------------------------------------------------
#define KC 64
#define PP 72                               // smem pitch in bf16 (144 B rows)
#define MAT_B (128 * PP * 2)                // 18432 B
#define STAGE_B (4 * MAT_B)                 // 73728 B
#define GEMM_DYN (3 * STAGE_B)              // 221184 B

static __device__ __forceinline__ void gemm_issue(
    uint32_t stage, const char* a0, const char* a1,
    const char* a2, const char* a3, int Kb, int k0b, int tid)
{
    const char* srcs[4] = {a0, a1, a2, a3};
    #pragma unroll
    for (int i = 0; i < 8; i++) {
        int idx = i * 512 + tid;
        int arr = idx >> 10, rem = idx & 1023;
        int row = rem >> 3, c = rem & 7;
        CP_A16(stage + arr * MAT_B + row * (PP * 2) + c * 16,
               srcs[arr] + (size_t)row * Kb + k0b + c * 16);
    }
}

#define GEMM_MAINLOOP(Ah, Al, Bh, Bl, K)                                      \
    const uint32_t sbase = smem_u32(dyn);                                     \
    const int NCH = (K) / KC;                                                 \
    const int Kb = (K) * 2;                                                   \
    const char* a0 = (const char*)((Ah) + (size_t)arow0 * (K));               \
    const char* a1 = (const char*)((Al) + (size_t)arow0 * (K));               \
    const char* a2 = (const char*)((Bh) + (size_t)bcol0 * (K));               \
    const char* a3 = (const char*)((Bl) + (size_t)bcol0 * (K));               \
    gemm_issue(sbase, a0, a1, a2, a3, Kb, 0, tid); CP_COMMIT();               \
    gemm_issue(sbase + STAGE_B, a0, a1, a2, a3, Kb, KC * 2, tid); CP_COMMIT();\
    for (int c = 0; c < NCH; c++) {                                           \
        if (c < NCH - 1) { CP_WAIT1(); } else { CP_WAIT0(); }                 \
        __syncthreads();                                                      \
        if (c + 2 < NCH) {                                                    \
            gemm_issue(sbase + (uint32_t)((c + 2) % 3) * STAGE_B,             \
                       a0, a1, a2, a3, Kb, (c + 2) * KC * 2, tid);            \
            CP_COMMIT();                                                      \
        }                                                                     \
        const uint32_t stb = sbase + (uint32_t)(c % 3) * STAGE_B;             \
        const uint32_t aAh = stb + 0 * MAT_B;                                 \
        const uint32_t aAl = stb + 1 * MAT_B;                                 \
        const uint32_t aBh = stb + 2 * MAT_B;                                 \
        const uint32_t aBl = stb + 3 * MAT_B;                                 \
        _Pragma("unroll")                                                     \
        for (int ks = 0; ks < KC / 16; ks++) {                                \
            const int k0 = ks * 16;                                           \
            uint32_t ahf[2][4], alf[2][4];                                    \
            uint32_t bhf[2][4], blf[2][4];                                    \
            _Pragma("unroll")                                                 \
            for (int mt = 0; mt < 2; mt++) {                                  \
                uint32_t ao = (uint32_t)((warp_m * 32 + mt * 16 + dr) * PP    \
                                         + k0 + dka) * 2;                     \
                LDSM_X4(ahf[mt], aAh + ao);                                   \
                LDSM_X4(alf[mt], aAl + ao);                                   \
            }                                                                 \
            _Pragma("unroll")                                                 \
            for (int pr = 0; pr < 2; pr++) {                                  \
                uint32_t bo = (uint32_t)((warp_n * 32 + pr * 16 + dn) * PP    \
                                         + k0 + dkb) * 2;                     \
                LDSM_X4(bhf[pr], aBh + bo);                                   \
                LDSM_X4(blf[pr], aBl + bo);                                   \
            }                                                                 \
            _Pragma("unroll")                                                 \
            for (int mt = 0; mt < 2; mt++)                                    \
                _Pragma("unroll")                                             \
                for (int nt = 0; nt < 4; nt++) {                              \
                    const int pr = nt >> 1, sb2 = (nt & 1) * 2;               \
                    MMA16816(acc[mt][nt], ahf[mt], bhf[pr][sb2], bhf[pr][sb2 + 1]); \
                    MMA16816(acc[mt][nt], ahf[mt], blf[pr][sb2], blf[pr][sb2 + 1]); \
                    MMA16816(acc[mt][nt], alf[mt], bhf[pr][sb2], bhf[pr][sb2 + 1]); \
                }                                                             \
        }                                                                     \
    }

// ---------------------------------------------------------------------------
// gemm_mma: generic fp32 output + bias (output projection)
// ---------------------------------------------------------------------------
__global__ __launch_bounds__(512, 1) void gemm_mma(
    const __nv_bfloat16* __restrict__ Ah, const __nv_bfloat16* __restrict__ Al,
    const __nv_bfloat16* __restrict__ Bh, const __nv_bfloat16* __restrict__ Bl,
    const float* __restrict__ bias, float* __restrict__ C,
    int M, int N, int K)
{
    extern __shared__ char dyn[];
    const int tid = threadIdx.x;
    const int wid = tid >> 5, l = tid & 31;
    const int warp_m = wid & 3, warp_n = wid >> 2;     // 4 x 4 warp grid
    const int bc = blockIdx.x, br = blockIdx.y;
    const int arow0 = br * 128, bcol0 = bc * 128;

    const int mat = l >> 3;
    const int dr  = (mat & 1) * 8 + (l & 7);
    const int dka = (mat >> 1) * 8;
    const int dn  = (mat >> 1) * 8 + (l & 7);
    const int dkb = (mat & 1) * 8;

    float acc[2][4][4];
    #pragma unroll
    for (int i = 0; i < 2; i++)
        #pragma unroll
        for (int j = 0; j < 4; j++)
            #pragma unroll
            for (int q = 0; q < 4; q++) acc[i][j][q] = 0.f;

    GEMM_MAINLOOP(Ah, Al, Bh, Bl, K)

    const int rbase = arow0 + warp_m * 32 + (l >> 2);
    const int cbase = bcol0 + warp_n * 32 + (l & 3) * 2;
    #pragma unroll
    for (int mt = 0; mt < 2; mt++)
        #pragma unroll
        for (int nt = 0; nt < 4; nt++) {
            const int row = rbase + mt * 16;
            const int col = cbase + nt * 8;
            float2 v0, v1;
            v0.x = acc[mt][nt][0] + bias[col];
            v0.y = acc[mt][nt][1] + bias[col + 1];
            v1.x = acc[mt][nt][2] + bias[col];
            v1.y = acc[mt][nt][3] + bias[col + 1];
            *(float2*)(C + (size_t)row * N + col) = v0;
            *(float2*)(C + (size_t)(row + 8) * N + col) = v1;
        }
}

// ---------------------------------------------------------------------------
// gemm_qkv: QKV projection with fused split epilogue (Q/K/V consumer formats)
// ---------------------------------------------------------------------------
__global__ __launch_bounds__(512, 1) void gemm_qkv(
    const __nv_bfloat16* __restrict__ Ah, const __nv_bfloat16* __restrict__ Al,
    const __nv_bfloat16* __restrict__ Bh, const __nv_bfloat16* __restrict__ Bl,
    const float* __restrict__ bias,
    __nv_bfloat16* __restrict__ qh, __nv_bfloat16* __restrict__ ql,
    __nv_bfloat16* __restrict__ kh, __nv_bfloat16* __restrict__ kl,
    __half* __restrict__ vh)
{
    extern __shared__ char dyn[];
    const int tid = threadIdx.x;
    const int wid = tid >> 5, l = tid & 31;
    const int warp_m = wid & 3, warp_n = wid >> 2;
    const int bc = blockIdx.x, br = blockIdx.y;
    const int arow0 = br * 128, bcol0 = bc * 128;
    const int K = CCH;

    const int mat = l >> 3;
    const int dr  = (mat & 1) * 8 + (l & 7);
    const int dka = (mat >> 1) * 8;
    const int dn  = (mat >> 1) * 8 + (l & 7);
    const int dkb = (mat & 1) * 8;

    float acc[2][4][4];
    #pragma unroll
    for (int i = 0; i < 2; i++)
        #pragma unroll
        for (int j = 0; j < 4; j++)
            #pragma unroll
            for (int q = 0; q < 4; q++) acc[i][j][q] = 0.f;

    GEMM_MAINLOOP(Ah, Al, Bh, Bl, K)

    const int rbase = arow0 + warp_m * 32 + (l >> 2);
    const int cbase = bcol0 + warp_n * 32 + (l & 3) * 2;
    #pragma unroll
    for (int mt = 0; mt < 2; mt++)
        #pragma unroll
        for (int nt = 0; nt < 4; nt++) {
            #pragma unroll
            for (int half2i = 0; half2i < 2; half2i++) {
                const int row = rbase + mt * 16 + half2i * 8;
                const int col = cbase + nt * 8;
                float v0 = acc[mt][nt][half2i * 2 + 0] + bias[col];
                float v1 = acc[mt][nt][half2i * 2 + 1] + bias[col + 1];
                if (bc < 8) {
                    v0 *= 0.125f; v1 *= 0.125f;
                    __nv_bfloat16 h0 = __float2bfloat16(v0);
                    __nv_bfloat16 h1 = __float2bfloat16(v1);
                    size_t o = (size_t)row * DA + col;
                    *(__nv_bfloat162*)(qh + o) = __nv_bfloat162(h0, h1);
                    *(__nv_bfloat162*)(ql + o) = __nv_bfloat162(
                        __float2bfloat16(v0 - __bfloat162float(h0)),
                        __float2bfloat16(v1 - __bfloat162float(h1)));
                } else {
                    const int cg = col - (bc < 16 ? 1024 : 2048);
                    const int head = cg >> 6, d = cg & 63;
                    const int t = row & (TT - 1), bb = row >> 11;
                    size_t o = ((size_t)(bb * NH + head) * TT + t) * 64 + d;
                    if (bc < 16) {
                        __nv_bfloat16 h0 = __float2bfloat16(v0);
                        __nv_bfloat16 h1 = __float2bfloat16(v1);
                        *(__nv_bfloat162*)(kh + o) = __nv_bfloat162(h0, h1);
                        *(__nv_bfloat162*)(kl + o) = __nv_bfloat162(
                            __float2bfloat16(v0 - __bfloat162float(h0)),
                            __float2bfloat16(v1 - __bfloat162float(h1)));
                    } else {
                        *(__half2*)(vh + o) =
                            __half2(__float2half_rn(v0), __float2half_rn(v1));
                    }
                }
            }
        }
}

// ---------------------------------------------------------------------------
// Tensor-core flash attention v6 (causal):
//  - 2 CTAs/SM, regs 128, Q frags re-loaded from smem per tile
//  - KV stage = Kh,Kl,Vh (single fp16 V product — Vl dropped)
//  - 2-stage cp.async KV pipeline, LPT scheduling
// ---------------------------------------------------------------------------
#define QPF 72                              // smem pitch in b16 elems
#define KVT_B (64 * QPF * 2)                // 9216 B per array tile
#define KV_STAGE (3 * KVT_B)                // 27648 B (Kh, Kl, Vh)
#define Q_OFF (2 * KV_STAGE)                // 55296
#define QARR_B (128 * QPF * 2)              // 18432 B per Q array
#define FL_DYN (2 * KV_STAGE + 2 * QARR_B)  // 92160 B  (x2 CTAs = 180 KB/SM)

static __device__ __forceinline__ void flash_issue(
    uint32_t stage, const char* kh, const char* kl,
    const char* vh, size_t tile_off, int tid)
{
    const char* srcs[3] = {kh + tile_off, kl + tile_off, vh + tile_off};
    #pragma unroll
    for (int i = 0; i < 6; i++) {
        int idx = i * 256 + tid;
        int arr = idx >> 9, rem = idx & 511;
        int r = rem >> 3, c = rem & 7;
        CP_A16(stage + arr * KVT_B + r * (QPF * 2) + c * 16,
               srcs[arr] + r * 128 + c * 16);
    }
}

__global__ __launch_bounds__(256, 2) void flash_mma(
    const __nv_bfloat16* __restrict__ qh_g, const __nv_bfloat16* __restrict__ ql_g,
    const __nv_bfloat16* __restrict__ kh_g, const __nv_bfloat16* __restrict__ kl_g,
    const __half* __restrict__ vh_g,
    __nv_bfloat16* __restrict__ oh, __nv_bfloat16* __restrict__ ol)
{
    extern __shared__ char fsm[];
    const int tid = threadIdx.x;
    const int w = tid >> 5, l = tid & 31;
    const int qt = (int)gridDim.x - 1 - (int)blockIdx.x;   // LPT: big tiles first
    const int h = blockIdx.y, b = blockIdx.z;

    const uint32_t sbase = smem_u32(fsm);
    const size_t headoff = ((size_t)(b * NH + h) * TT) * 64 * 2;  // bytes
    const char* kh_c = (const char*)kh_g + headoff;
    const char* kl_c = (const char*)kl_g + headoff;
    const char* vh_c = (const char*)vh_g + headoff;
    const int jmax = 2 * qt + 1;

    // Prologue: Q region (group 0), KV stage 0 (group 1), KV stage 1 (group 2)
    {
        const char* q0 = (const char*)qh_g
            + ((size_t)(b * TT + qt * 128) * DA + h * 64) * 2;
        const char* q1 = (const char*)ql_g
            + ((size_t)(b * TT + qt * 128) * DA + h * 64) * 2;
        const char* srcs[2] = {q0, q1};
        #pragma unroll
        for (int i = 0; i < 8; i++) {
            int idx = i * 256 + tid;
            int arr = idx >> 10, rem = idx & 1023;
            int r = rem >> 3, c = rem & 7;
            CP_A16(sbase + Q_OFF + arr * QARR_B + r * (QPF * 2) + c * 16,
                   srcs[arr] + (size_t)r * (DA * 2) + c * 16);
        }
    }
    CP_COMMIT();
    flash_issue(sbase, kh_c, kl_c, vh_c, 0, tid);
    CP_COMMIT();
    flash_issue(sbase + KV_STAGE, kh_c, kl_c, vh_c, 8192, tid);
    CP_COMMIT();
    CP_WAIT2();        // Q region complete
    __syncthreads();

    const int mat = l >> 3;
    const int dr  = (mat & 1) * 8 + (l & 7);
    const int dka = (mat >> 1) * 8;
    const int dn  = (mat >> 1) * 8 + (l & 7);
    const int dkb = (mat & 1) * 8;
    const uint32_t aQh = sbase + Q_OFF, aQl = aQh + QARR_B;

    float o[8][4];
    #pragma unroll
    for (int nt = 0; nt < 8; nt++)
        #pragma unroll
        for (int e = 0; e < 4; e++) o[nt][e] = 0.f;
    float m_a = -INFINITY, m_b = -INFINITY, l_a = 0.f, l_b = 0.f;

    for (int j = 0; j <= jmax; j++) {
        if (j < jmax) { CP_WAIT1(); } else { CP_WAIT0(); }
        __syncthreads();   // stage j&1 published to all warps

        const bool active = (j * 64 <= qt * 128 + w * 16 + 15);
        if (active) {
            const uint32_t sb = sbase + (uint32_t)(j & 1) * KV_STAGE;
            const uint32_t aKh = sb, aKl = sb + KVT_B;
            const uint32_t aVh = sb + 2 * KVT_B;

            float c[8][4];
            #pragma unroll
            for (int nt = 0; nt < 8; nt++)
                #pragma unroll
                for (int e = 0; e < 4; e++) c[nt][e] = 0.f;

            #pragma unroll
            for (int t = 0; t < 4; t++) {
                uint32_t qhf[4], qlf[4];
                uint32_t qo = (uint32_t)((w * 16 + dr) * QPF + t * 16 + dka) * 2;
                LDSM_X4(qhf, aQh + qo);
                LDSM_X4(qlf, aQl + qo);
                #pragma unroll
                for (int p = 0; p < 4; p++) {
                    uint32_t kb[4], kl2[4];
                    uint32_t bo = (uint32_t)((p * 16 + dn) * QPF + t * 16 + dkb) * 2;
                    LDSM_X4(kb, aKh + bo);
                    LDSM_X4(kl2, aKl + bo);
                    #pragma unroll
                    for (int sub = 0; sub < 2; sub++) {
                        const int nt = 2 * p + sub;
                        MMA16816(c[nt], qhf, kb[sub * 2], kb[sub * 2 + 1]);
                        MMA16816(c[nt], qhf, kl2[sub * 2], kl2[sub * 2 + 1]);
                        MMA16816(c[nt], qlf, kb[sub * 2], kb[sub * 2 + 1]);
                    }
                }
            }

            if (j >= 2 * qt) {
                const int qa = qt * 128 + w * 16 + (l >> 2);
                const int kc0 = j * 64 + (l & 3) * 2;
                #pragma unroll
                for (int nt = 0; nt < 8; nt++) {
                    int col = kc0 + nt * 8;
                    if (col > qa)     c[nt][0] = -INFINITY;
                    if (col + 1 > qa) c[nt][1] = -INFINITY;
                    if (col > qa + 8)     c[nt][2] = -INFINITY;
                    if (col + 1 > qa + 8) c[nt][3] = -INFINITY;
                }
            }

            float ma = -INFINITY, mb = -INFINITY;
            #pragma unroll
            for (int nt = 0; nt < 8; nt++) {
                ma = fmaxf(ma, fmaxf(c[nt][0], c[nt][1]));
                mb = fmaxf(mb, fmaxf(c[nt][2], c[nt][3]));
            }
            ma = fmaxf(ma, __shfl_xor_sync(0xffffffffu, ma, 1));
            ma = fmaxf(ma, __shfl_xor_sync(0xffffffffu, ma, 2));
            mb = fmaxf(mb, __shfl_xor_sync(0xffffffffu, mb, 1));
            mb = fmaxf(mb, __shfl_xor_sync(0xffffffffu, mb, 2));
            float mna = fmaxf(m_a, ma), mnb = fmaxf(m_b, mb);
            float aa = __expf(m_a - mna), ab = __expf(m_b - mnb);
            float sa = 0.f, sb2 = 0.f;
            #pragma unroll
            for (int nt = 0; nt < 8; nt++) {
                c[nt][0] = __expf(c[nt][0] - mna);
                c[nt][1] = __expf(c[nt][1] - mna);
                c[nt][2] = __expf(c[nt][2] - mnb);
                c[nt][3] = __expf(c[nt][3] - mnb);
                sa += c[nt][0] + c[nt][1];
                sb2 += c[nt][2] + c[nt][3];
            }
            sa += __shfl_xor_sync(0xffffffffu, sa, 1);
            sa += __shfl_xor_sync(0xffffffffu, sa, 2);
            sb2 += __shfl_xor_sync(0xffffffffu, sb2, 1);
            sb2 += __shfl_xor_sync(0xffffffffu, sb2, 2);
            l_a = l_a * aa + sa;
            l_b = l_b * ab + sb2;
            m_a = mna; m_b = mnb;
            #pragma unroll
            for (int nt = 0; nt < 8; nt++) {
                o[nt][0] *= aa; o[nt][1] *= aa;
                o[nt][2] *= ab; o[nt][3] *= ab;
            }

            #pragma unroll
            for (int t = 0; t < 4; t++) {
                uint32_t pa[4];
                pa[0] = packh2(c[2 * t][0],     c[2 * t][1]);
                pa[1] = packh2(c[2 * t][2],     c[2 * t][3]);
                pa[2] = packh2(c[2 * t + 1][0], c[2 * t + 1][1]);
                pa[3] = packh2(c[2 * t + 1][2], c[2 * t + 1][3]);
                #pragma unroll
                for (int p = 0; p < 4; p++) {
                    uint32_t vb[4];
                    uint32_t vo = (uint32_t)((t * 16 + (mat & 1) * 8 + (l & 7)) * QPF
                                             + p * 16 + (mat >> 1) * 8) * 2;
                    LDSM_X4_T(vb, aVh + vo);
                    MMA16816H(o[2 * p],     pa, vb[0], vb[1]);
                    MMA16816H(o[2 * p + 1], pa, vb[2], vb[3]);
                }
            }
        }
        __syncthreads();   // all warps done reading stage j&1
        if (j + 2 <= jmax) {
            flash_issue(sbase + (uint32_t)(j & 1) * KV_STAGE,
                        kh_c, kl_c, vh_c, (size_t)(j + 2) * 8192, tid);
            CP_COMMIT();
        }
    }

    // Epilogue: write split bf16 directly (feeds phase-3 GEMM)
    const float ia = 1.f / l_a, ib = 1.f / l_b;
    const int row = (b * TT + qt * 128 + w * 16 + (l >> 2));
    const int col = h * 64 + (l & 3) * 2;
    #pragma unroll
    for (int nt = 0; nt < 8; nt++) {
        float v0 = o[nt][0] * ia, v1 = o[nt][1] * ia;
        float v2 = o[nt][2] * ib, v3 = o[nt][3] * ib;
        __nv_bfloat16 h0 = __float2bfloat16(v0), h1 = __float2bfloat16(v1);
        __nv_bfloat16 h2 = __float2bfloat16(v2), h3 = __float2bfloat16(v3);
        size_t o0 = (size_t)row * DA + col + nt * 8;
        size_t o1 = (size_t)(row + 8) * DA + col + nt * 8;
        *(__nv_bfloat162*)(oh + o0) = __nv_bfloat162(h0, h1);
        *(__nv_bfloat162*)(ol + o0) = __nv_bfloat162(
            __float2bfloat16(v0 - __bfloat162float(h0)),
            __float2bfloat16(v1 - __bfloat162float(h1)));
        *(__nv_bfloat162*)(oh + o1) = __nv_bfloat162(h2, h3);
        *(__nv_bfloat162*)(ol + o1) = __nv_bfloat162(
            __float2bfloat16(v2 - __bfloat162float(h2)),
            __float2bfloat16(v3 - __bfloat162float(h3)));
    }
}

// ---------------------------------------------------------------------------
// Launch
// ---------------------------------------------------------------------------
extern "C" void kernel_launch(void* const* d_in, const int* in_sizes, int n_in,
                              void* d_out, int out_size)
{
    const float* x    = (const float*)d_in[0];
    const float* Wqkv = (const float*)d_in[2];
    const float* bqkv = (const float*)d_in[3];
    const float* Wout = (const float*)d_in[4];
    const float* bout = (const float*)d_in[5];
    float* out = (float*)d_out;

    __nv_bfloat16 *ah, *al, *bh, *bl, *qh, *ql, *kh, *kl;
    __half *vh;
    cudaGetSymbolAddress((void**)&ah, g_ah);
    cudaGetSymbolAddress((void**)&al, g_al);
    cudaGetSymbolAddress((void**)&bh, g_bh);
    cudaGetSymbolAddress((void**)&bl, g_bl);
    cudaGetSymbolAddress((void**)&qh, g_qh);
    cudaGetSymbolAddress((void**)&ql, g_ql);
    cudaGetSymbolAddress((void**)&kh, g_kh);
    cudaGetSymbolAddress((void**)&kl, g_kl);
    cudaGetSymbolAddress((void**)&vh, g_vh);

    cudaFuncSetAttribute(gemm_mma,
                         cudaFuncAttributeMaxDynamicSharedMemorySize, (int)GEMM_DYN);
    cudaFuncSetAttribute(gemm_qkv,
                         cudaFuncAttributeMaxDynamicSharedMemorySize, (int)GEMM_DYN);
    cudaFuncSetAttribute(flash_mma,
                         cudaFuncAttributeMaxDynamicSharedMemorySize, (int)FL_DYN);

    // Phase 1: QKV projection with fused split epilogue
    split_f4<<<(MM * CCH / 4 + 255) / 256, 256>>>(x, ah, al, MM * CCH / 4);
    transpose_split<<<dim3(3 * DA / 32, CCH / 32), dim3(32, 8)>>>(Wqkv, bh, bl, CCH, 3 * DA);
    gemm_qkv<<<dim3(3 * DA / 128, MM / 128), 512, GEMM_DYN>>>(
        ah, al, bh, bl, bqkv, qh, ql, kh, kl, vh);

    // Phase 2: tensor-core flash (writes split attn to ah/al)
    flash_mma<<<dim3(TT / 128, NH, BV), 256, FL_DYN>>>(
        qh, ql, kh, kl, vh, ah, al);

    // Phase 3: out = attn @ Wout + b
    transpose_split<<<dim3(CCH / 32, DA / 32), dim3(32, 8)>>>(Wout, bh, bl, DA, CCH);
    gemm_mma<<<dim3(CCH / 128, MM / 128), 512, GEMM_DYN>>>(
        ah, al, bh, bl, bout, out, MM, CCH, DA);
}

// round 12
// speedup vs baseline: 4.9346x; 1.1035x over previous
#include <cuda_runtime.h>
#include <cuda_bf16.h>
#include <cuda_fp16.h>
#include <math.h>
#include <stdint.h>

// Problem constants
#define BV 4
#define TT 2048
#define CCH 1024
#define DA 1024
#define NH 16
#define HDM 64
#define MM (BV * TT)   // 8192 rows

// ---------------------------------------------------------------------------
// Device scratch (allocations forbidden; __device__ globals are sanctioned)
// ---------------------------------------------------------------------------
__device__ float g_a32[(size_t)MM * CCH];                 // activations (tf32)
__device__ float g_b32[(size_t)CCH * 3 * DA];             // W^T (tf32)
__device__ __nv_bfloat16 g_qh[(size_t)MM * DA];           // Q split (scaled)
__device__ __nv_bfloat16 g_ql[(size_t)MM * DA];
__device__ __nv_bfloat16 g_kh[(size_t)MM * DA];           // head-major K split
__device__ __nv_bfloat16 g_kl[(size_t)MM * DA];
__device__ __half        g_vh[(size_t)MM * DA];           // head-major V (fp16)

__device__ __forceinline__ uint32_t smem_u32(const void* p) {
    uint32_t a;
    asm("{ .reg .u64 t; cvta.to.shared.u64 t, %1; cvt.u32.u64 %0, t; }"
        : "=r"(a) : "l"(p));
    return a;
}
__device__ __forceinline__ float cvt_tf32(float x) {
    uint32_t r;
    asm("cvt.rna.tf32.f32 %0, %1;" : "=r"(r) : "f"(x));
    return __uint_as_float(r);
}

#define LDSM_X4(r, addr) \
    asm volatile("ldmatrix.sync.aligned.m8n8.x4.shared.b16 {%0,%1,%2,%3}, [%4];" \
        : "=r"((r)[0]), "=r"((r)[1]), "=r"((r)[2]), "=r"((r)[3]) : "r"(addr))

#define LDSM_X4_T(r, addr) \
    asm volatile("ldmatrix.sync.aligned.m8n8.x4.trans.shared.b16 {%0,%1,%2,%3}, [%4];" \
        : "=r"((r)[0]), "=r"((r)[1]), "=r"((r)[2]), "=r"((r)[3]) : "r"(addr))

#define MMA16816(c, a, b0, b1) \
    asm volatile("mma.sync.aligned.m16n8k16.row.col.f32.bf16.bf16.f32 " \
        "{%0,%1,%2,%3}, {%4,%5,%6,%7}, {%8,%9}, {%0,%1,%2,%3};" \
        : "+f"((c)[0]), "+f"((c)[1]), "+f"((c)[2]), "+f"((c)[3]) \
        : "r"((a)[0]), "r"((a)[1]), "r"((a)[2]), "r"((a)[3]), "r"(b0), "r"(b1))

#define MMA16816H(c, a, b0, b1) \
    asm volatile("mma.sync.aligned.m16n8k16.row.col.f32.f16.f16.f32 " \
        "{%0,%1,%2,%3}, {%4,%5,%6,%7}, {%8,%9}, {%0,%1,%2,%3};" \
        : "+f"((c)[0]), "+f"((c)[1]), "+f"((c)[2]), "+f"((c)[3]) \
        : "r"((a)[0]), "r"((a)[1]), "r"((a)[2]), "r"((a)[3]), "r"(b0), "r"(b1))

#define MMA168T(c, a, b0, b1) \
    asm volatile("mma.sync.aligned.m16n8k8.row.col.f32.tf32.tf32.f32 " \
        "{%0,%1,%2,%3}, {%4,%5,%6,%7}, {%8,%9}, {%0,%1,%2,%3};" \
        : "+f"((c)[0]), "+f"((c)[1]), "+f"((c)[2]), "+f"((c)[3]) \
        : "r"((a)[0]), "r"((a)[1]), "r"((a)[2]), "r"((a)[3]), "r"(b0), "r"(b1))

#define CP_A16(dst, src) \
    asm volatile("cp.async.cg.shared.global [%0], [%1], 16;" \
                 :: "r"(dst), "l"(src) : "memory")
#define CP_COMMIT() asm volatile("cp.async.commit_group;" ::: "memory")
#define CP_WAIT2()  asm volatile("cp.async.wait_group 2;" ::: "memory")
#define CP_WAIT1()  asm volatile("cp.async.wait_group 1;" ::: "memory")
#define CP_WAIT0()  asm volatile("cp.async.wait_group 0;" ::: "memory")

__device__ __forceinline__ uint32_t packh2(float a, float b) {
    __half2 h = __floats2half2_rn(a, b);
    return *(uint32_t*)&h;
}

// ---------------------------------------------------------------------------
// round_tf32: fp32 -> tf32-rounded fp32 (input x)
// ---------------------------------------------------------------------------
__global__ void round_tf32(const float* __restrict__ src,
                           float* __restrict__ dst, int n4)
{
    int i = blockIdx.x * blockDim.x + threadIdx.x;
    if (i >= n4) return;
    float4 v = ((const float4*)src)[i];
    v.x = cvt_tf32(v.x); v.y = cvt_tf32(v.y);
    v.z = cvt_tf32(v.z); v.w = cvt_tf32(v.w);
    ((float4*)dst)[i] = v;
}

// W[K][N] -> T[N][K] tf32-rounded. 32x32 smem-tiled transpose.
__global__ void transpose_tf32(const float* __restrict__ W,
                               float* __restrict__ T, int K, int N)
{
    __shared__ float tile[32][33];
    int tx = threadIdx.x, ty = threadIdx.y;
    int n0 = blockIdx.x * 32, k0 = blockIdx.y * 32;
    #pragma unroll
    for (int j = 0; j < 32; j += 8)
        tile[ty + j][tx] = W[(size_t)(k0 + ty + j) * N + n0 + tx];
    __syncthreads();
    #pragma unroll
    for (int j = 0; j < 32; j += 8)
        T[(size_t)(n0 + ty + j) * K + k0 + tx] = cvt_tf32(tile[tx][ty + j]);
}

// ---------------------------------------------------------------------------
// tf32 GEMM mainloop: CTA 128x128, 512 threads (16 warps, 4x4 grid, 32x32
// warp tile), KC=64, 3-stage cp.async, single tf32 product.
// Smem pitch 68 fp32 (272 B rows) -> conflict-free ldmatrix phases.
// ---------------------------------------------------------------------------
#define KC 64
#define P4 68
#define MAT4_B (128 * P4 * 4)               // 34816 B
#define STG4_B (2 * MAT4_B)                 // 69632 B (A32, B32)
#define GEMM_DYN (3 * STG4_B)               // 208896 B

static __device__ __forceinline__ void gemm_issue4(
    uint32_t stage, const char* a, const char* b, int Kb, int k0b, int tid)
{
    const char* srcs[2] = {a, b};
    #pragma unroll
    for (int i = 0; i < 8; i++) {
        int idx = i * 512 + tid;
        int arr = idx >> 11, rem = idx & 2047;
        int row = rem >> 4, c = rem & 15;
        CP_A16(stage + arr * MAT4_B + row * (P4 * 4) + c * 16,
               srcs[arr] + (size_t)row * Kb + k0b + c * 16);
    }
}

// Computes acc[2][4][4] for this CTA tile (tf32 single product).
// Lane helpers: mat = l>>3, lr = (mat&1)*8 + (l&7)  (ldmatrix address row),
// lc = (mat>>1)*4 (tf32 k-col offset).
#define GEMM_MAINLOOP(A32, B32, K)                                            \
    const uint32_t sbase = smem_u32(dyn);                                     \
    const int NCH = (K) / KC;                                                 \
    const int Kb = (K) * 4;                                                   \
    const char* ga = (const char*)((A32) + (size_t)arow0 * (K));              \
    const char* gb = (const char*)((B32) + (size_t)bcol0 * (K));              \
    gemm_issue4(sbase, ga, gb, Kb, 0, tid); CP_COMMIT();                      \
    gemm_issue4(sbase + STG4_B, ga, gb, Kb, KC * 4, tid); CP_COMMIT();        \
    for (int c = 0; c < NCH; c++) {                                           \
        if (c < NCH - 1) { CP_WAIT1(); } else { CP_WAIT0(); }                 \
        __syncthreads();                                                      \
        if (c + 2 < NCH) {                                                    \
            gemm_issue4(sbase + (uint32_t)((c + 2) % 3) * STG4_B,             \
                        ga, gb, Kb, (c + 2) * KC * 4, tid);                   \
            CP_COMMIT();                                                      \
        }                                                                     \
        const uint32_t aA = sbase + (uint32_t)(c % 3) * STG4_B;               \
        const uint32_t aB = aA + MAT4_B;                                      \
        _Pragma("unroll")                                                     \
        for (int ks = 0; ks < KC / 8; ks++) {                                 \
            const int k0 = ks * 8;                                            \
            uint32_t af[2][4], bf[2][4];                                      \
            _Pragma("unroll")                                                 \
            for (int mt = 0; mt < 2; mt++) {                                  \
                uint32_t ao = (uint32_t)((warp_m * 32 + mt * 16 + lr) * P4    \
                                         + k0 + lc) * 4;                      \
                LDSM_X4(af[mt], aA + ao);                                     \
            }                                                                 \
            _Pragma("unroll")                                                 \
            for (int pr = 0; pr < 2; pr++) {                                  \
                uint32_t bo = (uint32_t)((warp_n * 32 + pr * 16 + lr) * P4    \
                                         + k0 + lc) * 4;                      \
                LDSM_X4(bf[pr], aB + bo);                                     \
            }                                                                 \
            _Pragma("unroll")                                                 \
            for (int mt = 0; mt < 2; mt++)                                    \
                _Pragma("unroll")                                             \
                for (int nt = 0; nt < 4; nt++) {                              \
                    const int pr = nt >> 1, od = nt & 1;                      \
                    MMA168T(acc[mt][nt], af[mt], bf[pr][od], bf[pr][od + 2]); \
                }                                                             \
        }                                                                     \
    }

// ---------------------------------------------------------------------------
// gemm_mma: generic fp32 output + bias (output projection)
// ---------------------------------------------------------------------------
__global__ __launch_bounds__(512, 1) void gemm_mma(
    const float* __restrict__ A32, const float* __restrict__ B32,
    const float* __restrict__ bias, float* __restrict__ C,
    int M, int N, int K)
{
    extern __shared__ char dyn[];
    const int tid = threadIdx.x;
    const int wid = tid >> 5, l = tid & 31;
    const int warp_m = wid & 3, warp_n = wid >> 2;     // 4 x 4 warp grid
    const int bc = blockIdx.x, br = blockIdx.y;
    const int arow0 = br * 128, bcol0 = bc * 128;

    const int mat = l >> 3;
    const int lr = (mat & 1) * 8 + (l & 7);
    const int lc = (mat >> 1) * 4;

    float acc[2][4][4];
    #pragma unroll
    for (int i = 0; i < 2; i++)
        #pragma unroll
        for (int j = 0; j < 4; j++)
            #pragma unroll
            for (int q = 0; q < 4; q++) acc[i][j][q] = 0.f;

    GEMM_MAINLOOP(A32, B32, K)

    const int rbase = arow0 + warp_m * 32 + (l >> 2);
    const int cbase = bcol0 + warp_n * 32 + (l & 3) * 2;
    #pragma unroll
    for (int mt = 0; mt < 2; mt++)
        #pragma unroll
        for (int nt = 0; nt < 4; nt++) {
            const int row = rbase + mt * 16;
            const int col = cbase + nt * 8;
            float2 v0, v1;
            v0.x = acc[mt][nt][0] + bias[col];
            v0.y = acc[mt][nt][1] + bias[col + 1];
            v1.x = acc[mt][nt][2] + bias[col];
            v1.y = acc[mt][nt][3] + bias[col + 1];
            *(float2*)(C + (size_t)row * N + col) = v0;
            *(float2*)(C + (size_t)(row + 8) * N + col) = v1;
        }
}

// ---------------------------------------------------------------------------
// gemm_qkv: QKV projection with fused split epilogue (Q/K/V consumer formats)
// ---------------------------------------------------------------------------
__global__ __launch_bounds__(512, 1) void gemm_qkv(
    const float* __restrict__ A32, const float* __restrict__ B32,
    const float* __restrict__ bias,
    __nv_bfloat16* __restrict__ qh, __nv_bfloat16* __restrict__ ql,
    __nv_bfloat16* __restrict__ kh, __nv_bfloat16* __restrict__ kl,
    __half* __restrict__ vh)
{
    extern __shared__ char dyn[];
    const int tid = threadIdx.x;
    const int wid = tid >> 5, l = tid & 31;
    const int warp_m = wid & 3, warp_n = wid >> 2;
    const int bc = blockIdx.x, br = blockIdx.y;
    const int arow0 = br * 128, bcol0 = bc * 128;
    const int K = CCH;

    const int mat = l >> 3;
    const int lr = (mat & 1) * 8 + (l & 7);
    const int lc = (mat >> 1) * 4;

    float acc[2][4][4];
    #pragma unroll
    for (int i = 0; i < 2; i++)
        #pragma unroll
        for (int j = 0; j < 4; j++)
            #pragma unroll
            for (int q = 0; q < 4; q++) acc[i][j][q] = 0.f;

    GEMM_MAINLOOP(A32, B32, K)

    const int rbase = arow0 + warp_m * 32 + (l >> 2);
    const int cbase = bcol0 + warp_n * 32 + (l & 3) * 2;
    #pragma unroll
    for (int mt = 0; mt < 2; mt++)
        #pragma unroll
        for (int nt = 0; nt < 4; nt++) {
            #pragma unroll
            for (int half2i = 0; half2i < 2; half2i++) {
                const int row = rbase + mt * 16 + half2i * 8;
                const int col = cbase + nt * 8;
                float v0 = acc[mt][nt][half2i * 2 + 0] + bias[col];
                float v1 = acc[mt][nt][half2i * 2 + 1] + bias[col + 1];
                if (bc < 8) {
                    v0 *= 0.125f; v1 *= 0.125f;
                    __nv_bfloat16 h0 = __float2bfloat16(v0);
                    __nv_bfloat16 h1 = __float2bfloat16(v1);
                    size_t o = (size_t)row * DA + col;
                    *(__nv_bfloat162*)(qh + o) = __nv_bfloat162(h0, h1);
                    *(__nv_bfloat162*)(ql + o) = __nv_bfloat162(
                        __float2bfloat16(v0 - __bfloat162float(h0)),
                        __float2bfloat16(v1 - __bfloat162float(h1)));
                } else {
                    const int cg = col - (bc < 16 ? 1024 : 2048);
                    const int head = cg >> 6, d = cg & 63;
                    const int t = row & (TT - 1), bb = row >> 11;
                    size_t o = ((size_t)(bb * NH + head) * TT + t) * 64 + d;
                    if (bc < 16) {
                        __nv_bfloat16 h0 = __float2bfloat16(v0);
                        __nv_bfloat16 h1 = __float2bfloat16(v1);
                        *(__nv_bfloat162*)(kh + o) = __nv_bfloat162(h0, h1);
                        *(__nv_bfloat162*)(kl + o) = __nv_bfloat162(
                            __float2bfloat16(v0 - __bfloat162float(h0)),
                            __float2bfloat16(v1 - __bfloat162float(h1)));
                    } else {
                        *(__half2*)(vh + o) =
                            __half2(__float2half_rn(v0), __float2half_rn(v1));
                    }
                }
            }
        }
}

// ---------------------------------------------------------------------------
// Tensor-core flash attention v6 (causal) — unchanged mainloop; epilogue
// writes tf32-rounded fp32 into a32 (out-proj A operand).
// ---------------------------------------------------------------------------
#define QPF 72
#define KVT_B (64 * QPF * 2)
#define KV_STAGE (3 * KVT_B)
#define Q_OFF (2 * KV_STAGE)
#define QARR_B (128 * QPF * 2)
#define FL_DYN (2 * KV_STAGE + 2 * QARR_B)   // 92160 B

static __device__ __forceinline__ void flash_issue(
    uint32_t stage, const char* kh, const char* kl,
    const char* vh, size_t tile_off, int tid)
{
    const char* srcs[3] = {kh + tile_off, kl + tile_off, vh + tile_off};
    #pragma unroll
    for (int i = 0; i < 6; i++) {
        int idx = i * 256 + tid;
        int arr = idx >> 9, rem = idx & 511;
        int r = rem >> 3, c = rem & 7;
        CP_A16(stage + arr * KVT_B + r * (QPF * 2) + c * 16,
               srcs[arr] + r * 128 + c * 16);
    }
}

__global__ __launch_bounds__(256, 2) void flash_mma(
    const __nv_bfloat16* __restrict__ qh_g, const __nv_bfloat16* __restrict__ ql_g,
    const __nv_bfloat16* __restrict__ kh_g, const __nv_bfloat16* __restrict__ kl_g,
    const __half* __restrict__ vh_g, float* __restrict__ o32)
{
    extern __shared__ char fsm[];
    const int tid = threadIdx.x;
    const int w = tid >> 5, l = tid & 31;
    const int qt = (int)gridDim.x - 1 - (int)blockIdx.x;
    const int h = blockIdx.y, b = blockIdx.z;

    const uint32_t sbase = smem_u32(fsm);
    const size_t headoff = ((size_t)(b * NH + h) * TT) * 64 * 2;
    const char* kh_c = (const char*)kh_g + headoff;
    const char* kl_c = (const char*)kl_g + headoff;
    const char* vh_c = (const char*)vh_g + headoff;
    const int jmax = 2 * qt + 1;

    {
        const char* q0 = (const char*)qh_g
            + ((size_t)(b * TT + qt * 128) * DA + h * 64) * 2;
        const char* q1 = (const char*)ql_g
            + ((size_t)(b * TT + qt * 128) * DA + h * 64) * 2;
        const char* srcs[2] = {q0, q1};
        #pragma unroll
        for (int i = 0; i < 8; i++) {
            int idx = i * 256 + tid;
            int arr = idx >> 10, rem = idx & 1023;
            int r = rem >> 3, c = rem & 7;
            CP_A16(sbase + Q_OFF + arr * QARR_B + r * (QPF * 2) + c * 16,
                   srcs[arr] + (size_t)r * (DA * 2) + c * 16);
        }
    }
    CP_COMMIT();
    flash_issue(sbase, kh_c, kl_c, vh_c, 0, tid);
    CP_COMMIT();
    flash_issue(sbase + KV_STAGE, kh_c, kl_c, vh_c, 8192, tid);
    CP_COMMIT();
    CP_WAIT2();
    __syncthreads();

    const int mat = l >> 3;
    const int dr  = (mat & 1) * 8 + (l & 7);
    const int dka = (mat >> 1) * 8;
    const int dn  = (mat >> 1) * 8 + (l & 7);
    const int dkb = (mat & 1) * 8;
    const uint32_t aQh = sbase + Q_OFF, aQl = aQh + QARR_B;

    float o[8][4];
    #pragma unroll
    for (int nt = 0; nt < 8; nt++)
        #pragma unroll
        for (int e = 0; e < 4; e++) o[nt][e] = 0.f;
    float m_a = -INFINITY, m_b = -INFINITY, l_a = 0.f, l_b = 0.f;

    for (int j = 0; j <= jmax; j++) {
        if (j < jmax) { CP_WAIT1(); } else { CP_WAIT0(); }
        __syncthreads();

        const bool active = (j * 64 <= qt * 128 + w * 16 + 15);
        if (active) {
            const uint32_t sb = sbase + (uint32_t)(j & 1) * KV_STAGE;
            const uint32_t aKh = sb, aKl = sb + KVT_B;
            const uint32_t aVh = sb + 2 * KVT_B;

            float c[8][4];
            #pragma unroll
            for (int nt = 0; nt < 8; nt++)
                #pragma unroll
                for (int e = 0; e < 4; e++) c[nt][e] = 0.f;

            #pragma unroll
            for (int t = 0; t < 4; t++) {
                uint32_t qhf[4], qlf[4];
                uint32_t qo = (uint32_t)((w * 16 + dr) * QPF + t * 16 + dka) * 2;
                LDSM_X4(qhf, aQh + qo);
                LDSM_X4(qlf, aQl + qo);
                #pragma unroll
                for (int p = 0; p < 4; p++) {
                    uint32_t kb[4], kl2[4];
                    uint32_t bo = (uint32_t)((p * 16 + dn) * QPF + t * 16 + dkb) * 2;
                    LDSM_X4(kb, aKh + bo);
                    LDSM_X4(kl2, aKl + bo);
                    #pragma unroll
                    for (int sub = 0; sub < 2; sub++) {
                        const int nt = 2 * p + sub;
                        MMA16816(c[nt], qhf, kb[sub * 2], kb[sub * 2 + 1]);
                        MMA16816(c[nt], qhf, kl2[sub * 2], kl2[sub * 2 + 1]);
                        MMA16816(c[nt], qlf, kb[sub * 2], kb[sub * 2 + 1]);
                    }
                }
            }

            if (j >= 2 * qt) {
                const int qa = qt * 128 + w * 16 + (l >> 2);
                const int kc0 = j * 64 + (l & 3) * 2;
                #pragma unroll
                for (int nt = 0; nt < 8; nt++) {
                    int col = kc0 + nt * 8;
                    if (col > qa)     c[nt][0] = -INFINITY;
                    if (col + 1 > qa) c[nt][1] = -INFINITY;
                    if (col > qa + 8)     c[nt][2] = -INFINITY;
                    if (col + 1 > qa + 8) c[nt][3] = -INFINITY;
                }
            }

            float ma = -INFINITY, mb = -INFINITY;
            #pragma unroll
            for (int nt = 0; nt < 8; nt++) {
                ma = fmaxf(ma, fmaxf(c[nt][0], c[nt][1]));
                mb = fmaxf(mb, fmaxf(c[nt][2], c[nt][3]));
            }
            ma = fmaxf(ma, __shfl_xor_sync(0xffffffffu, ma, 1));
            ma = fmaxf(ma, __shfl_xor_sync(0xffffffffu, ma, 2));
            mb = fmaxf(mb, __shfl_xor_sync(0xffffffffu, mb, 1));
            mb = fmaxf(mb, __shfl_xor_sync(0xffffffffu, mb, 2));
            float mna = fmaxf(m_a, ma), mnb = fmaxf(m_b, mb);
            float aa = __expf(m_a - mna), ab = __expf(m_b - mnb);
            float sa = 0.f, sb2 = 0.f;
            #pragma unroll
            for (int nt = 0; nt < 8; nt++) {
                c[nt][0] = __expf(c[nt][0] - mna);
                c[nt][1] = __expf(c[nt][1] - mna);
                c[nt][2] = __expf(c[nt][2] - mnb);
                c[nt][3] = __expf(c[nt][3] - mnb);
                sa += c[nt][0] + c[nt][1];
                sb2 += c[nt][2] + c[nt][3];
            }
            sa += __shfl_xor_sync(0xffffffffu, sa, 1);
            sa += __shfl_xor_sync(0xffffffffu, sa, 2);
            sb2 += __shfl_xor_sync(0xffffffffu, sb2, 1);
            sb2 += __shfl_xor_sync(0xffffffffu, sb2, 2);
            l_a = l_a * aa + sa;
            l_b = l_b * ab + sb2;
            m_a = mna; m_b = mnb;
            #pragma unroll
            for (int nt = 0; nt < 8; nt++) {
                o[nt][0] *= aa; o[nt][1] *= aa;
                o[nt][2] *= ab; o[nt][3] *= ab;
            }

            #pragma unroll
            for (int t = 0; t < 4; t++) {
                uint32_t pa[4];
                pa[0] = packh2(c[2 * t][0],     c[2 * t][1]);
                pa[1] = packh2(c[2 * t][2],     c[2 * t][3]);
                pa[2] = packh2(c[2 * t + 1][0], c[2 * t + 1][1]);
                pa[3] = packh2(c[2 * t + 1][2], c[2 * t + 1][3]);
                #pragma unroll
                for (int p = 0; p < 4; p++) {
                    uint32_t vb[4];
                    uint32_t vo = (uint32_t)((t * 16 + (mat & 1) * 8 + (l & 7)) * QPF
                                             + p * 16 + (mat >> 1) * 8) * 2;
                    LDSM_X4_T(vb, aVh + vo);
                    MMA16816H(o[2 * p],     pa, vb[0], vb[1]);
                    MMA16816H(o[2 * p + 1], pa, vb[2], vb[3]);
                }
            }
        }
        __syncthreads();
        if (j + 2 <= jmax) {
            flash_issue(sbase + (uint32_t)(j & 1) * KV_STAGE,
                        kh_c, kl_c, vh_c, (size_t)(j + 2) * 8192, tid);
            CP_COMMIT();
        }
    }

    // Epilogue: tf32-rounded fp32 attn output (A operand of out-proj)
    const float ia = 1.f / l_a, ib = 1.f / l_b;
    const int row = (b * TT + qt * 128 + w * 16 + (l >> 2));
    const int col = h * 64 + (l & 3) * 2;
    #pragma unroll
    for (int nt = 0; nt < 8; nt++) {
        float2 w0 = { cvt_tf32(o[nt][0] * ia), cvt_tf32(o[nt][1] * ia) };
        float2 w1 = { cvt_tf32(o[nt][2] * ib), cvt_tf32(o[nt][3] * ib) };
        *(float2*)(o32 + (size_t)row * DA + col + nt * 8) = w0;
        *(float2*)(o32 + (size_t)(row + 8) * DA + col + nt * 8) = w1;
    }
}

// ---------------------------------------------------------------------------
// Launch
// ---------------------------------------------------------------------------
extern "C" void kernel_launch(void* const* d_in, const int* in_sizes, int n_in,
                              void* d_out, int out_size)
{
    const float* x    = (const float*)d_in[0];
    const float* Wqkv = (const float*)d_in[2];
    const float* bqkv = (const float*)d_in[3];
    const float* Wout = (const float*)d_in[4];
    const float* bout = (const float*)d_in[5];
    float* out = (float*)d_out;

    float *a32, *b32;
    __nv_bfloat16 *qh, *ql, *kh, *kl;
    __half *vh;
    cudaGetSymbolAddress((void**)&a32, g_a32);
    cudaGetSymbolAddress((void**)&b32, g_b32);
    cudaGetSymbolAddress((void**)&qh, g_qh);
    cudaGetSymbolAddress((void**)&ql, g_ql);
    cudaGetSymbolAddress((void**)&kh, g_kh);
    cudaGetSymbolAddress((void**)&kl, g_kl);
    cudaGetSymbolAddress((void**)&vh, g_vh);

    cudaFuncSetAttribute(gemm_mma,
                         cudaFuncAttributeMaxDynamicSharedMemorySize, (int)GEMM_DYN);
    cudaFuncSetAttribute(gemm_qkv,
                         cudaFuncAttributeMaxDynamicSharedMemorySize, (int)GEMM_DYN);
    cudaFuncSetAttribute(flash_mma,
                         cudaFuncAttributeMaxDynamicSharedMemorySize, (int)FL_DYN);

    // Phase 1: QKV = x @ Wqkv + b (tf32), fused split epilogue
    round_tf32<<<(MM * CCH / 4 + 255) / 256, 256>>>(x, a32, MM * CCH / 4);
    transpose_tf32<<<dim3(3 * DA / 32, CCH / 32), dim3(32, 8)>>>(Wqkv, b32, CCH, 3 * DA);
    gemm_qkv<<<dim3(3 * DA / 128, MM / 128), 512, GEMM_DYN>>>(
        a32, b32, bqkv, qh, ql, kh, kl, vh);

    // Phase 2: tensor-core flash (writes tf32 attn to a32)
    flash_mma<<<dim3(TT / 128, NH, BV), 256, FL_DYN>>>(
        qh, ql, kh, kl, vh, a32);

    // Phase 3: out = attn @ Wout + b (tf32)
    transpose_tf32<<<dim3(CCH / 32, DA / 32), dim3(32, 8)>>>(Wout, b32, DA, CCH);
    gemm_mma<<<dim3(CCH / 128, MM / 128), 512, GEMM_DYN>>>(
        a32, b32, bout, out, MM, CCH, DA);
}

// round 13
// speedup vs baseline: 5.3381x; 1.0818x over previous
#include <cuda_runtime.h>
#include <cuda_bf16.h>
#include <cuda_fp16.h>
#include <math.h>
#include <stdint.h>

// Problem constants
#define BV 4
#define TT 2048
#define CCH 1024
#define DA 1024
#define NH 16
#define HDM 64
#define MM (BV * TT)   // 8192 rows

// ---------------------------------------------------------------------------
// Device scratch (allocations forbidden; __device__ globals are sanctioned)
// ---------------------------------------------------------------------------
__device__ float g_a32[(size_t)MM * CCH];                 // activations (tf32)
__device__ float g_b32[(size_t)CCH * 3 * DA];             // W^T (tf32)
__device__ __nv_bfloat16 g_qh[(size_t)MM * DA];           // Q split (scaled)
__device__ __nv_bfloat16 g_ql[(size_t)MM * DA];
__device__ __nv_bfloat16 g_kh[(size_t)MM * DA];           // head-major K split
__device__ __nv_bfloat16 g_kl[(size_t)MM * DA];
__device__ __half        g_vh[(size_t)MM * DA];           // head-major V (fp16)

__device__ __forceinline__ uint32_t smem_u32(const void* p) {
    uint32_t a;
    asm("{ .reg .u64 t; cvta.to.shared.u64 t, %1; cvt.u32.u64 %0, t; }"
        : "=r"(a) : "l"(p));
    return a;
}
__device__ __forceinline__ float cvt_tf32(float x) {
    uint32_t r;
    asm("cvt.rna.tf32.f32 %0, %1;" : "=r"(r) : "f"(x));
    return __uint_as_float(r);
}

#define LDSM_X4(r, addr) \
    asm volatile("ldmatrix.sync.aligned.m8n8.x4.shared.b16 {%0,%1,%2,%3}, [%4];" \
        : "=r"((r)[0]), "=r"((r)[1]), "=r"((r)[2]), "=r"((r)[3]) : "r"(addr))

#define LDSM_X4_T(r, addr) \
    asm volatile("ldmatrix.sync.aligned.m8n8.x4.trans.shared.b16 {%0,%1,%2,%3}, [%4];" \
        : "=r"((r)[0]), "=r"((r)[1]), "=r"((r)[2]), "=r"((r)[3]) : "r"(addr))

#define MMA16816(c, a, b0, b1) \
    asm volatile("mma.sync.aligned.m16n8k16.row.col.f32.bf16.bf16.f32 " \
        "{%0,%1,%2,%3}, {%4,%5,%6,%7}, {%8,%9}, {%0,%1,%2,%3};" \
        : "+f"((c)[0]), "+f"((c)[1]), "+f"((c)[2]), "+f"((c)[3]) \
        : "r"((a)[0]), "r"((a)[1]), "r"((a)[2]), "r"((a)[3]), "r"(b0), "r"(b1))

#define MMA16816H(c, a, b0, b1) \
    asm volatile("mma.sync.aligned.m16n8k16.row.col.f32.f16.f16.f32 " \
        "{%0,%1,%2,%3}, {%4,%5,%6,%7}, {%8,%9}, {%0,%1,%2,%3};" \
        : "+f"((c)[0]), "+f"((c)[1]), "+f"((c)[2]), "+f"((c)[3]) \
        : "r"((a)[0]), "r"((a)[1]), "r"((a)[2]), "r"((a)[3]), "r"(b0), "r"(b1))

#define MMA168T(c, a, b0, b1) \
    asm volatile("mma.sync.aligned.m16n8k8.row.col.f32.tf32.tf32.f32 " \
        "{%0,%1,%2,%3}, {%4,%5,%6,%7}, {%8,%9}, {%0,%1,%2,%3};" \
        : "+f"((c)[0]), "+f"((c)[1]), "+f"((c)[2]), "+f"((c)[3]) \
        : "r"((a)[0]), "r"((a)[1]), "r"((a)[2]), "r"((a)[3]), "r"(b0), "r"(b1))

#define CP_A16(dst, src) \
    asm volatile("cp.async.cg.shared.global [%0], [%1], 16;" \
                 :: "r"(dst), "l"(src) : "memory")
#define CP_COMMIT() asm volatile("cp.async.commit_group;" ::: "memory")
#define CP_WAIT2()  asm volatile("cp.async.wait_group 2;" ::: "memory")
#define CP_WAIT1()  asm volatile("cp.async.wait_group 1;" ::: "memory")
#define CP_WAIT0()  asm volatile("cp.async.wait_group 0;" ::: "memory")

__device__ __forceinline__ uint32_t packh2(float a, float b) {
    __half2 h = __floats2half2_rn(a, b);
    return *(uint32_t*)&h;
}

// ---------------------------------------------------------------------------
// round_tf32: fp32 -> tf32-rounded fp32 (input x)
// ---------------------------------------------------------------------------
__global__ void round_tf32(const float* __restrict__ src,
                           float* __restrict__ dst, int n4)
{
    int i = blockIdx.x * blockDim.x + threadIdx.x;
    if (i >= n4) return;
    float4 v = ((const float4*)src)[i];
    v.x = cvt_tf32(v.x); v.y = cvt_tf32(v.y);
    v.z = cvt_tf32(v.z); v.w = cvt_tf32(v.w);
    ((float4*)dst)[i] = v;
}

// W[K][N] -> T[N][K] tf32-rounded. 32x32 smem-tiled transpose.
__global__ void transpose_tf32(const float* __restrict__ W,
                               float* __restrict__ T, int K, int N)
{
    __shared__ float tile[32][33];
    int tx = threadIdx.x, ty = threadIdx.y;
    int n0 = blockIdx.x * 32, k0 = blockIdx.y * 32;
    #pragma unroll
    for (int j = 0; j < 32; j += 8)
        tile[ty + j][tx] = W[(size_t)(k0 + ty + j) * N + n0 + tx];
    __syncthreads();
    #pragma unroll
    for (int j = 0; j < 32; j += 8)
        T[(size_t)(n0 + ty + j) * K + k0 + tx] = cvt_tf32(tile[tx][ty + j]);
}

// ---------------------------------------------------------------------------
// tf32 GEMM mainloop: CTA 128x128, 256 threads (8 warps, 2x4 grid, 64x32
// warp tile), KC=32, 3-stage cp.async, 2 CTAs/SM.
// Smem pitch 36 fp32 (144 B rows) -> conflict-free ldmatrix phases.
// ---------------------------------------------------------------------------
#define KC 32
#define P4 36
#define MAT4_B (128 * P4 * 4)               // 18432 B
#define STG4_B (2 * MAT4_B)                 // 36864 B (A32, B32)
#define GEMM_DYN (3 * STG4_B)               // 110592 B  (x2 CTAs = 216 KB/SM)

static __device__ __forceinline__ void gemm_issue4(
    uint32_t stage, const char* a, const char* b, int Kb, int k0b, int tid)
{
    const char* srcs[2] = {a, b};
    #pragma unroll
    for (int i = 0; i < 8; i++) {
        int idx = i * 256 + tid;
        int arr = idx >> 10, rem = idx & 1023;
        int row = rem >> 3, c = rem & 7;
        CP_A16(stage + arr * MAT4_B + row * (P4 * 4) + c * 16,
               srcs[arr] + (size_t)row * Kb + k0b + c * 16);
    }
}

// Computes acc[4][4][4] for this CTA tile (tf32 single product).
// Lane helpers: mat = l>>3, lr = (mat&1)*8 + (l&7), lc = (mat>>1)*4.
#define GEMM_MAINLOOP(A32, B32, K)                                            \
    const uint32_t sbase = smem_u32(dyn);                                     \
    const int NCH = (K) / KC;                                                 \
    const int Kb = (K) * 4;                                                   \
    const char* ga = (const char*)((A32) + (size_t)arow0 * (K));              \
    const char* gb = (const char*)((B32) + (size_t)bcol0 * (K));              \
    gemm_issue4(sbase, ga, gb, Kb, 0, tid); CP_COMMIT();                      \
    gemm_issue4(sbase + STG4_B, ga, gb, Kb, KC * 4, tid); CP_COMMIT();        \
    for (int c = 0; c < NCH; c++) {                                           \
        if (c < NCH - 1) { CP_WAIT1(); } else { CP_WAIT0(); }                 \
        __syncthreads();                                                      \
        if (c + 2 < NCH) {                                                    \
            gemm_issue4(sbase + (uint32_t)((c + 2) % 3) * STG4_B,             \
                        ga, gb, Kb, (c + 2) * KC * 4, tid);                   \
            CP_COMMIT();                                                      \
        }                                                                     \
        const uint32_t aA = sbase + (uint32_t)(c % 3) * STG4_B;               \
        const uint32_t aB = aA + MAT4_B;                                      \
        _Pragma("unroll")                                                     \
        for (int ks = 0; ks < KC / 8; ks++) {                                 \
            const int k0 = ks * 8;                                            \
            uint32_t af[4][4], bf[2][4];                                      \
            _Pragma("unroll")                                                 \
            for (int mt = 0; mt < 4; mt++) {                                  \
                uint32_t ao = (uint32_t)((warp_m * 64 + mt * 16 + lr) * P4    \
                                         + k0 + lc) * 4;                      \
                LDSM_X4(af[mt], aA + ao);                                     \
            }                                                                 \
            _Pragma("unroll")                                                 \
            for (int pr = 0; pr < 2; pr++) {                                  \
                uint32_t bo = (uint32_t)((warp_n * 32 + pr * 16 + lr) * P4    \
                                         + k0 + lc) * 4;                      \
                LDSM_X4(bf[pr], aB + bo);                                     \
            }                                                                 \
            _Pragma("unroll")                                                 \
            for (int mt = 0; mt < 4; mt++)                                    \
                _Pragma("unroll")                                             \
                for (int nt = 0; nt < 4; nt++) {                              \
                    const int pr = nt >> 1, od = nt & 1;                      \
                    MMA168T(acc[mt][nt], af[mt], bf[pr][od], bf[pr][od + 2]); \
                }                                                             \
        }                                                                     \
    }

// ---------------------------------------------------------------------------
// gemm_mma: generic fp32 output + bias (output projection)
// ---------------------------------------------------------------------------
__global__ __launch_bounds__(256, 2) void gemm_mma(
    const float* __restrict__ A32, const float* __restrict__ B32,
    const float* __restrict__ bias, float* __restrict__ C,
    int M, int N, int K)
{
    extern __shared__ char dyn[];
    const int tid = threadIdx.x;
    const int wid = tid >> 5, l = tid & 31;
    const int warp_m = wid & 1, warp_n = wid >> 1;     // 2 x 4 warp grid
    const int bc = blockIdx.x, br = blockIdx.y;
    const int arow0 = br * 128, bcol0 = bc * 128;

    const int mat = l >> 3;
    const int lr = (mat & 1) * 8 + (l & 7);
    const int lc = (mat >> 1) * 4;

    float acc[4][4][4];
    #pragma unroll
    for (int i = 0; i < 4; i++)
        #pragma unroll
        for (int j = 0; j < 4; j++)
            #pragma unroll
            for (int q = 0; q < 4; q++) acc[i][j][q] = 0.f;

    GEMM_MAINLOOP(A32, B32, K)

    const int rbase = arow0 + warp_m * 64 + (l >> 2);
    const int cbase = bcol0 + warp_n * 32 + (l & 3) * 2;
    #pragma unroll
    for (int mt = 0; mt < 4; mt++)
        #pragma unroll
        for (int nt = 0; nt < 4; nt++) {
            const int row = rbase + mt * 16;
            const int col = cbase + nt * 8;
            float2 v0, v1;
            v0.x = acc[mt][nt][0] + bias[col];
            v0.y = acc[mt][nt][1] + bias[col + 1];
            v1.x = acc[mt][nt][2] + bias[col];
            v1.y = acc[mt][nt][3] + bias[col + 1];
            *(float2*)(C + (size_t)row * N + col) = v0;
            *(float2*)(C + (size_t)(row + 8) * N + col) = v1;
        }
}

// ---------------------------------------------------------------------------
// gemm_qkv: QKV projection with fused split epilogue (Q/K/V consumer formats)
// ---------------------------------------------------------------------------
__global__ __launch_bounds__(256, 2) void gemm_qkv(
    const float* __restrict__ A32, const float* __restrict__ B32,
    const float* __restrict__ bias,
    __nv_bfloat16* __restrict__ qh, __nv_bfloat16* __restrict__ ql,
    __nv_bfloat16* __restrict__ kh, __nv_bfloat16* __restrict__ kl,
    __half* __restrict__ vh)
{
    extern __shared__ char dyn[];
    const int tid = threadIdx.x;
    const int wid = tid >> 5, l = tid & 31;
    const int warp_m = wid & 1, warp_n = wid >> 1;
    const int bc = blockIdx.x, br = blockIdx.y;
    const int arow0 = br * 128, bcol0 = bc * 128;
    const int K = CCH;

    const int mat = l >> 3;
    const int lr = (mat & 1) * 8 + (l & 7);
    const int lc = (mat >> 1) * 4;

    float acc[4][4][4];
    #pragma unroll
    for (int i = 0; i < 4; i++)
        #pragma unroll
        for (int j = 0; j < 4; j++)
            #pragma unroll
            for (int q = 0; q < 4; q++) acc[i][j][q] = 0.f;

    GEMM_MAINLOOP(A32, B32, K)

    const int rbase = arow0 + warp_m * 64 + (l >> 2);
    const int cbase = bcol0 + warp_n * 32 + (l & 3) * 2;
    #pragma unroll
    for (int mt = 0; mt < 4; mt++)
        #pragma unroll
        for (int nt = 0; nt < 4; nt++) {
            #pragma unroll
            for (int half2i = 0; half2i < 2; half2i++) {
                const int row = rbase + mt * 16 + half2i * 8;
                const int col = cbase + nt * 8;
                float v0 = acc[mt][nt][half2i * 2 + 0] + bias[col];
                float v1 = acc[mt][nt][half2i * 2 + 1] + bias[col + 1];
                if (bc < 8) {
                    v0 *= 0.125f; v1 *= 0.125f;
                    __nv_bfloat16 h0 = __float2bfloat16(v0);
                    __nv_bfloat16 h1 = __float2bfloat16(v1);
                    size_t o = (size_t)row * DA + col;
                    *(__nv_bfloat162*)(qh + o) = __nv_bfloat162(h0, h1);
                    *(__nv_bfloat162*)(ql + o) = __nv_bfloat162(
                        __float2bfloat16(v0 - __bfloat162float(h0)),
                        __float2bfloat16(v1 - __bfloat162float(h1)));
                } else {
                    const int cg = col - (bc < 16 ? 1024 : 2048);
                    const int head = cg >> 6, d = cg & 63;
                    const int t = row & (TT - 1), bb = row >> 11;
                    size_t o = ((size_t)(bb * NH + head) * TT + t) * 64 + d;
                    if (bc < 16) {
                        __nv_bfloat16 h0 = __float2bfloat16(v0);
                        __nv_bfloat16 h1 = __float2bfloat16(v1);
                        *(__nv_bfloat162*)(kh + o) = __nv_bfloat162(h0, h1);
                        *(__nv_bfloat162*)(kl + o) = __nv_bfloat162(
                            __float2bfloat16(v0 - __bfloat162float(h0)),
                            __float2bfloat16(v1 - __bfloat162float(h1)));
                    } else {
                        *(__half2*)(vh + o) =
                            __half2(__float2half_rn(v0), __float2half_rn(v1));
                    }
                }
            }
        }
}

// ---------------------------------------------------------------------------
// Tensor-core flash attention v6 (causal) — unchanged from round 12.
// ---------------------------------------------------------------------------
#define QPF 72
#define KVT_B (64 * QPF * 2)
#define KV_STAGE (3 * KVT_B)
#define Q_OFF (2 * KV_STAGE)
#define QARR_B (128 * QPF * 2)
#define FL_DYN (2 * KV_STAGE + 2 * QARR_B)   // 92160 B

static __device__ __forceinline__ void flash_issue(
    uint32_t stage, const char* kh, const char* kl,
    const char* vh, size_t tile_off, int tid)
{
    const char* srcs[3] = {kh + tile_off, kl + tile_off, vh + tile_off};
    #pragma unroll
    for (int i = 0; i < 6; i++) {
        int idx = i * 256 + tid;
        int arr = idx >> 9, rem = idx & 511;
        int r = rem >> 3, c = rem & 7;
        CP_A16(stage + arr * KVT_B + r * (QPF * 2) + c * 16,
               srcs[arr] + r * 128 + c * 16);
    }
}

__global__ __launch_bounds__(256, 2) void flash_mma(
    const __nv_bfloat16* __restrict__ qh_g, const __nv_bfloat16* __restrict__ ql_g,
    const __nv_bfloat16* __restrict__ kh_g, const __nv_bfloat16* __restrict__ kl_g,
    const __half* __restrict__ vh_g, float* __restrict__ o32)
{
    extern __shared__ char fsm[];
    const int tid = threadIdx.x;
    const int w = tid >> 5, l = tid & 31;
    const int qt = (int)gridDim.x - 1 - (int)blockIdx.x;
    const int h = blockIdx.y, b = blockIdx.z;

    const uint32_t sbase = smem_u32(fsm);
    const size_t headoff = ((size_t)(b * NH + h) * TT) * 64 * 2;
    const char* kh_c = (const char*)kh_g + headoff;
    const char* kl_c = (const char*)kl_g + headoff;
    const char* vh_c = (const char*)vh_g + headoff;
    const int jmax = 2 * qt + 1;

    {
        const char* q0 = (const char*)qh_g
            + ((size_t)(b * TT + qt * 128) * DA + h * 64) * 2;
        const char* q1 = (const char*)ql_g
            + ((size_t)(b * TT + qt * 128) * DA + h * 64) * 2;
        const char* srcs[2] = {q0, q1};
        #pragma unroll
        for (int i = 0; i < 8; i++) {
            int idx = i * 256 + tid;
            int arr = idx >> 10, rem = idx & 1023;
            int r = rem >> 3, c = rem & 7;
            CP_A16(sbase + Q_OFF + arr * QARR_B + r * (QPF * 2) + c * 16,
                   srcs[arr] + (size_t)r * (DA * 2) + c * 16);
        }
    }
    CP_COMMIT();
    flash_issue(sbase, kh_c, kl_c, vh_c, 0, tid);
    CP_COMMIT();
    flash_issue(sbase + KV_STAGE, kh_c, kl_c, vh_c, 8192, tid);
    CP_COMMIT();
    CP_WAIT2();
    __syncthreads();

    const int mat = l >> 3;
    const int dr  = (mat & 1) * 8 + (l & 7);
    const int dka = (mat >> 1) * 8;
    const int dn  = (mat >> 1) * 8 + (l & 7);
    const int dkb = (mat & 1) * 8;
    const uint32_t aQh = sbase + Q_OFF, aQl = aQh + QARR_B;

    float o[8][4];
    #pragma unroll
    for (int nt = 0; nt < 8; nt++)
        #pragma unroll
        for (int e = 0; e < 4; e++) o[nt][e] = 0.f;
    float m_a = -INFINITY, m_b = -INFINITY, l_a = 0.f, l_b = 0.f;

    for (int j = 0; j <= jmax; j++) {
        if (j < jmax) { CP_WAIT1(); } else { CP_WAIT0(); }
        __syncthreads();

        const bool active = (j * 64 <= qt * 128 + w * 16 + 15);
        if (active) {
            const uint32_t sb = sbase + (uint32_t)(j & 1) * KV_STAGE;
            const uint32_t aKh = sb, aKl = sb + KVT_B;
            const uint32_t aVh = sb + 2 * KVT_B;

            float c[8][4];
            #pragma unroll
            for (int nt = 0; nt < 8; nt++)
                #pragma unroll
                for (int e = 0; e < 4; e++) c[nt][e] = 0.f;

            #pragma unroll
            for (int t = 0; t < 4; t++) {
                uint32_t qhf[4], qlf[4];
                uint32_t qo = (uint32_t)((w * 16 + dr) * QPF + t * 16 + dka) * 2;
                LDSM_X4(qhf, aQh + qo);
                LDSM_X4(qlf, aQl + qo);
                #pragma unroll
                for (int p = 0; p < 4; p++) {
                    uint32_t kb[4], kl2[4];
                    uint32_t bo = (uint32_t)((p * 16 + dn) * QPF + t * 16 + dkb) * 2;
                    LDSM_X4(kb, aKh + bo);
                    LDSM_X4(kl2, aKl + bo);
                    #pragma unroll
                    for (int sub = 0; sub < 2; sub++) {
                        const int nt = 2 * p + sub;
                        MMA16816(c[nt], qhf, kb[sub * 2], kb[sub * 2 + 1]);
                        MMA16816(c[nt], qhf, kl2[sub * 2], kl2[sub * 2 + 1]);
                        MMA16816(c[nt], qlf, kb[sub * 2], kb[sub * 2 + 1]);
                    }
                }
            }

            if (j >= 2 * qt) {
                const int qa = qt * 128 + w * 16 + (l >> 2);
                const int kc0 = j * 64 + (l & 3) * 2;
                #pragma unroll
                for (int nt = 0; nt < 8; nt++) {
                    int col = kc0 + nt * 8;
                    if (col > qa)     c[nt][0] = -INFINITY;
                    if (col + 1 > qa) c[nt][1] = -INFINITY;
                    if (col > qa + 8)     c[nt][2] = -INFINITY;
                    if (col + 1 > qa + 8) c[nt][3] = -INFINITY;
                }
            }

            float ma = -INFINITY, mb = -INFINITY;
            #pragma unroll
            for (int nt = 0; nt < 8; nt++) {
                ma = fmaxf(ma, fmaxf(c[nt][0], c[nt][1]));
                mb = fmaxf(mb, fmaxf(c[nt][2], c[nt][3]));
            }
            ma = fmaxf(ma, __shfl_xor_sync(0xffffffffu, ma, 1));
            ma = fmaxf(ma, __shfl_xor_sync(0xffffffffu, ma, 2));
            mb = fmaxf(mb, __shfl_xor_sync(0xffffffffu, mb, 1));
            mb = fmaxf(mb, __shfl_xor_sync(0xffffffffu, mb, 2));
            float mna = fmaxf(m_a, ma), mnb = fmaxf(m_b, mb);
            float aa = __expf(m_a - mna), ab = __expf(m_b - mnb);
            float sa = 0.f, sb2 = 0.f;
            #pragma unroll
            for (int nt = 0; nt < 8; nt++) {
                c[nt][0] = __expf(c[nt][0] - mna);
                c[nt][1] = __expf(c[nt][1] - mna);
                c[nt][2] = __expf(c[nt][2] - mnb);
                c[nt][3] = __expf(c[nt][3] - mnb);
                sa += c[nt][0] + c[nt][1];
                sb2 += c[nt][2] + c[nt][3];
            }
            sa += __shfl_xor_sync(0xffffffffu, sa, 1);
            sa += __shfl_xor_sync(0xffffffffu, sa, 2);
            sb2 += __shfl_xor_sync(0xffffffffu, sb2, 1);
            sb2 += __shfl_xor_sync(0xffffffffu, sb2, 2);
            l_a = l_a * aa + sa;
            l_b = l_b * ab + sb2;
            m_a = mna; m_b = mnb;
            #pragma unroll
            for (int nt = 0; nt < 8; nt++) {
                o[nt][0] *= aa; o[nt][1] *= aa;
                o[nt][2] *= ab; o[nt][3] *= ab;
            }

            #pragma unroll
            for (int t = 0; t < 4; t++) {
                uint32_t pa[4];
                pa[0] = packh2(c[2 * t][0],     c[2 * t][1]);
                pa[1] = packh2(c[2 * t][2],     c[2 * t][3]);
                pa[2] = packh2(c[2 * t + 1][0], c[2 * t + 1][1]);
                pa[3] = packh2(c[2 * t + 1][2], c[2 * t + 1][3]);
                #pragma unroll
                for (int p = 0; p < 4; p++) {
                    uint32_t vb[4];
                    uint32_t vo = (uint32_t)((t * 16 + (mat & 1) * 8 + (l & 7)) * QPF
                                             + p * 16 + (mat >> 1) * 8) * 2;
                    LDSM_X4_T(vb, aVh + vo);
                    MMA16816H(o[2 * p],     pa, vb[0], vb[1]);
                    MMA16816H(o[2 * p + 1], pa, vb[2], vb[3]);
                }
            }
        }
        __syncthreads();
        if (j + 2 <= jmax) {
            flash_issue(sbase + (uint32_t)(j & 1) * KV_STAGE,
                        kh_c, kl_c, vh_c, (size_t)(j + 2) * 8192, tid);
            CP_COMMIT();
        }
    }

    // Epilogue: tf32-rounded fp32 attn output (A operand of out-proj)
    const float ia = 1.f / l_a, ib = 1.f / l_b;
    const int row = (b * TT + qt * 128 + w * 16 + (l >> 2));
    const int col = h * 64 + (l & 3) * 2;
    #pragma unroll
    for (int nt = 0; nt < 8; nt++) {
        float2 w0 = { cvt_tf32(o[nt][0] * ia), cvt_tf32(o[nt][1] * ia) };
        float2 w1 = { cvt_tf32(o[nt][2] * ib), cvt_tf32(o[nt][3] * ib) };
        *(float2*)(o32 + (size_t)row * DA + col + nt * 8) = w0;
        *(float2*)(o32 + (size_t)(row + 8) * DA + col + nt * 8) = w1;
    }
}

// ---------------------------------------------------------------------------
// Launch
// ---------------------------------------------------------------------------
extern "C" void kernel_launch(void* const* d_in, const int* in_sizes, int n_in,
                              void* d_out, int out_size)
{
    const float* x    = (const float*)d_in[0];
    const float* Wqkv = (const float*)d_in[2];
    const float* bqkv = (const float*)d_in[3];
    const float* Wout = (const float*)d_in[4];
    const float* bout = (const float*)d_in[5];
    float* out = (float*)d_out;

    float *a32, *b32;
    __nv_bfloat16 *qh, *ql, *kh, *kl;
    __half *vh;
    cudaGetSymbolAddress((void**)&a32, g_a32);
    cudaGetSymbolAddress((void**)&b32, g_b32);
    cudaGetSymbolAddress((void**)&qh, g_qh);
    cudaGetSymbolAddress((void**)&ql, g_ql);
    cudaGetSymbolAddress((void**)&kh, g_kh);
    cudaGetSymbolAddress((void**)&kl, g_kl);
    cudaGetSymbolAddress((void**)&vh, g_vh);

    cudaFuncSetAttribute(gemm_mma,
                         cudaFuncAttributeMaxDynamicSharedMemorySize, (int)GEMM_DYN);
    cudaFuncSetAttribute(gemm_qkv,
                         cudaFuncAttributeMaxDynamicSharedMemorySize, (int)GEMM_DYN);
    cudaFuncSetAttribute(flash_mma,
                         cudaFuncAttributeMaxDynamicSharedMemorySize, (int)FL_DYN);

    // Phase 1: QKV = x @ Wqkv + b (tf32), fused split epilogue
    round_tf32<<<(MM * CCH / 4 + 255) / 256, 256>>>(x, a32, MM * CCH / 4);
    transpose_tf32<<<dim3(3 * DA / 32, CCH / 32), dim3(32, 8)>>>(Wqkv, b32, CCH, 3 * DA);
    gemm_qkv<<<dim3(3 * DA / 128, MM / 128), 256, GEMM_DYN>>>(
        a32, b32, bqkv, qh, ql, kh, kl, vh);

    // Phase 2: tensor-core flash (writes tf32 attn to a32)
    flash_mma<<<dim3(TT / 128, NH, BV), 256, FL_DYN>>>(
        qh, ql, kh, kl, vh, a32);

    // Phase 3: out = attn @ Wout + b (tf32)
    transpose_tf32<<<dim3(CCH / 32, DA / 32), dim3(32, 8)>>>(Wout, b32, DA, CCH);
    gemm_mma<<<dim3(CCH / 128, MM / 128), 256, GEMM_DYN>>>(
        a32, b32, bout, out, MM, CCH, DA);
}

// round 14
// speedup vs baseline: 8.2310x; 1.5419x over previous
#include <cuda_runtime.h>
#include <cuda_bf16.h>
#include <cuda_fp16.h>
#include <math.h>
#include <stdint.h>

// Problem constants
#define BV 4
#define TT 2048
#define CCH 1024
#define DA 1024
#define NH 16
#define HDM 64
#define MM (BV * TT)   // 8192 rows

// ---------------------------------------------------------------------------
// Device scratch (allocations forbidden; __device__ globals are sanctioned)
// ---------------------------------------------------------------------------
__device__ __half g_a16[(size_t)MM * CCH];                // activations (fp16)
__device__ __half g_b16[(size_t)CCH * 3 * DA];            // W^T (fp16)
__device__ __nv_bfloat16 g_qh[(size_t)MM * DA];           // Q split (scaled)
__device__ __nv_bfloat16 g_ql[(size_t)MM * DA];
__device__ __nv_bfloat16 g_kh[(size_t)MM * DA];           // head-major K split
__device__ __nv_bfloat16 g_kl[(size_t)MM * DA];
__device__ __half        g_vh[(size_t)MM * DA];           // head-major V (fp16)

__device__ __forceinline__ uint32_t smem_u32(const void* p) {
    uint32_t a;
    asm("{ .reg .u64 t; cvta.to.shared.u64 t, %1; cvt.u32.u64 %0, t; }"
        : "=r"(a) : "l"(p));
    return a;
}

#define LDSM_X4(r, addr) \
    asm volatile("ldmatrix.sync.aligned.m8n8.x4.shared.b16 {%0,%1,%2,%3}, [%4];" \
        : "=r"((r)[0]), "=r"((r)[1]), "=r"((r)[2]), "=r"((r)[3]) : "r"(addr))

#define LDSM_X4_T(r, addr) \
    asm volatile("ldmatrix.sync.aligned.m8n8.x4.trans.shared.b16 {%0,%1,%2,%3}, [%4];" \
        : "=r"((r)[0]), "=r"((r)[1]), "=r"((r)[2]), "=r"((r)[3]) : "r"(addr))

#define MMA16816(c, a, b0, b1) \
    asm volatile("mma.sync.aligned.m16n8k16.row.col.f32.bf16.bf16.f32 " \
        "{%0,%1,%2,%3}, {%4,%5,%6,%7}, {%8,%9}, {%0,%1,%2,%3};" \
        : "+f"((c)[0]), "+f"((c)[1]), "+f"((c)[2]), "+f"((c)[3]) \
        : "r"((a)[0]), "r"((a)[1]), "r"((a)[2]), "r"((a)[3]), "r"(b0), "r"(b1))

#define MMA16816H(c, a, b0, b1) \
    asm volatile("mma.sync.aligned.m16n8k16.row.col.f32.f16.f16.f32 " \
        "{%0,%1,%2,%3}, {%4,%5,%6,%7}, {%8,%9}, {%0,%1,%2,%3};" \
        : "+f"((c)[0]), "+f"((c)[1]), "+f"((c)[2]), "+f"((c)[3]) \
        : "r"((a)[0]), "r"((a)[1]), "r"((a)[2]), "r"((a)[3]), "r"(b0), "r"(b1))

#define CP_A16(dst, src) \
    asm volatile("cp.async.cg.shared.global [%0], [%1], 16;" \
                 :: "r"(dst), "l"(src) : "memory")
#define CP_COMMIT() asm volatile("cp.async.commit_group;" ::: "memory")
#define CP_WAIT2()  asm volatile("cp.async.wait_group 2;" ::: "memory")
#define CP_WAIT1()  asm volatile("cp.async.wait_group 1;" ::: "memory")
#define CP_WAIT0()  asm volatile("cp.async.wait_group 0;" ::: "memory")

__device__ __forceinline__ uint32_t packh2(float a, float b) {
    __half2 h = __floats2half2_rn(a, b);
    return *(uint32_t*)&h;
}

// ---------------------------------------------------------------------------
// conv_f16: fp32 -> fp16 (input x)
// ---------------------------------------------------------------------------
__global__ void conv_f16(const float* __restrict__ src,
                         __half* __restrict__ dst, int n4)
{
    int i = blockIdx.x * blockDim.x + threadIdx.x;
    if (i >= n4) return;
    float4 v = ((const float4*)src)[i];
    ((__half2*)dst)[2 * i]     = __floats2half2_rn(v.x, v.y);
    ((__half2*)dst)[2 * i + 1] = __floats2half2_rn(v.z, v.w);
}

// W[K][N] -> T[N][K] fp16. 32x32 smem-tiled transpose.
__global__ void transpose_f16(const float* __restrict__ W,
                              __half* __restrict__ T, int K, int N)
{
    __shared__ float tile[32][33];
    int tx = threadIdx.x, ty = threadIdx.y;
    int n0 = blockIdx.x * 32, k0 = blockIdx.y * 32;
    #pragma unroll
    for (int j = 0; j < 32; j += 8)
        tile[ty + j][tx] = W[(size_t)(k0 + ty + j) * N + n0 + tx];
    __syncthreads();
    #pragma unroll
    for (int j = 0; j < 32; j += 8)
        T[(size_t)(n0 + ty + j) * K + k0 + tx] = __float2half_rn(tile[tx][ty + j]);
}

// ---------------------------------------------------------------------------
// fp16 single-product GEMM mainloop: CTA 128x128, 256 threads (8 warps,
// 2x4 grid, 64x32 warp tile), KC=64, 3-stage cp.async, 2 CTAs/SM.
// Smem pitch 72 halfs (144 B rows) -> conflict-free ldmatrix phases.
// ---------------------------------------------------------------------------
#define KC 64
#define GP 72
#define GMAT_B (128 * GP * 2)               // 18432 B per matrix
#define GSTG_B (2 * GMAT_B)                 // 36864 B (A16, B16)
#define GEMM_DYN (3 * GSTG_B)               // 110592 B  (x2 CTAs = 216 KB/SM)

static __device__ __forceinline__ void gemm_issue(
    uint32_t stage, const char* a, const char* b, int Kb, int k0b, int tid)
{
    const char* srcs[2] = {a, b};
    #pragma unroll
    for (int i = 0; i < 8; i++) {
        int idx = i * 256 + tid;
        int arr = idx >> 10, rem = idx & 1023;
        int row = rem >> 3, c = rem & 7;
        CP_A16(stage + arr * GMAT_B + row * (GP * 2) + c * 16,
               srcs[arr] + (size_t)row * Kb + k0b + c * 16);
    }
}

// Computes acc[4][4][4] for this CTA tile (fp16 single product).
// Lane helpers: mat = l>>3, dr = (mat&1)*8+(l&7), dka = (mat>>1)*8,
//               dn = (mat>>1)*8+(l&7),  dkb = (mat&1)*8.
#define GEMM_MAINLOOP(A16, B16, K)                                            \
    const uint32_t sbase = smem_u32(dyn);                                     \
    const int NCH = (K) / KC;                                                 \
    const int Kb = (K) * 2;                                                   \
    const char* ga = (const char*)((A16) + (size_t)arow0 * (K));              \
    const char* gb = (const char*)((B16) + (size_t)bcol0 * (K));              \
    gemm_issue(sbase, ga, gb, Kb, 0, tid); CP_COMMIT();                       \
    gemm_issue(sbase + GSTG_B, ga, gb, Kb, KC * 2, tid); CP_COMMIT();         \
    for (int c = 0; c < NCH; c++) {                                           \
        if (c < NCH - 1) { CP_WAIT1(); } else { CP_WAIT0(); }                 \
        __syncthreads();                                                      \
        if (c + 2 < NCH) {                                                    \
            gemm_issue(sbase + (uint32_t)((c + 2) % 3) * GSTG_B,              \
                       ga, gb, Kb, (c + 2) * KC * 2, tid);                    \
            CP_COMMIT();                                                      \
        }                                                                     \
        const uint32_t aA = sbase + (uint32_t)(c % 3) * GSTG_B;               \
        const uint32_t aB = aA + GMAT_B;                                      \
        _Pragma("unroll")                                                     \
        for (int ks = 0; ks < KC / 16; ks++) {                                \
            const int k0 = ks * 16;                                           \
            uint32_t af[4][4], bf[2][4];                                      \
            _Pragma("unroll")                                                 \
            for (int mt = 0; mt < 4; mt++) {                                  \
                uint32_t ao = (uint32_t)((warp_m * 64 + mt * 16 + dr) * GP    \
                                         + k0 + dka) * 2;                     \
                LDSM_X4(af[mt], aA + ao);                                     \
            }                                                                 \
            _Pragma("unroll")                                                 \
            for (int pr = 0; pr < 2; pr++) {                                  \
                uint32_t bo = (uint32_t)((warp_n * 32 + pr * 16 + dn) * GP    \
                                         + k0 + dkb) * 2;                     \
                LDSM_X4(bf[pr], aB + bo);                                     \
            }                                                                 \
            _Pragma("unroll")                                                 \
            for (int mt = 0; mt < 4; mt++)                                    \
                _Pragma("unroll")                                             \
                for (int nt = 0; nt < 4; nt++) {                              \
                    const int pr = nt >> 1, sb2 = (nt & 1) * 2;               \
                    MMA16816H(acc[mt][nt], af[mt], bf[pr][sb2], bf[pr][sb2 + 1]); \
                }                                                             \
        }                                                                     \
    }

// ---------------------------------------------------------------------------
// gemm_mma: generic fp32 output + bias (output projection)
// ---------------------------------------------------------------------------
__global__ __launch_bounds__(256, 2) void gemm_mma(
    const __half* __restrict__ A16, const __half* __restrict__ B16,
    const float* __restrict__ bias, float* __restrict__ C,
    int M, int N, int K)
{
    extern __shared__ char dyn[];
    const int tid = threadIdx.x;
    const int wid = tid >> 5, l = tid & 31;
    const int warp_m = wid & 1, warp_n = wid >> 1;     // 2 x 4 warp grid
    const int bc = blockIdx.x, br = blockIdx.y;
    const int arow0 = br * 128, bcol0 = bc * 128;

    const int mat = l >> 3;
    const int dr  = (mat & 1) * 8 + (l & 7);
    const int dka = (mat >> 1) * 8;
    const int dn  = (mat >> 1) * 8 + (l & 7);
    const int dkb = (mat & 1) * 8;

    float acc[4][4][4];
    #pragma unroll
    for (int i = 0; i < 4; i++)
        #pragma unroll
        for (int j = 0; j < 4; j++)
            #pragma unroll
            for (int q = 0; q < 4; q++) acc[i][j][q] = 0.f;

    GEMM_MAINLOOP(A16, B16, K)

    const int rbase = arow0 + warp_m * 64 + (l >> 2);
    const int cbase = bcol0 + warp_n * 32 + (l & 3) * 2;
    #pragma unroll
    for (int mt = 0; mt < 4; mt++)
        #pragma unroll
        for (int nt = 0; nt < 4; nt++) {
            const int row = rbase + mt * 16;
            const int col = cbase + nt * 8;
            float2 v0, v1;
            v0.x = acc[mt][nt][0] + bias[col];
            v0.y = acc[mt][nt][1] + bias[col + 1];
            v1.x = acc[mt][nt][2] + bias[col];
            v1.y = acc[mt][nt][3] + bias[col + 1];
            *(float2*)(C + (size_t)row * N + col) = v0;
            *(float2*)(C + (size_t)(row + 8) * N + col) = v1;
        }
}

// ---------------------------------------------------------------------------
// gemm_qkv: QKV projection with fused split epilogue (Q/K/V consumer formats)
// ---------------------------------------------------------------------------
__global__ __launch_bounds__(256, 2) void gemm_qkv(
    const __half* __restrict__ A16, const __half* __restrict__ B16,
    const float* __restrict__ bias,
    __nv_bfloat16* __restrict__ qh, __nv_bfloat16* __restrict__ ql,
    __nv_bfloat16* __restrict__ kh, __nv_bfloat16* __restrict__ kl,
    __half* __restrict__ vh)
{
    extern __shared__ char dyn[];
    const int tid = threadIdx.x;
    const int wid = tid >> 5, l = tid & 31;
    const int warp_m = wid & 1, warp_n = wid >> 1;
    const int bc = blockIdx.x, br = blockIdx.y;
    const int arow0 = br * 128, bcol0 = bc * 128;
    const int K = CCH;

    const int mat = l >> 3;
    const int dr  = (mat & 1) * 8 + (l & 7);
    const int dka = (mat >> 1) * 8;
    const int dn  = (mat >> 1) * 8 + (l & 7);
    const int dkb = (mat & 1) * 8;

    float acc[4][4][4];
    #pragma unroll
    for (int i = 0; i < 4; i++)
        #pragma unroll
        for (int j = 0; j < 4; j++)
            #pragma unroll
            for (int q = 0; q < 4; q++) acc[i][j][q] = 0.f;

    GEMM_MAINLOOP(A16, B16, K)

    const int rbase = arow0 + warp_m * 64 + (l >> 2);
    const int cbase = bcol0 + warp_n * 32 + (l & 3) * 2;
    #pragma unroll
    for (int mt = 0; mt < 4; mt++)
        #pragma unroll
        for (int nt = 0; nt < 4; nt++) {
            #pragma unroll
            for (int half2i = 0; half2i < 2; half2i++) {
                const int row = rbase + mt * 16 + half2i * 8;
                const int col = cbase + nt * 8;
                float v0 = acc[mt][nt][half2i * 2 + 0] + bias[col];
                float v1 = acc[mt][nt][half2i * 2 + 1] + bias[col + 1];
                if (bc < 8) {
                    v0 *= 0.125f; v1 *= 0.125f;
                    __nv_bfloat16 h0 = __float2bfloat16(v0);
                    __nv_bfloat16 h1 = __float2bfloat16(v1);
                    size_t o = (size_t)row * DA + col;
                    *(__nv_bfloat162*)(qh + o) = __nv_bfloat162(h0, h1);
                    *(__nv_bfloat162*)(ql + o) = __nv_bfloat162(
                        __float2bfloat16(v0 - __bfloat162float(h0)),
                        __float2bfloat16(v1 - __bfloat162float(h1)));
                } else {
                    const int cg = col - (bc < 16 ? 1024 : 2048);
                    const int head = cg >> 6, d = cg & 63;
                    const int t = row & (TT - 1), bb = row >> 11;
                    size_t o = ((size_t)(bb * NH + head) * TT + t) * 64 + d;
                    if (bc < 16) {
                        __nv_bfloat16 h0 = __float2bfloat16(v0);
                        __nv_bfloat16 h1 = __float2bfloat16(v1);
                        *(__nv_bfloat162*)(kh + o) = __nv_bfloat162(h0, h1);
                        *(__nv_bfloat162*)(kl + o) = __nv_bfloat162(
                            __float2bfloat16(v0 - __bfloat162float(h0)),
                            __float2bfloat16(v1 - __bfloat162float(h1)));
                    } else {
                        *(__half2*)(vh + o) =
                            __half2(__float2half_rn(v0), __float2half_rn(v1));
                    }
                }
            }
        }
}

// ---------------------------------------------------------------------------
// Tensor-core flash attention v6 (causal) — mainloop unchanged; epilogue
// writes fp16 attn output into a16 (out-proj A operand).
// ---------------------------------------------------------------------------
#define QPF 72
#define KVT_B (64 * QPF * 2)
#define KV_STAGE (3 * KVT_B)
#define Q_OFF (2 * KV_STAGE)
#define QARR_B (128 * QPF * 2)
#define FL_DYN (2 * KV_STAGE + 2 * QARR_B)   // 92160 B

static __device__ __forceinline__ void flash_issue(
    uint32_t stage, const char* kh, const char* kl,
    const char* vh, size_t tile_off, int tid)
{
    const char* srcs[3] = {kh + tile_off, kl + tile_off, vh + tile_off};
    #pragma unroll
    for (int i = 0; i < 6; i++) {
        int idx = i * 256 + tid;
        int arr = idx >> 9, rem = idx & 511;
        int r = rem >> 3, c = rem & 7;
        CP_A16(stage + arr * KVT_B + r * (QPF * 2) + c * 16,
               srcs[arr] + r * 128 + c * 16);
    }
}

__global__ __launch_bounds__(256, 2) void flash_mma(
    const __nv_bfloat16* __restrict__ qh_g, const __nv_bfloat16* __restrict__ ql_g,
    const __nv_bfloat16* __restrict__ kh_g, const __nv_bfloat16* __restrict__ kl_g,
    const __half* __restrict__ vh_g, __half* __restrict__ o16)
{
    extern __shared__ char fsm[];
    const int tid = threadIdx.x;
    const int w = tid >> 5, l = tid & 31;
    const int qt = (int)gridDim.x - 1 - (int)blockIdx.x;
    const int h = blockIdx.y, b = blockIdx.z;

    const uint32_t sbase = smem_u32(fsm);
    const size_t headoff = ((size_t)(b * NH + h) * TT) * 64 * 2;
    const char* kh_c = (const char*)kh_g + headoff;
    const char* kl_c = (const char*)kl_g + headoff;
    const char* vh_c = (const char*)vh_g + headoff;
    const int jmax = 2 * qt + 1;

    {
        const char* q0 = (const char*)qh_g
            + ((size_t)(b * TT + qt * 128) * DA + h * 64) * 2;
        const char* q1 = (const char*)ql_g
            + ((size_t)(b * TT + qt * 128) * DA + h * 64) * 2;
        const char* srcs[2] = {q0, q1};
        #pragma unroll
        for (int i = 0; i < 8; i++) {
            int idx = i * 256 + tid;
            int arr = idx >> 10, rem = idx & 1023;
            int r = rem >> 3, c = rem & 7;
            CP_A16(sbase + Q_OFF + arr * QARR_B + r * (QPF * 2) + c * 16,
                   srcs[arr] + (size_t)r * (DA * 2) + c * 16);
        }
    }
    CP_COMMIT();
    flash_issue(sbase, kh_c, kl_c, vh_c, 0, tid);
    CP_COMMIT();
    flash_issue(sbase + KV_STAGE, kh_c, kl_c, vh_c, 8192, tid);
    CP_COMMIT();
    CP_WAIT2();
    __syncthreads();

    const int mat = l >> 3;
    const int dr  = (mat & 1) * 8 + (l & 7);
    const int dka = (mat >> 1) * 8;
    const int dn  = (mat >> 1) * 8 + (l & 7);
    const int dkb = (mat & 1) * 8;
    const uint32_t aQh = sbase + Q_OFF, aQl = aQh + QARR_B;

    float o[8][4];
    #pragma unroll
    for (int nt = 0; nt < 8; nt++)
        #pragma unroll
        for (int e = 0; e < 4; e++) o[nt][e] = 0.f;
    float m_a = -INFINITY, m_b = -INFINITY, l_a = 0.f, l_b = 0.f;

    for (int j = 0; j <= jmax; j++) {
        if (j < jmax) { CP_WAIT1(); } else { CP_WAIT0(); }
        __syncthreads();

        const bool active = (j * 64 <= qt * 128 + w * 16 + 15);
        if (active) {
            const uint32_t sb = sbase + (uint32_t)(j & 1) * KV_STAGE;
            const uint32_t aKh = sb, aKl = sb + KVT_B;
            const uint32_t aVh = sb + 2 * KVT_B;

            float c[8][4];
            #pragma unroll
            for (int nt = 0; nt < 8; nt++)
                #pragma unroll
                for (int e = 0; e < 4; e++) c[nt][e] = 0.f;

            #pragma unroll
            for (int t = 0; t < 4; t++) {
                uint32_t qhf[4], qlf[4];
                uint32_t qo = (uint32_t)((w * 16 + dr) * QPF + t * 16 + dka) * 2;
                LDSM_X4(qhf, aQh + qo);
                LDSM_X4(qlf, aQl + qo);
                #pragma unroll
                for (int p = 0; p < 4; p++) {
                    uint32_t kb[4], kl2[4];
                    uint32_t bo = (uint32_t)((p * 16 + dn) * QPF + t * 16 + dkb) * 2;
                    LDSM_X4(kb, aKh + bo);
                    LDSM_X4(kl2, aKl + bo);
                    #pragma unroll
                    for (int sub = 0; sub < 2; sub++) {
                        const int nt = 2 * p + sub;
                        MMA16816(c[nt], qhf, kb[sub * 2], kb[sub * 2 + 1]);
                        MMA16816(c[nt], qhf, kl2[sub * 2], kl2[sub * 2 + 1]);
                        MMA16816(c[nt], qlf, kb[sub * 2], kb[sub * 2 + 1]);
                    }
                }
            }

            if (j >= 2 * qt) {
                const int qa = qt * 128 + w * 16 + (l >> 2);
                const int kc0 = j * 64 + (l & 3) * 2;
                #pragma unroll
                for (int nt = 0; nt < 8; nt++) {
                    int col = kc0 + nt * 8;
                    if (col > qa)     c[nt][0] = -INFINITY;
                    if (col + 1 > qa) c[nt][1] = -INFINITY;
                    if (col > qa + 8)     c[nt][2] = -INFINITY;
                    if (col + 1 > qa + 8) c[nt][3] = -INFINITY;
                }
            }

            float ma = -INFINITY, mb = -INFINITY;
            #pragma unroll
            for (int nt = 0; nt < 8; nt++) {
                ma = fmaxf(ma, fmaxf(c[nt][0], c[nt][1]));
                mb = fmaxf(mb, fmaxf(c[nt][2], c[nt][3]));
            }
            ma = fmaxf(ma, __shfl_xor_sync(0xffffffffu, ma, 1));
            ma = fmaxf(ma, __shfl_xor_sync(0xffffffffu, ma, 2));
            mb = fmaxf(mb, __shfl_xor_sync(0xffffffffu, mb, 1));
            mb = fmaxf(mb, __shfl_xor_sync(0xffffffffu, mb, 2));
            float mna = fmaxf(m_a, ma), mnb = fmaxf(m_b, mb);
            float aa = __expf(m_a - mna), ab = __expf(m_b - mnb);
            float sa = 0.f, sb2 = 0.f;
            #pragma unroll
            for (int nt = 0; nt < 8; nt++) {
                c[nt][0] = __expf(c[nt][0] - mna);
                c[nt][1] = __expf(c[nt][1] - mna);
                c[nt][2] = __expf(c[nt][2] - mnb);
                c[nt][3] = __expf(c[nt][3] - mnb);
                sa += c[nt][0] + c[nt][1];
                sb2 += c[nt][2] + c[nt][3];
            }
            sa += __shfl_xor_sync(0xffffffffu, sa, 1);
            sa += __shfl_xor_sync(0xffffffffu, sa, 2);
            sb2 += __shfl_xor_sync(0xffffffffu, sb2, 1);
            sb2 += __shfl_xor_sync(0xffffffffu, sb2, 2);
            l_a = l_a * aa + sa;
            l_b = l_b * ab + sb2;
            m_a = mna; m_b = mnb;
            #pragma unroll
            for (int nt = 0; nt < 8; nt++) {
                o[nt][0] *= aa; o[nt][1] *= aa;
                o[nt][2] *= ab; o[nt][3] *= ab;
            }

            #pragma unroll
            for (int t = 0; t < 4; t++) {
                uint32_t pa[4];
                pa[0] = packh2(c[2 * t][0],     c[2 * t][1]);
                pa[1] = packh2(c[2 * t][2],     c[2 * t][3]);
                pa[2] = packh2(c[2 * t + 1][0], c[2 * t + 1][1]);
                pa[3] = packh2(c[2 * t + 1][2], c[2 * t + 1][3]);
                #pragma unroll
                for (int p = 0; p < 4; p++) {
                    uint32_t vb[4];
                    uint32_t vo = (uint32_t)((t * 16 + (mat & 1) * 8 + (l & 7)) * QPF
                                             + p * 16 + (mat >> 1) * 8) * 2;
                    LDSM_X4_T(vb, aVh + vo);
                    MMA16816H(o[2 * p],     pa, vb[0], vb[1]);
                    MMA16816H(o[2 * p + 1], pa, vb[2], vb[3]);
                }
            }
        }
        __syncthreads();
        if (j + 2 <= jmax) {
            flash_issue(sbase + (uint32_t)(j & 1) * KV_STAGE,
                        kh_c, kl_c, vh_c, (size_t)(j + 2) * 8192, tid);
            CP_COMMIT();
        }
    }

    // Epilogue: fp16 attn output (A operand of out-proj)
    const float ia = 1.f / l_a, ib = 1.f / l_b;
    const int row = (b * TT + qt * 128 + w * 16 + (l >> 2));
    const int col = h * 64 + (l & 3) * 2;
    #pragma unroll
    for (int nt = 0; nt < 8; nt++) {
        *(__half2*)(o16 + (size_t)row * DA + col + nt * 8) =
            __floats2half2_rn(o[nt][0] * ia, o[nt][1] * ia);
        *(__half2*)(o16 + (size_t)(row + 8) * DA + col + nt * 8) =
            __floats2half2_rn(o[nt][2] * ib, o[nt][3] * ib);
    }
}

// ---------------------------------------------------------------------------
// Launch
// ---------------------------------------------------------------------------
extern "C" void kernel_launch(void* const* d_in, const int* in_sizes, int n_in,
                              void* d_out, int out_size)
{
    const float* x    = (const float*)d_in[0];
    const float* Wqkv = (const float*)d_in[2];
    const float* bqkv = (const float*)d_in[3];
    const float* Wout = (const float*)d_in[4];
    const float* bout = (const float*)d_in[5];
    float* out = (float*)d_out;

    __half *a16, *b16, *vh;
    __nv_bfloat16 *qh, *ql, *kh, *kl;
    cudaGetSymbolAddress((void**)&a16, g_a16);
    cudaGetSymbolAddress((void**)&b16, g_b16);
    cudaGetSymbolAddress((void**)&qh, g_qh);
    cudaGetSymbolAddress((void**)&ql, g_ql);
    cudaGetSymbolAddress((void**)&kh, g_kh);
    cudaGetSymbolAddress((void**)&kl, g_kl);
    cudaGetSymbolAddress((void**)&vh, g_vh);

    cudaFuncSetAttribute(gemm_mma,
                         cudaFuncAttributeMaxDynamicSharedMemorySize, (int)GEMM_DYN);
    cudaFuncSetAttribute(gemm_qkv,
                         cudaFuncAttributeMaxDynamicSharedMemorySize, (int)GEMM_DYN);
    cudaFuncSetAttribute(flash_mma,
                         cudaFuncAttributeMaxDynamicSharedMemorySize, (int)FL_DYN);

    // Phase 1: QKV = x @ Wqkv + b (fp16 operands), fused split epilogue
    conv_f16<<<(MM * CCH / 4 + 255) / 256, 256>>>(x, a16, MM * CCH / 4);
    transpose_f16<<<dim3(3 * DA / 32, CCH / 32), dim3(32, 8)>>>(Wqkv, b16, CCH, 3 * DA);
    gemm_qkv<<<dim3(3 * DA / 128, MM / 128), 256, GEMM_DYN>>>(
        a16, b16, bqkv, qh, ql, kh, kl, vh);

    // Phase 2: tensor-core flash (writes fp16 attn to a16)
    flash_mma<<<dim3(TT / 128, NH, BV), 256, FL_DYN>>>(
        qh, ql, kh, kl, vh, a16);

    // Phase 3: out = attn @ Wout + b (fp16 operands)
    transpose_f16<<<dim3(CCH / 32, DA / 32), dim3(32, 8)>>>(Wout, b16, DA, CCH);
    gemm_mma<<<dim3(CCH / 128, MM / 128), 256, GEMM_DYN>>>(
        a16, b16, bout, out, MM, CCH, DA);
}

// round 15
// speedup vs baseline: 10.0699x; 1.2234x over previous
#include <cuda_runtime.h>
#include <cuda_bf16.h>
#include <cuda_fp16.h>
#include <math.h>
#include <stdint.h>

// Problem constants
#define BV 4
#define TT 2048
#define CCH 1024
#define DA 1024
#define NH 16
#define HDM 64
#define MM (BV * TT)   // 8192 rows

// ---------------------------------------------------------------------------
// Device scratch (allocations forbidden; __device__ globals are sanctioned)
// ---------------------------------------------------------------------------
__device__ __half g_a16[(size_t)MM * CCH];                // activations (fp16)
__device__ __half g_b16[(size_t)CCH * 3 * DA];            // W^T (fp16)
__device__ __half g_q16[(size_t)MM * DA];                 // Q fp16 (scaled)
__device__ __half g_k16[(size_t)MM * DA];                 // head-major K fp16
__device__ __half g_vh [(size_t)MM * DA];                 // head-major V fp16

__device__ __forceinline__ uint32_t smem_u32(const void* p) {
    uint32_t a;
    asm("{ .reg .u64 t; cvta.to.shared.u64 t, %1; cvt.u32.u64 %0, t; }"
        : "=r"(a) : "l"(p));
    return a;
}

#define LDSM_X4(r, addr) \
    asm volatile("ldmatrix.sync.aligned.m8n8.x4.shared.b16 {%0,%1,%2,%3}, [%4];" \
        : "=r"((r)[0]), "=r"((r)[1]), "=r"((r)[2]), "=r"((r)[3]) : "r"(addr))

#define LDSM_X4_T(r, addr) \
    asm volatile("ldmatrix.sync.aligned.m8n8.x4.trans.shared.b16 {%0,%1,%2,%3}, [%4];" \
        : "=r"((r)[0]), "=r"((r)[1]), "=r"((r)[2]), "=r"((r)[3]) : "r"(addr))

#define MMA16816H(c, a, b0, b1) \
    asm volatile("mma.sync.aligned.m16n8k16.row.col.f32.f16.f16.f32 " \
        "{%0,%1,%2,%3}, {%4,%5,%6,%7}, {%8,%9}, {%0,%1,%2,%3};" \
        : "+f"((c)[0]), "+f"((c)[1]), "+f"((c)[2]), "+f"((c)[3]) \
        : "r"((a)[0]), "r"((a)[1]), "r"((a)[2]), "r"((a)[3]), "r"(b0), "r"(b1))

#define CP_A16(dst, src) \
    asm volatile("cp.async.cg.shared.global [%0], [%1], 16;" \
                 :: "r"(dst), "l"(src) : "memory")
#define CP_COMMIT() asm volatile("cp.async.commit_group;" ::: "memory")
#define CP_WAIT2()  asm volatile("cp.async.wait_group 2;" ::: "memory")
#define CP_WAIT1()  asm volatile("cp.async.wait_group 1;" ::: "memory")
#define CP_WAIT0()  asm volatile("cp.async.wait_group 0;" ::: "memory")

__device__ __forceinline__ uint32_t packh2(float a, float b) {
    __half2 h = __floats2half2_rn(a, b);
    return *(uint32_t*)&h;
}

// ---------------------------------------------------------------------------
// conv_f16: fp32 -> fp16 (input x)
// ---------------------------------------------------------------------------
__global__ void conv_f16(const float* __restrict__ src,
                         __half* __restrict__ dst, int n4)
{
    int i = blockIdx.x * blockDim.x + threadIdx.x;
    if (i >= n4) return;
    float4 v = ((const float4*)src)[i];
    ((__half2*)dst)[2 * i]     = __floats2half2_rn(v.x, v.y);
    ((__half2*)dst)[2 * i + 1] = __floats2half2_rn(v.z, v.w);
}

// W[K][N] -> T[N][K] fp16. 32x32 smem-tiled transpose.
__global__ void transpose_f16(const float* __restrict__ W,
                              __half* __restrict__ T, int K, int N)
{
    __shared__ float tile[32][33];
    int tx = threadIdx.x, ty = threadIdx.y;
    int n0 = blockIdx.x * 32, k0 = blockIdx.y * 32;
    #pragma unroll
    for (int j = 0; j < 32; j += 8)
        tile[ty + j][tx] = W[(size_t)(k0 + ty + j) * N + n0 + tx];
    __syncthreads();
    #pragma unroll
    for (int j = 0; j < 32; j += 8)
        T[(size_t)(n0 + ty + j) * K + k0 + tx] = __float2half_rn(tile[tx][ty + j]);
}

// ---------------------------------------------------------------------------
// fp16 single-product GEMM mainloop: CTA 128x128, 256 threads (8 warps,
// 2x4 grid, 64x32 warp tile), KC=64, 3-stage cp.async, 2 CTAs/SM.
// ---------------------------------------------------------------------------
#define KC 64
#define GP 72
#define GMAT_B (128 * GP * 2)               // 18432 B per matrix
#define GSTG_B (2 * GMAT_B)                 // 36864 B (A16, B16)
#define GEMM_DYN (3 * GSTG_B)               // 110592 B  (x2 CTAs = 216 KB/SM)

static __device__ __forceinline__ void gemm_issue(
    uint32_t stage, const char* a, const char* b, int Kb, int k0b, int tid)
{
    const char* srcs[2] = {a, b};
    #pragma unroll
    for (int i = 0; i < 8; i++) {
        int idx = i * 256 + tid;
        int arr = idx >> 10, rem = idx & 1023;
        int row = rem >> 3, c = rem & 7;
        CP_A16(stage + arr * GMAT_B + row * (GP * 2) + c * 16,
               srcs[arr] + (size_t)row * Kb + k0b + c * 16);
    }
}

#define GEMM_MAINLOOP(A16, B16, K)                                            \
    const uint32_t sbase = smem_u32(dyn);                                     \
    const int NCH = (K) / KC;                                                 \
    const int Kb = (K) * 2;                                                   \
    const char* ga = (const char*)((A16) + (size_t)arow0 * (K));              \
    const char* gb = (const char*)((B16) + (size_t)bcol0 * (K));              \
    gemm_issue(sbase, ga, gb, Kb, 0, tid); CP_COMMIT();                       \
    gemm_issue(sbase + GSTG_B, ga, gb, Kb, KC * 2, tid); CP_COMMIT();         \
    for (int c = 0; c < NCH; c++) {                                           \
        if (c < NCH - 1) { CP_WAIT1(); } else { CP_WAIT0(); }                 \
        __syncthreads();                                                      \
        if (c + 2 < NCH) {                                                    \
            gemm_issue(sbase + (uint32_t)((c + 2) % 3) * GSTG_B,              \
                       ga, gb, Kb, (c + 2) * KC * 2, tid);                    \
            CP_COMMIT();                                                      \
        }                                                                     \
        const uint32_t aA = sbase + (uint32_t)(c % 3) * GSTG_B;               \
        const uint32_t aB = aA + GMAT_B;                                      \
        _Pragma("unroll")                                                     \
        for (int ks = 0; ks < KC / 16; ks++) {                                \
            const int k0 = ks * 16;                                           \
            uint32_t af[4][4], bf[2][4];                                      \
            _Pragma("unroll")                                                 \
            for (int mt = 0; mt < 4; mt++) {                                  \
                uint32_t ao = (uint32_t)((warp_m * 64 + mt * 16 + dr) * GP    \
                                         + k0 + dka) * 2;                     \
                LDSM_X4(af[mt], aA + ao);                                     \
            }                                                                 \
            _Pragma("unroll")                                                 \
            for (int pr = 0; pr < 2; pr++) {                                  \
                uint32_t bo = (uint32_t)((warp_n * 32 + pr * 16 + dn) * GP    \
                                         + k0 + dkb) * 2;                     \
                LDSM_X4(bf[pr], aB + bo);                                     \
            }                                                                 \
            _Pragma("unroll")                                                 \
            for (int mt = 0; mt < 4; mt++)                                    \
                _Pragma("unroll")                                             \
                for (int nt = 0; nt < 4; nt++) {                              \
                    const int pr = nt >> 1, sb2 = (nt & 1) * 2;               \
                    MMA16816H(acc[mt][nt], af[mt], bf[pr][sb2], bf[pr][sb2 + 1]); \
                }                                                             \
        }                                                                     \
    }

// ---------------------------------------------------------------------------
// gemm_mma: generic fp32 output + bias (output projection)
// ---------------------------------------------------------------------------
__global__ __launch_bounds__(256, 2) void gemm_mma(
    const __half* __restrict__ A16, const __half* __restrict__ B16,
    const float* __restrict__ bias, float* __restrict__ C,
    int M, int N, int K)
{
    extern __shared__ char dyn[];
    const int tid = threadIdx.x;
    const int wid = tid >> 5, l = tid & 31;
    const int warp_m = wid & 1, warp_n = wid >> 1;     // 2 x 4 warp grid
    const int bc = blockIdx.x, br = blockIdx.y;
    const int arow0 = br * 128, bcol0 = bc * 128;

    const int mat = l >> 3;
    const int dr  = (mat & 1) * 8 + (l & 7);
    const int dka = (mat >> 1) * 8;
    const int dn  = (mat >> 1) * 8 + (l & 7);
    const int dkb = (mat & 1) * 8;

    float acc[4][4][4];
    #pragma unroll
    for (int i = 0; i < 4; i++)
        #pragma unroll
        for (int j = 0; j < 4; j++)
            #pragma unroll
            for (int q = 0; q < 4; q++) acc[i][j][q] = 0.f;

    GEMM_MAINLOOP(A16, B16, K)

    const int rbase = arow0 + warp_m * 64 + (l >> 2);
    const int cbase = bcol0 + warp_n * 32 + (l & 3) * 2;
    #pragma unroll
    for (int mt = 0; mt < 4; mt++)
        #pragma unroll
        for (int nt = 0; nt < 4; nt++) {
            const int row = rbase + mt * 16;
            const int col = cbase + nt * 8;
            float2 v0, v1;
            v0.x = acc[mt][nt][0] + bias[col];
            v0.y = acc[mt][nt][1] + bias[col + 1];
            v1.x = acc[mt][nt][2] + bias[col];
            v1.y = acc[mt][nt][3] + bias[col + 1];
            *(float2*)(C + (size_t)row * N + col) = v0;
            *(float2*)(C + (size_t)(row + 8) * N + col) = v1;
        }
}

// ---------------------------------------------------------------------------
// gemm_qkv: QKV projection with fused fp16 epilogue (Q scaled; K,V head-major)
// ---------------------------------------------------------------------------
__global__ __launch_bounds__(256, 2) void gemm_qkv(
    const __half* __restrict__ A16, const __half* __restrict__ B16,
    const float* __restrict__ bias,
    __half* __restrict__ q16, __half* __restrict__ k16,
    __half* __restrict__ vh)
{
    extern __shared__ char dyn[];
    const int tid = threadIdx.x;
    const int wid = tid >> 5, l = tid & 31;
    const int warp_m = wid & 1, warp_n = wid >> 1;
    const int bc = blockIdx.x, br = blockIdx.y;
    const int arow0 = br * 128, bcol0 = bc * 128;
    const int K = CCH;

    const int mat = l >> 3;
    const int dr  = (mat & 1) * 8 + (l & 7);
    const int dka = (mat >> 1) * 8;
    const int dn  = (mat >> 1) * 8 + (l & 7);
    const int dkb = (mat & 1) * 8;

    float acc[4][4][4];
    #pragma unroll
    for (int i = 0; i < 4; i++)
        #pragma unroll
        for (int j = 0; j < 4; j++)
            #pragma unroll
            for (int q = 0; q < 4; q++) acc[i][j][q] = 0.f;

    GEMM_MAINLOOP(A16, B16, K)

    const int rbase = arow0 + warp_m * 64 + (l >> 2);
    const int cbase = bcol0 + warp_n * 32 + (l & 3) * 2;
    #pragma unroll
    for (int mt = 0; mt < 4; mt++)
        #pragma unroll
        for (int nt = 0; nt < 4; nt++) {
            #pragma unroll
            for (int half2i = 0; half2i < 2; half2i++) {
                const int row = rbase + mt * 16 + half2i * 8;
                const int col = cbase + nt * 8;
                float v0 = acc[mt][nt][half2i * 2 + 0] + bias[col];
                float v1 = acc[mt][nt][half2i * 2 + 1] + bias[col + 1];
                if (bc < 8) {
                    // Q: fold 1/sqrt(64), token-major fp16
                    *(__half2*)(q16 + (size_t)row * DA + col) =
                        __floats2half2_rn(v0 * 0.125f, v1 * 0.125f);
                } else {
                    const int cg = col - (bc < 16 ? 1024 : 2048);
                    const int head = cg >> 6, d = cg & 63;
                    const int t = row & (TT - 1), bb = row >> 11;
                    size_t o = ((size_t)(bb * NH + head) * TT + t) * 64 + d;
                    __half* dst = (bc < 16) ? k16 : vh;
                    *(__half2*)(dst + o) = __floats2half2_rn(v0, v1);
                }
            }
        }
}

// ---------------------------------------------------------------------------
// Tensor-core flash attention v7 (causal): full fp16 single-product QK + PV.
//  - 2 CTAs/SM, KV stage = K,V fp16 (18.4 KB), Q fp16 in smem
//  - 2-stage cp.async KV pipeline, LPT scheduling
// ---------------------------------------------------------------------------
#define QPF 72
#define KVT_B (64 * QPF * 2)                 // 9216 B per array tile
#define KV_STAGE (2 * KVT_B)                 // 18432 B (K, V)
#define Q_OFF (2 * KV_STAGE)                 // 36864
#define QARR_B (128 * QPF * 2)               // 18432 B
#define FL_DYN (2 * KV_STAGE + QARR_B)       // 55296 B (x2 CTAs = 108 KB/SM)

static __device__ __forceinline__ void flash_issue(
    uint32_t stage, const char* k, const char* v, size_t tile_off, int tid)
{
    const char* srcs[2] = {k + tile_off, v + tile_off};
    #pragma unroll
    for (int i = 0; i < 4; i++) {
        int idx = i * 256 + tid;
        int arr = idx >> 9, rem = idx & 511;
        int r = rem >> 3, c = rem & 7;
        CP_A16(stage + arr * KVT_B + r * (QPF * 2) + c * 16,
               srcs[arr] + r * 128 + c * 16);
    }
}

__global__ __launch_bounds__(256, 2) void flash_mma(
    const __half* __restrict__ q16_g, const __half* __restrict__ k16_g,
    const __half* __restrict__ vh_g, __half* __restrict__ o16)
{
    extern __shared__ char fsm[];
    const int tid = threadIdx.x;
    const int w = tid >> 5, l = tid & 31;
    const int qt = (int)gridDim.x - 1 - (int)blockIdx.x;   // LPT
    const int h = blockIdx.y, b = blockIdx.z;

    const uint32_t sbase = smem_u32(fsm);
    const size_t headoff = ((size_t)(b * NH + h) * TT) * 64 * 2;
    const char* k_c = (const char*)k16_g + headoff;
    const char* v_c = (const char*)vh_g + headoff;
    const int jmax = 2 * qt + 1;

    // Prologue: Q (group 0), KV stage 0 (group 1), KV stage 1 (group 2)
    {
        const char* q0 = (const char*)q16_g
            + ((size_t)(b * TT + qt * 128) * DA + h * 64) * 2;
        #pragma unroll
        for (int i = 0; i < 4; i++) {
            int idx = i * 256 + tid;
            int r = idx >> 3, c = idx & 7;
            CP_A16(sbase + Q_OFF + r * (QPF * 2) + c * 16,
                   q0 + (size_t)r * (DA * 2) + c * 16);
        }
    }
    CP_COMMIT();
    flash_issue(sbase, k_c, v_c, 0, tid);
    CP_COMMIT();
    flash_issue(sbase + KV_STAGE, k_c, v_c, 8192, tid);
    CP_COMMIT();
    CP_WAIT2();
    __syncthreads();

    const int mat = l >> 3;
    const int dr  = (mat & 1) * 8 + (l & 7);
    const int dka = (mat >> 1) * 8;
    const int dn  = (mat >> 1) * 8 + (l & 7);
    const int dkb = (mat & 1) * 8;
    const uint32_t aQ = sbase + Q_OFF;

    float o[8][4];
    #pragma unroll
    for (int nt = 0; nt < 8; nt++)
        #pragma unroll
        for (int e = 0; e < 4; e++) o[nt][e] = 0.f;
    float m_a = -INFINITY, m_b = -INFINITY, l_a = 0.f, l_b = 0.f;

    for (int j = 0; j <= jmax; j++) {
        if (j < jmax) { CP_WAIT1(); } else { CP_WAIT0(); }
        __syncthreads();

        const bool active = (j * 64 <= qt * 128 + w * 16 + 15);
        if (active) {
            const uint32_t sb = sbase + (uint32_t)(j & 1) * KV_STAGE;
            const uint32_t aK = sb, aV = sb + KVT_B;

            float c[8][4];
            #pragma unroll
            for (int nt = 0; nt < 8; nt++)
                #pragma unroll
                for (int e = 0; e < 4; e++) c[nt][e] = 0.f;

            // S = Q K^T, single fp16 product
            #pragma unroll
            for (int t = 0; t < 4; t++) {
                uint32_t qf[4];
                uint32_t qo = (uint32_t)((w * 16 + dr) * QPF + t * 16 + dka) * 2;
                LDSM_X4(qf, aQ + qo);
                #pragma unroll
                for (int p = 0; p < 4; p++) {
                    uint32_t kb[4];
                    uint32_t bo = (uint32_t)((p * 16 + dn) * QPF + t * 16 + dkb) * 2;
                    LDSM_X4(kb, aK + bo);
                    MMA16816H(c[2 * p],     qf, kb[0], kb[1]);
                    MMA16816H(c[2 * p + 1], qf, kb[2], kb[3]);
                }
            }

            if (j >= 2 * qt) {
                const int qa = qt * 128 + w * 16 + (l >> 2);
                const int kc0 = j * 64 + (l & 3) * 2;
                #pragma unroll
                for (int nt = 0; nt < 8; nt++) {
                    int col = kc0 + nt * 8;
                    if (col > qa)     c[nt][0] = -INFINITY;
                    if (col + 1 > qa) c[nt][1] = -INFINITY;
                    if (col > qa + 8)     c[nt][2] = -INFINITY;
                    if (col + 1 > qa + 8) c[nt][3] = -INFINITY;
                }
            }

            float ma = -INFINITY, mb = -INFINITY;
            #pragma unroll
            for (int nt = 0; nt < 8; nt++) {
                ma = fmaxf(ma, fmaxf(c[nt][0], c[nt][1]));
                mb = fmaxf(mb, fmaxf(c[nt][2], c[nt][3]));
            }
            ma = fmaxf(ma, __shfl_xor_sync(0xffffffffu, ma, 1));
            ma = fmaxf(ma, __shfl_xor_sync(0xffffffffu, ma, 2));
            mb = fmaxf(mb, __shfl_xor_sync(0xffffffffu, mb, 1));
            mb = fmaxf(mb, __shfl_xor_sync(0xffffffffu, mb, 2));
            float mna = fmaxf(m_a, ma), mnb = fmaxf(m_b, mb);
            float aa = __expf(m_a - mna), ab = __expf(m_b - mnb);
            float sa = 0.f, sb2 = 0.f;
            #pragma unroll
            for (int nt = 0; nt < 8; nt++) {
                c[nt][0] = __expf(c[nt][0] - mna);
                c[nt][1] = __expf(c[nt][1] - mna);
                c[nt][2] = __expf(c[nt][2] - mnb);
                c[nt][3] = __expf(c[nt][3] - mnb);
                sa += c[nt][0] + c[nt][1];
                sb2 += c[nt][2] + c[nt][3];
            }
            sa += __shfl_xor_sync(0xffffffffu, sa, 1);
            sa += __shfl_xor_sync(0xffffffffu, sa, 2);
            sb2 += __shfl_xor_sync(0xffffffffu, sb2, 1);
            sb2 += __shfl_xor_sync(0xffffffffu, sb2, 2);
            l_a = l_a * aa + sa;
            l_b = l_b * ab + sb2;
            m_a = mna; m_b = mnb;
            #pragma unroll
            for (int nt = 0; nt < 8; nt++) {
                o[nt][0] *= aa; o[nt][1] *= aa;
                o[nt][2] *= ab; o[nt][3] *= ab;
            }

            // O += P V
            #pragma unroll
            for (int t = 0; t < 4; t++) {
                uint32_t pa[4];
                pa[0] = packh2(c[2 * t][0],     c[2 * t][1]);
                pa[1] = packh2(c[2 * t][2],     c[2 * t][3]);
                pa[2] = packh2(c[2 * t + 1][0], c[2 * t + 1][1]);
                pa[3] = packh2(c[2 * t + 1][2], c[2 * t + 1][3]);
                #pragma unroll
                for (int p = 0; p < 4; p++) {
                    uint32_t vb[4];
                    uint32_t vo = (uint32_t)((t * 16 + (mat & 1) * 8 + (l & 7)) * QPF
                                             + p * 16 + (mat >> 1) * 8) * 2;
                    LDSM_X4_T(vb, aV + vo);
                    MMA16816H(o[2 * p],     pa, vb[0], vb[1]);
                    MMA16816H(o[2 * p + 1], pa, vb[2], vb[3]);
                }
            }
        }
        __syncthreads();
        if (j + 2 <= jmax) {
            flash_issue(sbase + (uint32_t)(j & 1) * KV_STAGE,
                        k_c, v_c, (size_t)(j + 2) * 8192, tid);
            CP_COMMIT();
        }
    }

    // Epilogue: fp16 attn output (A operand of out-proj)
    const float ia = 1.f / l_a, ib = 1.f / l_b;
    const int row = (b * TT + qt * 128 + w * 16 + (l >> 2));
    const int col = h * 64 + (l & 3) * 2;
    #pragma unroll
    for (int nt = 0; nt < 8; nt++) {
        *(__half2*)(o16 + (size_t)row * DA + col + nt * 8) =
            __floats2half2_rn(o[nt][0] * ia, o[nt][1] * ia);
        *(__half2*)(o16 + (size_t)(row + 8) * DA + col + nt * 8) =
            __floats2half2_rn(o[nt][2] * ib, o[nt][3] * ib);
    }
}

// ---------------------------------------------------------------------------
// Launch
// ---------------------------------------------------------------------------
extern "C" void kernel_launch(void* const* d_in, const int* in_sizes, int n_in,
                              void* d_out, int out_size)
{
    const float* x    = (const float*)d_in[0];
    const float* Wqkv = (const float*)d_in[2];
    const float* bqkv = (const float*)d_in[3];
    const float* Wout = (const float*)d_in[4];
    const float* bout = (const float*)d_in[5];
    float* out = (float*)d_out;

    __half *a16, *b16, *q16, *k16, *vh;
    cudaGetSymbolAddress((void**)&a16, g_a16);
    cudaGetSymbolAddress((void**)&b16, g_b16);
    cudaGetSymbolAddress((void**)&q16, g_q16);
    cudaGetSymbolAddress((void**)&k16, g_k16);
    cudaGetSymbolAddress((void**)&vh, g_vh);

    cudaFuncSetAttribute(gemm_mma,
                         cudaFuncAttributeMaxDynamicSharedMemorySize, (int)GEMM_DYN);
    cudaFuncSetAttribute(gemm_qkv,
                         cudaFuncAttributeMaxDynamicSharedMemorySize, (int)GEMM_DYN);
    cudaFuncSetAttribute(flash_mma,
                         cudaFuncAttributeMaxDynamicSharedMemorySize, (int)FL_DYN);

    // Phase 1: QKV = x @ Wqkv + b (fp16 operands), fused fp16 epilogue
    conv_f16<<<(MM * CCH / 4 + 255) / 256, 256>>>(x, a16, MM * CCH / 4);
    transpose_f16<<<dim3(3 * DA / 32, CCH / 32), dim3(32, 8)>>>(Wqkv, b16, CCH, 3 * DA);
    gemm_qkv<<<dim3(3 * DA / 128, MM / 128), 256, GEMM_DYN>>>(
        a16, b16, bqkv, q16, k16, vh);

    // Phase 2: tensor-core flash (fp16 QK + PV; writes fp16 attn to a16)
    flash_mma<<<dim3(TT / 128, NH, BV), 256, FL_DYN>>>(
        q16, k16, vh, a16);

    // Phase 3: out = attn @ Wout + b (fp16 operands)
    transpose_f16<<<dim3(CCH / 32, DA / 32), dim3(32, 8)>>>(Wout, b16, DA, CCH);
    gemm_mma<<<dim3(CCH / 128, MM / 128), 256, GEMM_DYN>>>(
        a16, b16, bout, out, MM, CCH, DA);
}

// round 16
// speedup vs baseline: 10.3435x; 1.0272x over previous
#include <cuda_runtime.h>
#include <cuda_bf16.h>
#include <cuda_fp16.h>
#include <math.h>
#include <stdint.h>

// Problem constants
#define BV 4
#define TT 2048
#define CCH 1024
#define DA 1024
#define NH 16
#define HDM 64
#define MM (BV * TT)   // 8192 rows

// Q scale with log2(e) folded: softmax runs in base-2 domain.
#define QSCL 0.180336880111112f    // 0.125 * 1.44269504088896

// ---------------------------------------------------------------------------
// Device scratch (allocations forbidden; __device__ globals are sanctioned)
// ---------------------------------------------------------------------------
__device__ __half g_a16[(size_t)MM * CCH];                // activations (fp16)
__device__ __half g_b16[(size_t)CCH * 3 * DA];            // W^T (fp16)
__device__ __half g_q16[(size_t)MM * DA];                 // Q fp16 (scaled)
__device__ __half g_k16[(size_t)MM * DA];                 // head-major K fp16
__device__ __half g_vh [(size_t)MM * DA];                 // head-major V fp16

__device__ __forceinline__ uint32_t smem_u32(const void* p) {
    uint32_t a;
    asm("{ .reg .u64 t; cvta.to.shared.u64 t, %1; cvt.u32.u64 %0, t; }"
        : "=r"(a) : "l"(p));
    return a;
}
__device__ __forceinline__ float ex2(float x) {
    float y;
    asm("ex2.approx.ftz.f32 %0, %1;" : "=f"(y) : "f"(x));
    return y;
}

#define LDSM_X4(r, addr) \
    asm volatile("ldmatrix.sync.aligned.m8n8.x4.shared.b16 {%0,%1,%2,%3}, [%4];" \
        : "=r"((r)[0]), "=r"((r)[1]), "=r"((r)[2]), "=r"((r)[3]) : "r"(addr))

#define LDSM_X4_T(r, addr) \
    asm volatile("ldmatrix.sync.aligned.m8n8.x4.trans.shared.b16 {%0,%1,%2,%3}, [%4];" \
        : "=r"((r)[0]), "=r"((r)[1]), "=r"((r)[2]), "=r"((r)[3]) : "r"(addr))

#define MMA16816H(c, a, b0, b1) \
    asm volatile("mma.sync.aligned.m16n8k16.row.col.f32.f16.f16.f32 " \
        "{%0,%1,%2,%3}, {%4,%5,%6,%7}, {%8,%9}, {%0,%1,%2,%3};" \
        : "+f"((c)[0]), "+f"((c)[1]), "+f"((c)[2]), "+f"((c)[3]) \
        : "r"((a)[0]), "r"((a)[1]), "r"((a)[2]), "r"((a)[3]), "r"(b0), "r"(b1))

#define CP_A16(dst, src) \
    asm volatile("cp.async.cg.shared.global [%0], [%1], 16;" \
                 :: "r"(dst), "l"(src) : "memory")
#define CP_COMMIT() asm volatile("cp.async.commit_group;" ::: "memory")
#define CP_WAIT2()  asm volatile("cp.async.wait_group 2;" ::: "memory")
#define CP_WAIT1()  asm volatile("cp.async.wait_group 1;" ::: "memory")
#define CP_WAIT0()  asm volatile("cp.async.wait_group 0;" ::: "memory")

__device__ __forceinline__ uint32_t packh2(float a, float b) {
    __half2 h = __floats2half2_rn(a, b);
    return *(uint32_t*)&h;
}

// ---------------------------------------------------------------------------
// conv_f16: fp32 -> fp16 (input x)
// ---------------------------------------------------------------------------
__global__ void conv_f16(const float* __restrict__ src,
                         __half* __restrict__ dst, int n4)
{
    int i = blockIdx.x * blockDim.x + threadIdx.x;
    if (i >= n4) return;
    float4 v = ((const float4*)src)[i];
    ((__half2*)dst)[2 * i]     = __floats2half2_rn(v.x, v.y);
    ((__half2*)dst)[2 * i + 1] = __floats2half2_rn(v.z, v.w);
}

// W[K][N] -> T[N][K] fp16. 32x32 smem-tiled transpose.
__global__ void transpose_f16(const float* __restrict__ W,
                              __half* __restrict__ T, int K, int N)
{
    __shared__ float tile[32][33];
    int tx = threadIdx.x, ty = threadIdx.y;
    int n0 = blockIdx.x * 32, k0 = blockIdx.y * 32;
    #pragma unroll
    for (int j = 0; j < 32; j += 8)
        tile[ty + j][tx] = W[(size_t)(k0 + ty + j) * N + n0 + tx];
    __syncthreads();
    #pragma unroll
    for (int j = 0; j < 32; j += 8)
        T[(size_t)(n0 + ty + j) * K + k0 + tx] = __float2half_rn(tile[tx][ty + j]);
}

// ---------------------------------------------------------------------------
// fp16 single-product GEMM mainloop: CTA 128x128, 256 threads (8 warps,
// 2x4 grid, 64x32 warp tile), KC=64, 3-stage cp.async, 2 CTAs/SM.
// ---------------------------------------------------------------------------
#define KC 64
#define GP 72
#define GMAT_B (128 * GP * 2)               // 18432 B per matrix
#define GSTG_B (2 * GMAT_B)                 // 36864 B (A16, B16)
#define GEMM_DYN (3 * GSTG_B)               // 110592 B  (x2 CTAs = 216 KB/SM)

static __device__ __forceinline__ void gemm_issue(
    uint32_t stage, const char* a, const char* b, int Kb, int k0b, int tid)
{
    const char* srcs[2] = {a, b};
    #pragma unroll
    for (int i = 0; i < 8; i++) {
        int idx = i * 256 + tid;
        int arr = idx >> 10, rem = idx & 1023;
        int row = rem >> 3, c = rem & 7;
        CP_A16(stage + arr * GMAT_B + row * (GP * 2) + c * 16,
               srcs[arr] + (size_t)row * Kb + k0b + c * 16);
    }
}

#define GEMM_MAINLOOP(A16, B16, K)                                            \
    const uint32_t sbase = smem_u32(dyn);                                     \
    const int NCH = (K) / KC;                                                 \
    const int Kb = (K) * 2;                                                   \
    const char* ga = (const char*)((A16) + (size_t)arow0 * (K));              \
    const char* gb = (const char*)((B16) + (size_t)bcol0 * (K));              \
    gemm_issue(sbase, ga, gb, Kb, 0, tid); CP_COMMIT();                       \
    gemm_issue(sbase + GSTG_B, ga, gb, Kb, KC * 2, tid); CP_COMMIT();         \
    for (int c = 0; c < NCH; c++) {                                           \
        if (c < NCH - 1) { CP_WAIT1(); } else { CP_WAIT0(); }                 \
        __syncthreads();                                                      \
        if (c + 2 < NCH) {                                                    \
            gemm_issue(sbase + (uint32_t)((c + 2) % 3) * GSTG_B,              \
                       ga, gb, Kb, (c + 2) * KC * 2, tid);                    \
            CP_COMMIT();                                                      \
        }                                                                     \
        const uint32_t aA = sbase + (uint32_t)(c % 3) * GSTG_B;               \
        const uint32_t aB = aA + GMAT_B;                                      \
        _Pragma("unroll")                                                     \
        for (int ks = 0; ks < KC / 16; ks++) {                                \
            const int k0 = ks * 16;                                           \
            uint32_t af[4][4], bf[2][4];                                      \
            _Pragma("unroll")                                                 \
            for (int mt = 0; mt < 4; mt++) {                                  \
                uint32_t ao = (uint32_t)((warp_m * 64 + mt * 16 + dr) * GP    \
                                         + k0 + dka) * 2;                     \
                LDSM_X4(af[mt], aA + ao);                                     \
            }                                                                 \
            _Pragma("unroll")                                                 \
            for (int pr = 0; pr < 2; pr++) {                                  \
                uint32_t bo = (uint32_t)((warp_n * 32 + pr * 16 + dn) * GP    \
                                         + k0 + dkb) * 2;                     \
                LDSM_X4(bf[pr], aB + bo);                                     \
            }                                                                 \
            _Pragma("unroll")                                                 \
            for (int mt = 0; mt < 4; mt++)                                    \
                _Pragma("unroll")                                             \
                for (int nt = 0; nt < 4; nt++) {                              \
                    const int pr = nt >> 1, sb2 = (nt & 1) * 2;               \
                    MMA16816H(acc[mt][nt], af[mt], bf[pr][sb2], bf[pr][sb2 + 1]); \
                }                                                             \
        }                                                                     \
    }

// ---------------------------------------------------------------------------
// gemm_mma: generic fp32 output + bias (output projection)
// ---------------------------------------------------------------------------
__global__ __launch_bounds__(256, 2) void gemm_mma(
    const __half* __restrict__ A16, const __half* __restrict__ B16,
    const float* __restrict__ bias, float* __restrict__ C,
    int M, int N, int K)
{
    extern __shared__ char dyn[];
    const int tid = threadIdx.x;
    const int wid = tid >> 5, l = tid & 31;
    const int warp_m = wid & 1, warp_n = wid >> 1;     // 2 x 4 warp grid
    const int bc = blockIdx.x, br = blockIdx.y;
    const int arow0 = br * 128, bcol0 = bc * 128;

    const int mat = l >> 3;
    const int dr  = (mat & 1) * 8 + (l & 7);
    const int dka = (mat >> 1) * 8;
    const int dn  = (mat >> 1) * 8 + (l & 7);
    const int dkb = (mat & 1) * 8;

    float acc[4][4][4];
    #pragma unroll
    for (int i = 0; i < 4; i++)
        #pragma unroll
        for (int j = 0; j < 4; j++)
            #pragma unroll
            for (int q = 0; q < 4; q++) acc[i][j][q] = 0.f;

    GEMM_MAINLOOP(A16, B16, K)

    const int rbase = arow0 + warp_m * 64 + (l >> 2);
    const int cbase = bcol0 + warp_n * 32 + (l & 3) * 2;
    #pragma unroll
    for (int mt = 0; mt < 4; mt++)
        #pragma unroll
        for (int nt = 0; nt < 4; nt++) {
            const int row = rbase + mt * 16;
            const int col = cbase + nt * 8;
            float2 v0, v1;
            v0.x = acc[mt][nt][0] + bias[col];
            v0.y = acc[mt][nt][1] + bias[col + 1];
            v1.x = acc[mt][nt][2] + bias[col];
            v1.y = acc[mt][nt][3] + bias[col + 1];
            *(float2*)(C + (size_t)row * N + col) = v0;
            *(float2*)(C + (size_t)(row + 8) * N + col) = v1;
        }
}

// ---------------------------------------------------------------------------
// gemm_qkv: QKV projection with fused fp16 epilogue (Q scaled; K,V head-major)
// ---------------------------------------------------------------------------
__global__ __launch_bounds__(256, 2) void gemm_qkv(
    const __half* __restrict__ A16, const __half* __restrict__ B16,
    const float* __restrict__ bias,
    __half* __restrict__ q16, __half* __restrict__ k16,
    __half* __restrict__ vh)
{
    extern __shared__ char dyn[];
    const int tid = threadIdx.x;
    const int wid = tid >> 5, l = tid & 31;
    const int warp_m = wid & 1, warp_n = wid >> 1;
    const int bc = blockIdx.x, br = blockIdx.y;
    const int arow0 = br * 128, bcol0 = bc * 128;
    const int K = CCH;

    const int mat = l >> 3;
    const int dr  = (mat & 1) * 8 + (l & 7);
    const int dka = (mat >> 1) * 8;
    const int dn  = (mat >> 1) * 8 + (l & 7);
    const int dkb = (mat & 1) * 8;

    float acc[4][4][4];
    #pragma unroll
    for (int i = 0; i < 4; i++)
        #pragma unroll
        for (int j = 0; j < 4; j++)
            #pragma unroll
            for (int q = 0; q < 4; q++) acc[i][j][q] = 0.f;

    GEMM_MAINLOOP(A16, B16, K)

    const int rbase = arow0 + warp_m * 64 + (l >> 2);
    const int cbase = bcol0 + warp_n * 32 + (l & 3) * 2;
    #pragma unroll
    for (int mt = 0; mt < 4; mt++)
        #pragma unroll
        for (int nt = 0; nt < 4; nt++) {
            #pragma unroll
            for (int half2i = 0; half2i < 2; half2i++) {
                const int row = rbase + mt * 16 + half2i * 8;
                const int col = cbase + nt * 8;
                float v0 = acc[mt][nt][half2i * 2 + 0] + bias[col];
                float v1 = acc[mt][nt][half2i * 2 + 1] + bias[col + 1];
                if (bc < 8) {
                    // Q: fold 1/sqrt(64) * log2(e), token-major fp16
                    *(__half2*)(q16 + (size_t)row * DA + col) =
                        __floats2half2_rn(v0 * QSCL, v1 * QSCL);
                } else {
                    const int cg = col - (bc < 16 ? 1024 : 2048);
                    const int head = cg >> 6, d = cg & 63;
                    const int t = row & (TT - 1), bb = row >> 11;
                    size_t o = ((size_t)(bb * NH + head) * TT + t) * 64 + d;
                    __half* dst = (bc < 16) ? k16 : vh;
                    *(__half2*)(dst + o) = __floats2half2_rn(v0, v1);
                }
            }
        }
}

// ---------------------------------------------------------------------------
// Tensor-core flash attention v8 (causal): fp16 QK + PV, base-2 softmax,
// l computed by the PV MMA via a ones-column appended to V (pitch 88).
//  - 2 CTAs/SM, 2-stage cp.async KV pipeline, LPT scheduling
// ---------------------------------------------------------------------------
#define QPF 72
#define VPF 88                               // V pitch (44 banks -> no conflicts)
#define KT_B (64 * QPF * 2)                  // 9216 B (K tile)
#define VT_B (64 * VPF * 2)                  // 11264 B (V tile incl. pad)
#define KV_STAGE (KT_B + VT_B)               // 20480 B
#define Q_OFF (2 * KV_STAGE)                 // 40960
#define QARR_B (128 * QPF * 2)               // 18432 B
#define FL_DYN (2 * KV_STAGE + QARR_B)       // 59392 B (x2 CTAs = 116 KB/SM)

static __device__ __forceinline__ void flash_issue(
    uint32_t stage, const char* k, const char* v, size_t tile_off, int tid)
{
    #pragma unroll
    for (int i = 0; i < 2; i++) {
        int idx = i * 256 + tid;
        int r = idx >> 3, c = idx & 7;
        CP_A16(stage + r * (QPF * 2) + c * 16, k + tile_off + r * 128 + c * 16);
    }
    #pragma unroll
    for (int i = 0; i < 2; i++) {
        int idx = i * 256 + tid;
        int r = idx >> 3, c = idx & 7;
        CP_A16(stage + KT_B + r * (VPF * 2) + c * 16,
               v + tile_off + r * 128 + c * 16);
    }
}

__global__ __launch_bounds__(256, 2) void flash_mma(
    const __half* __restrict__ q16_g, const __half* __restrict__ k16_g,
    const __half* __restrict__ vh_g, __half* __restrict__ o16)
{
    extern __shared__ char fsm[];
    const int tid = threadIdx.x;
    const int w = tid >> 5, l = tid & 31;
    const int qt = (int)gridDim.x - 1 - (int)blockIdx.x;   // LPT
    const int h = blockIdx.y, b = blockIdx.z;

    const uint32_t sbase = smem_u32(fsm);
    const size_t headoff = ((size_t)(b * NH + h) * TT) * 64 * 2;
    const char* k_c = (const char*)k16_g + headoff;
    const char* v_c = (const char*)vh_g + headoff;
    const int jmax = 2 * qt + 1;

    // V pad init: cols 64..87 of both stages (col 64 = 1.0, rest = 0).
    // cp.async only ever writes cols 0..63, so this persists for all tiles.
    {
        const uint4 one16 = {0x00003c00u, 0u, 0u, 0u};   // {1.0h, 0...}
        const uint4 zero16 = {0u, 0u, 0u, 0u};
        for (int idx = tid; idx < 384; idx += 256) {
            int st = idx / 192, rem = idx % 192;
            int r = rem / 3, ch = rem % 3;
            *(uint4*)(fsm + st * KV_STAGE + KT_B + r * (VPF * 2) + 128 + ch * 16)
                = (ch == 0) ? one16 : zero16;
        }
    }

    // Prologue: Q (group 0), KV stage 0 (group 1), KV stage 1 (group 2)
    {
        const char* q0 = (const char*)q16_g
            + ((size_t)(b * TT + qt * 128) * DA + h * 64) * 2;
        #pragma unroll
        for (int i = 0; i < 4; i++) {
            int idx = i * 256 + tid;
            int r = idx >> 3, c = idx & 7;
            CP_A16(sbase + Q_OFF + r * (QPF * 2) + c * 16,
                   q0 + (size_t)r * (DA * 2) + c * 16);
        }
    }
    CP_COMMIT();
    flash_issue(sbase, k_c, v_c, 0, tid);
    CP_COMMIT();
    flash_issue(sbase + KV_STAGE, k_c, v_c, 8192, tid);
    CP_COMMIT();
    CP_WAIT2();
    __syncthreads();

    const int mat = l >> 3;
    const int dr  = (mat & 1) * 8 + (l & 7);
    const int dka = (mat >> 1) * 8;
    const int dn  = (mat >> 1) * 8 + (l & 7);
    const int dkb = (mat & 1) * 8;
    const uint32_t aQ = sbase + Q_OFF;

    float o[9][4];   // o[8] accumulates l (ones column) in [0]/[2]
    #pragma unroll
    for (int nt = 0; nt < 9; nt++)
        #pragma unroll
        for (int e = 0; e < 4; e++) o[nt][e] = 0.f;
    float m_a = -INFINITY, m_b = -INFINITY;

    for (int j = 0; j <= jmax; j++) {
        if (j < jmax) { CP_WAIT1(); } else { CP_WAIT0(); }
        __syncthreads();

        const bool active = (j * 64 <= qt * 128 + w * 16 + 15);
        if (active) {
            const uint32_t sb = sbase + (uint32_t)(j & 1) * KV_STAGE;
            const uint32_t aK = sb, aV = sb + KT_B;

            float c[8][4];
            #pragma unroll
            for (int nt = 0; nt < 8; nt++)
                #pragma unroll
                for (int e = 0; e < 4; e++) c[nt][e] = 0.f;

            // S = Q K^T (log2-domain), single fp16 product
            #pragma unroll
            for (int t = 0; t < 4; t++) {
                uint32_t qf[4];
                uint32_t qo = (uint32_t)((w * 16 + dr) * QPF + t * 16 + dka) * 2;
                LDSM_X4(qf, aQ + qo);
                #pragma unroll
                for (int p = 0; p < 4; p++) {
                    uint32_t kb[4];
                    uint32_t bo = (uint32_t)((p * 16 + dn) * QPF + t * 16 + dkb) * 2;
                    LDSM_X4(kb, aK + bo);
                    MMA16816H(c[2 * p],     qf, kb[0], kb[1]);
                    MMA16816H(c[2 * p + 1], qf, kb[2], kb[3]);
                }
            }

            if (j >= 2 * qt) {
                const int qa = qt * 128 + w * 16 + (l >> 2);
                const int kc0 = j * 64 + (l & 3) * 2;
                #pragma unroll
                for (int nt = 0; nt < 8; nt++) {
                    int col = kc0 + nt * 8;
                    if (col > qa)     c[nt][0] = -INFINITY;
                    if (col + 1 > qa) c[nt][1] = -INFINITY;
                    if (col > qa + 8)     c[nt][2] = -INFINITY;
                    if (col + 1 > qa + 8) c[nt][3] = -INFINITY;
                }
            }

            float ma = -INFINITY, mb = -INFINITY;
            #pragma unroll
            for (int nt = 0; nt < 8; nt++) {
                ma = fmaxf(ma, fmaxf(c[nt][0], c[nt][1]));
                mb = fmaxf(mb, fmaxf(c[nt][2], c[nt][3]));
            }
            ma = fmaxf(ma, __shfl_xor_sync(0xffffffffu, ma, 1));
            ma = fmaxf(ma, __shfl_xor_sync(0xffffffffu, ma, 2));
            mb = fmaxf(mb, __shfl_xor_sync(0xffffffffu, mb, 1));
            mb = fmaxf(mb, __shfl_xor_sync(0xffffffffu, mb, 2));
            float mna = fmaxf(m_a, ma), mnb = fmaxf(m_b, mb);
            float aa = ex2(m_a - mna), ab = ex2(m_b - mnb);
            m_a = mna; m_b = mnb;
            #pragma unroll
            for (int nt = 0; nt < 8; nt++) {
                c[nt][0] = ex2(c[nt][0] - mna);
                c[nt][1] = ex2(c[nt][1] - mna);
                c[nt][2] = ex2(c[nt][2] - mnb);
                c[nt][3] = ex2(c[nt][3] - mnb);
            }
            #pragma unroll
            for (int nt = 0; nt < 9; nt++) {
                o[nt][0] *= aa; o[nt][1] *= aa;
                o[nt][2] *= ab; o[nt][3] *= ab;
            }

            // O += P V'   (V' col 64 = ones -> o[8][0]/[2] accumulate l)
            #pragma unroll
            for (int t = 0; t < 4; t++) {
                uint32_t pa[4];
                pa[0] = packh2(c[2 * t][0],     c[2 * t][1]);
                pa[1] = packh2(c[2 * t][2],     c[2 * t][3]);
                pa[2] = packh2(c[2 * t + 1][0], c[2 * t + 1][1]);
                pa[3] = packh2(c[2 * t + 1][2], c[2 * t + 1][3]);
                #pragma unroll
                for (int p = 0; p < 5; p++) {
                    uint32_t vb[4];
                    uint32_t vo = (uint32_t)((t * 16 + (mat & 1) * 8 + (l & 7)) * VPF
                                             + p * 16 + (mat >> 1) * 8) * 2;
                    LDSM_X4_T(vb, aV + vo);
                    MMA16816H(o[2 * p], pa, vb[0], vb[1]);
                    if (p < 4)
                        MMA16816H(o[2 * p + 1], pa, vb[2], vb[3]);
                }
            }
        }
        __syncthreads();
        if (j + 2 <= jmax) {
            flash_issue(sbase + (uint32_t)(j & 1) * KV_STAGE,
                        k_c, v_c, (size_t)(j + 2) * 8192, tid);
            CP_COMMIT();
        }
    }

    // l lives in lane (l & ~3) of each quad (column 64): broadcast.
    float l_a = __shfl_sync(0xffffffffu, o[8][0], l & ~3);
    float l_b = __shfl_sync(0xffffffffu, o[8][2], l & ~3);

    // Epilogue: fp16 attn output (A operand of out-proj)
    const float ia = 1.f / l_a, ib = 1.f / l_b;
    const int row = (b * TT + qt * 128 + w * 16 + (l >> 2));
    const int col = h * 64 + (l & 3) * 2;
    #pragma unroll
    for (int nt = 0; nt < 8; nt++) {
        *(__half2*)(o16 + (size_t)row * DA + col + nt * 8) =
            __floats2half2_rn(o[nt][0] * ia, o[nt][1] * ia);
        *(__half2*)(o16 + (size_t)(row + 8) * DA + col + nt * 8) =
            __floats2half2_rn(o[nt][2] * ib, o[nt][3] * ib);
    }
}

// ---------------------------------------------------------------------------
// Launch
// ---------------------------------------------------------------------------
extern "C" void kernel_launch(void* const* d_in, const int* in_sizes, int n_in,
                              void* d_out, int out_size)
{
    const float* x    = (const float*)d_in[0];
    const float* Wqkv = (const float*)d_in[2];
    const float* bqkv = (const float*)d_in[3];
    const float* Wout = (const float*)d_in[4];
    const float* bout = (const float*)d_in[5];
    float* out = (float*)d_out;

    __half *a16, *b16, *q16, *k16, *vh;
    cudaGetSymbolAddress((void**)&a16, g_a16);
    cudaGetSymbolAddress((void**)&b16, g_b16);
    cudaGetSymbolAddress((void**)&q16, g_q16);
    cudaGetSymbolAddress((void**)&k16, g_k16);
    cudaGetSymbolAddress((void**)&vh, g_vh);

    cudaFuncSetAttribute(gemm_mma,
                         cudaFuncAttributeMaxDynamicSharedMemorySize, (int)GEMM_DYN);
    cudaFuncSetAttribute(gemm_qkv,
                         cudaFuncAttributeMaxDynamicSharedMemorySize, (int)GEMM_DYN);
    cudaFuncSetAttribute(flash_mma,
                         cudaFuncAttributeMaxDynamicSharedMemorySize, (int)FL_DYN);

    // Phase 1: QKV = x @ Wqkv + b (fp16 operands), fused fp16 epilogue
    conv_f16<<<(MM * CCH / 4 + 255) / 256, 256>>>(x, a16, MM * CCH / 4);
    transpose_f16<<<dim3(3 * DA / 32, CCH / 32), dim3(32, 8)>>>(Wqkv, b16, CCH, 3 * DA);
    gemm_qkv<<<dim3(3 * DA / 128, MM / 128), 256, GEMM_DYN>>>(
        a16, b16, bqkv, q16, k16, vh);

    // Phase 2: tensor-core flash (fp16, base-2 softmax, MMA-computed l)
    flash_mma<<<dim3(TT / 128, NH, BV), 256, FL_DYN>>>(
        q16, k16, vh, a16);

    // Phase 3: out = attn @ Wout + b (fp16 operands)
    transpose_f16<<<dim3(CCH / 32, DA / 32), dim3(32, 8)>>>(Wout, b16, DA, CCH);
    gemm_mma<<<dim3(CCH / 128, MM / 128), 256, GEMM_DYN>>>(
        a16, b16, bout, out, MM, CCH, DA);
}

// round 17
// speedup vs baseline: 10.5874x; 1.0236x over previous
#include <cuda_runtime.h>
#include <cuda_bf16.h>
#include <cuda_fp16.h>
#include <math.h>
#include <stdint.h>

// Problem constants
#define BV 4
#define TT 2048
#define CCH 1024
#define DA 1024
#define NH 16
#define HDM 64
#define MM (BV * TT)   // 8192 rows

// Q scale with log2(e) folded: softmax runs in base-2 domain.
#define QSCL 0.180336880111112f    // 0.125 * 1.44269504088896

// ---------------------------------------------------------------------------
// Device scratch (allocations forbidden; __device__ globals are sanctioned)
// ---------------------------------------------------------------------------
__device__ __half g_a16[(size_t)MM * CCH];                // activations (fp16)
__device__ __half g_b16[(size_t)CCH * 3 * DA];            // W^T (fp16)
__device__ __half g_q16[(size_t)MM * DA];                 // Q fp16 (scaled)
__device__ __half g_k16[(size_t)MM * DA];                 // head-major K fp16
__device__ __half g_vh [(size_t)MM * DA];                 // head-major V fp16

__device__ __forceinline__ uint32_t smem_u32(const void* p) {
    uint32_t a;
    asm("{ .reg .u64 t; cvta.to.shared.u64 t, %1; cvt.u32.u64 %0, t; }"
        : "=r"(a) : "l"(p));
    return a;
}
__device__ __forceinline__ float ex2(float x) {
    float y;
    asm("ex2.approx.ftz.f32 %0, %1;" : "=f"(y) : "f"(x));
    return y;
}

#define LDSM_X4(r, addr) \
    asm volatile("ldmatrix.sync.aligned.m8n8.x4.shared.b16 {%0,%1,%2,%3}, [%4];" \
        : "=r"((r)[0]), "=r"((r)[1]), "=r"((r)[2]), "=r"((r)[3]) : "r"(addr))

#define LDSM_X4_T(r, addr) \
    asm volatile("ldmatrix.sync.aligned.m8n8.x4.trans.shared.b16 {%0,%1,%2,%3}, [%4];" \
        : "=r"((r)[0]), "=r"((r)[1]), "=r"((r)[2]), "=r"((r)[3]) : "r"(addr))

#define MMA16816H(c, a, b0, b1) \
    asm volatile("mma.sync.aligned.m16n8k16.row.col.f32.f16.f16.f32 " \
        "{%0,%1,%2,%3}, {%4,%5,%6,%7}, {%8,%9}, {%0,%1,%2,%3};" \
        : "+f"((c)[0]), "+f"((c)[1]), "+f"((c)[2]), "+f"((c)[3]) \
        : "r"((a)[0]), "r"((a)[1]), "r"((a)[2]), "r"((a)[3]), "r"(b0), "r"(b1))

#define CP_A16(dst, src) \
    asm volatile("cp.async.cg.shared.global [%0], [%1], 16;" \
                 :: "r"(dst), "l"(src) : "memory")
#define CP_COMMIT() asm volatile("cp.async.commit_group;" ::: "memory")
#define CP_WAIT2()  asm volatile("cp.async.wait_group 2;" ::: "memory")
#define CP_WAIT1()  asm volatile("cp.async.wait_group 1;" ::: "memory")
#define CP_WAIT0()  asm volatile("cp.async.wait_group 0;" ::: "memory")

__device__ __forceinline__ uint32_t packh2(float a, float b) {
    __half2 h = __floats2half2_rn(a, b);
    return *(uint32_t*)&h;
}

// ---------------------------------------------------------------------------
// conv_f16: fp32 -> fp16 (input x)
// ---------------------------------------------------------------------------
__global__ void conv_f16(const float* __restrict__ src,
                         __half* __restrict__ dst, int n4)
{
    int i = blockIdx.x * blockDim.x + threadIdx.x;
    if (i >= n4) return;
    float4 v = ((const float4*)src)[i];
    ((__half2*)dst)[2 * i]     = __floats2half2_rn(v.x, v.y);
    ((__half2*)dst)[2 * i + 1] = __floats2half2_rn(v.z, v.w);
}

// W[K][N] -> T[N][K] fp16. 32x32 smem-tiled transpose.
__global__ void transpose_f16(const float* __restrict__ W,
                              __half* __restrict__ T, int K, int N)
{
    __shared__ float tile[32][33];
    int tx = threadIdx.x, ty = threadIdx.y;
    int n0 = blockIdx.x * 32, k0 = blockIdx.y * 32;
    #pragma unroll
    for (int j = 0; j < 32; j += 8)
        tile[ty + j][tx] = W[(size_t)(k0 + ty + j) * N + n0 + tx];
    __syncthreads();
    #pragma unroll
    for (int j = 0; j < 32; j += 8)
        T[(size_t)(n0 + ty + j) * K + k0 + tx] = __float2half_rn(tile[tx][ty + j]);
}

// ---------------------------------------------------------------------------
// fp16 single-product GEMM mainloop: CTA 128x128, 256 threads (8 warps,
// 2x4 grid, 64x32 warp tile), KC=64, 3-stage cp.async, 2 CTAs/SM.
// ---------------------------------------------------------------------------
#define KC 64
#define GP 72
#define GMAT_B (128 * GP * 2)               // 18432 B per matrix
#define GSTG_B (2 * GMAT_B)                 // 36864 B (A16, B16)
#define GEMM_DYN (3 * GSTG_B)               // 110592 B  (x2 CTAs = 216 KB/SM)

static __device__ __forceinline__ void gemm_issue(
    uint32_t stage, const char* a, const char* b, int Kb, int k0b, int tid)
{
    const char* srcs[2] = {a, b};
    #pragma unroll
    for (int i = 0; i < 8; i++) {
        int idx = i * 256 + tid;
        int arr = idx >> 10, rem = idx & 1023;
        int row = rem >> 3, c = rem & 7;
        CP_A16(stage + arr * GMAT_B + row * (GP * 2) + c * 16,
               srcs[arr] + (size_t)row * Kb + k0b + c * 16);
    }
}

#define GEMM_MAINLOOP(A16, B16, K)                                            \
    const uint32_t sbase = smem_u32(dyn);                                     \
    const int NCH = (K) / KC;                                                 \
    const int Kb = (K) * 2;                                                   \
    const char* ga = (const char*)((A16) + (size_t)arow0 * (K));              \
    const char* gb = (const char*)((B16) + (size_t)bcol0 * (K));              \
    gemm_issue(sbase, ga, gb, Kb, 0, tid); CP_COMMIT();                       \
    gemm_issue(sbase + GSTG_B, ga, gb, Kb, KC * 2, tid); CP_COMMIT();         \
    for (int c = 0; c < NCH; c++) {                                           \
        if (c < NCH - 1) { CP_WAIT1(); } else { CP_WAIT0(); }                 \
        __syncthreads();                                                      \
        if (c + 2 < NCH) {                                                    \
            gemm_issue(sbase + (uint32_t)((c + 2) % 3) * GSTG_B,              \
                       ga, gb, Kb, (c + 2) * KC * 2, tid);                    \
            CP_COMMIT();                                                      \
        }                                                                     \
        const uint32_t aA = sbase + (uint32_t)(c % 3) * GSTG_B;               \
        const uint32_t aB = aA + GMAT_B;                                      \
        _Pragma("unroll")                                                     \
        for (int ks = 0; ks < KC / 16; ks++) {                                \
            const int k0 = ks * 16;                                           \
            uint32_t af[4][4], bf[2][4];                                      \
            _Pragma("unroll")                                                 \
            for (int mt = 0; mt < 4; mt++) {                                  \
                uint32_t ao = (uint32_t)((warp_m * 64 + mt * 16 + dr) * GP    \
                                         + k0 + dka) * 2;                     \
                LDSM_X4(af[mt], aA + ao);                                     \
            }                                                                 \
            _Pragma("unroll")                                                 \
            for (int pr = 0; pr < 2; pr++) {                                  \
                uint32_t bo = (uint32_t)((warp_n * 32 + pr * 16 + dn) * GP    \
                                         + k0 + dkb) * 2;                     \
                LDSM_X4(bf[pr], aB + bo);                                     \
            }                                                                 \
            _Pragma("unroll")                                                 \
            for (int mt = 0; mt < 4; mt++)                                    \
                _Pragma("unroll")                                             \
                for (int nt = 0; nt < 4; nt++) {                              \
                    const int pr = nt >> 1, sb2 = (nt & 1) * 2;               \
                    MMA16816H(acc[mt][nt], af[mt], bf[pr][sb2], bf[pr][sb2 + 1]); \
                }                                                             \
        }                                                                     \
    }

// ---------------------------------------------------------------------------
// gemm_mma: generic fp32 output + bias (output projection)
// ---------------------------------------------------------------------------
__global__ __launch_bounds__(256, 2) void gemm_mma(
    const __half* __restrict__ A16, const __half* __restrict__ B16,
    const float* __restrict__ bias, float* __restrict__ C,
    int M, int N, int K)
{
    extern __shared__ char dyn[];
    const int tid = threadIdx.x;
    const int wid = tid >> 5, l = tid & 31;
    const int warp_m = wid & 1, warp_n = wid >> 1;     // 2 x 4 warp grid
    const int bc = blockIdx.x, br = blockIdx.y;
    const int arow0 = br * 128, bcol0 = bc * 128;

    const int mat = l >> 3;
    const int dr  = (mat & 1) * 8 + (l & 7);
    const int dka = (mat >> 1) * 8;
    const int dn  = (mat >> 1) * 8 + (l & 7);
    const int dkb = (mat & 1) * 8;

    float acc[4][4][4];
    #pragma unroll
    for (int i = 0; i < 4; i++)
        #pragma unroll
        for (int j = 0; j < 4; j++)
            #pragma unroll
            for (int q = 0; q < 4; q++) acc[i][j][q] = 0.f;

    GEMM_MAINLOOP(A16, B16, K)

    const int rbase = arow0 + warp_m * 64 + (l >> 2);
    const int cbase = bcol0 + warp_n * 32 + (l & 3) * 2;
    #pragma unroll
    for (int mt = 0; mt < 4; mt++)
        #pragma unroll
        for (int nt = 0; nt < 4; nt++) {
            const int row = rbase + mt * 16;
            const int col = cbase + nt * 8;
            float2 v0, v1;
            v0.x = acc[mt][nt][0] + bias[col];
            v0.y = acc[mt][nt][1] + bias[col + 1];
            v1.x = acc[mt][nt][2] + bias[col];
            v1.y = acc[mt][nt][3] + bias[col + 1];
            *(float2*)(C + (size_t)row * N + col) = v0;
            *(float2*)(C + (size_t)(row + 8) * N + col) = v1;
        }
}

// ---------------------------------------------------------------------------
// gemm_qkv: QKV projection with fused fp16 epilogue (Q scaled; K,V head-major)
// ---------------------------------------------------------------------------
__global__ __launch_bounds__(256, 2) void gemm_qkv(
    const __half* __restrict__ A16, const __half* __restrict__ B16,
    const float* __restrict__ bias,
    __half* __restrict__ q16, __half* __restrict__ k16,
    __half* __restrict__ vh)
{
    extern __shared__ char dyn[];
    const int tid = threadIdx.x;
    const int wid = tid >> 5, l = tid & 31;
    const int warp_m = wid & 1, warp_n = wid >> 1;
    const int bc = blockIdx.x, br = blockIdx.y;
    const int arow0 = br * 128, bcol0 = bc * 128;
    const int K = CCH;

    const int mat = l >> 3;
    const int dr  = (mat & 1) * 8 + (l & 7);
    const int dka = (mat >> 1) * 8;
    const int dn  = (mat >> 1) * 8 + (l & 7);
    const int dkb = (mat & 1) * 8;

    float acc[4][4][4];
    #pragma unroll
    for (int i = 0; i < 4; i++)
        #pragma unroll
        for (int j = 0; j < 4; j++)
            #pragma unroll
            for (int q = 0; q < 4; q++) acc[i][j][q] = 0.f;

    GEMM_MAINLOOP(A16, B16, K)

    const int rbase = arow0 + warp_m * 64 + (l >> 2);
    const int cbase = bcol0 + warp_n * 32 + (l & 3) * 2;
    #pragma unroll
    for (int mt = 0; mt < 4; mt++)
        #pragma unroll
        for (int nt = 0; nt < 4; nt++) {
            #pragma unroll
            for (int half2i = 0; half2i < 2; half2i++) {
                const int row = rbase + mt * 16 + half2i * 8;
                const int col = cbase + nt * 8;
                float v0 = acc[mt][nt][half2i * 2 + 0] + bias[col];
                float v1 = acc[mt][nt][half2i * 2 + 1] + bias[col + 1];
                if (bc < 8) {
                    // Q: fold 1/sqrt(64) * log2(e), token-major fp16
                    *(__half2*)(q16 + (size_t)row * DA + col) =
                        __floats2half2_rn(v0 * QSCL, v1 * QSCL);
                } else {
                    const int cg = col - (bc < 16 ? 1024 : 2048);
                    const int head = cg >> 6, d = cg & 63;
                    const int t = row & (TT - 1), bb = row >> 11;
                    size_t o = ((size_t)(bb * NH + head) * TT + t) * 64 + d;
                    __half* dst = (bc < 16) ? k16 : vh;
                    *(__half2*)(dst + o) = __floats2half2_rn(v0, v1);
                }
            }
        }
}

// ---------------------------------------------------------------------------
// Tensor-core flash attention v9 (causal): fp16 QK + PV, base-2 softmax,
// MMA-computed l, 3-stage cp.async KV ring with ONE barrier per tile.
//  - 2 CTAs/SM, LPT scheduling
// ---------------------------------------------------------------------------
#define QPF 72
#define VPF 88                               // V pitch (44 banks -> no conflicts)
#define KT_B (64 * QPF * 2)                  // 9216 B (K tile)
#define VT_B (64 * VPF * 2)                  // 11264 B (V tile incl. pad)
#define KV_STAGE (KT_B + VT_B)               // 20480 B
#define Q_OFF (3 * KV_STAGE)                 // 61440
#define QARR_B (128 * QPF * 2)               // 18432 B
#define FL_DYN (3 * KV_STAGE + QARR_B)       // 79872 B (x2 CTAs = 160 KB/SM)

static __device__ __forceinline__ void flash_issue(
    uint32_t stage, const char* k, const char* v, size_t tile_off, int tid)
{
    #pragma unroll
    for (int i = 0; i < 2; i++) {
        int idx = i * 256 + tid;
        int r = idx >> 3, c = idx & 7;
        CP_A16(stage + r * (QPF * 2) + c * 16, k + tile_off + r * 128 + c * 16);
    }
    #pragma unroll
    for (int i = 0; i < 2; i++) {
        int idx = i * 256 + tid;
        int r = idx >> 3, c = idx & 7;
        CP_A16(stage + KT_B + r * (VPF * 2) + c * 16,
               v + tile_off + r * 128 + c * 16);
    }
}

__global__ __launch_bounds__(256, 2) void flash_mma(
    const __half* __restrict__ q16_g, const __half* __restrict__ k16_g,
    const __half* __restrict__ vh_g, __half* __restrict__ o16)
{
    extern __shared__ char fsm[];
    const int tid = threadIdx.x;
    const int w = tid >> 5, l = tid & 31;
    const int qt = (int)gridDim.x - 1 - (int)blockIdx.x;   // LPT
    const int h = blockIdx.y, b = blockIdx.z;

    const uint32_t sbase = smem_u32(fsm);
    const size_t headoff = ((size_t)(b * NH + h) * TT) * 64 * 2;
    const char* k_c = (const char*)k16_g + headoff;
    const char* v_c = (const char*)vh_g + headoff;
    const int jmax = 2 * qt + 1;

    // V pad init: cols 64..87 of all 3 stages (col 64 = 1.0, rest = 0).
    // cp.async only ever writes cols 0..63, so this persists for all tiles.
    {
        const uint4 one16 = {0x00003c00u, 0u, 0u, 0u};   // {1.0h, 0...}
        const uint4 zero16 = {0u, 0u, 0u, 0u};
        for (int idx = tid; idx < 576; idx += 256) {
            int st = idx / 192, rem = idx % 192;
            int r = rem / 3, ch = rem % 3;
            *(uint4*)(fsm + st * KV_STAGE + KT_B + r * (VPF * 2) + 128 + ch * 16)
                = (ch == 0) ? one16 : zero16;
        }
    }

    // Prologue: Q (group 0), KV stage 0 (group 1), KV stage 1 (group 2)
    {
        const char* q0 = (const char*)q16_g
            + ((size_t)(b * TT + qt * 128) * DA + h * 64) * 2;
        #pragma unroll
        for (int i = 0; i < 4; i++) {
            int idx = i * 256 + tid;
            int r = idx >> 3, c = idx & 7;
            CP_A16(sbase + Q_OFF + r * (QPF * 2) + c * 16,
                   q0 + (size_t)r * (DA * 2) + c * 16);
        }
    }
    CP_COMMIT();
    flash_issue(sbase, k_c, v_c, 0, tid);
    CP_COMMIT();
    flash_issue(sbase + KV_STAGE, k_c, v_c, 8192, tid);
    CP_COMMIT();

    const int mat = l >> 3;
    const int dr  = (mat & 1) * 8 + (l & 7);
    const int dka = (mat >> 1) * 8;
    const int dn  = (mat >> 1) * 8 + (l & 7);
    const int dkb = (mat & 1) * 8;
    const uint32_t aQ = sbase + Q_OFF;

    float o[9][4];   // o[8] accumulates l (ones column) in [0]/[2]
    #pragma unroll
    for (int nt = 0; nt < 9; nt++)
        #pragma unroll
        for (int e = 0; e < 4; e++) o[nt][e] = 0.f;
    float m_a = -INFINITY, m_b = -INFINITY;

    for (int j = 0; j <= jmax; j++) {
        // Stage j and (at j=0) the Q group must be complete; the newest
        // in-flight stage stays pending. Groups retire in commit order.
        if (j < jmax) { CP_WAIT1(); } else { CP_WAIT0(); }
        __syncthreads();   // entry barrier: publishes stage j%3; also means
                           // every thread is done reading stage (j+2)%3
                           // (last read at iter j-1) -> safe to refill now.
        if (j + 2 <= jmax) {
            flash_issue(sbase + (uint32_t)((j + 2) % 3) * KV_STAGE,
                        k_c, v_c, (size_t)(j + 2) * 8192, tid);
            CP_COMMIT();
        }

        const bool active = (j * 64 <= qt * 128 + w * 16 + 15);
        if (active) {
            const uint32_t sb = sbase + (uint32_t)(j % 3) * KV_STAGE;
            const uint32_t aK = sb, aV = sb + KT_B;

            float c[8][4];
            #pragma unroll
            for (int nt = 0; nt < 8; nt++)
                #pragma unroll
                for (int e = 0; e < 4; e++) c[nt][e] = 0.f;

            // S = Q K^T (log2-domain), single fp16 product
            #pragma unroll
            for (int t = 0; t < 4; t++) {
                uint32_t qf[4];
                uint32_t qo = (uint32_t)((w * 16 + dr) * QPF + t * 16 + dka) * 2;
                LDSM_X4(qf, aQ + qo);
                #pragma unroll
                for (int p = 0; p < 4; p++) {
                    uint32_t kb[4];
                    uint32_t bo = (uint32_t)((p * 16 + dn) * QPF + t * 16 + dkb) * 2;
                    LDSM_X4(kb, aK + bo);
                    MMA16816H(c[2 * p],     qf, kb[0], kb[1]);
                    MMA16816H(c[2 * p + 1], qf, kb[2], kb[3]);
                }
            }

            if (j >= 2 * qt) {
                const int qa = qt * 128 + w * 16 + (l >> 2);
                const int kc0 = j * 64 + (l & 3) * 2;
                #pragma unroll
                for (int nt = 0; nt < 8; nt++) {
                    int col = kc0 + nt * 8;
                    if (col > qa)     c[nt][0] = -INFINITY;
                    if (col + 1 > qa) c[nt][1] = -INFINITY;
                    if (col > qa + 8)     c[nt][2] = -INFINITY;
                    if (col + 1 > qa + 8) c[nt][3] = -INFINITY;
                }
            }

            float ma = -INFINITY, mb = -INFINITY;
            #pragma unroll
            for (int nt = 0; nt < 8; nt++) {
                ma = fmaxf(ma, fmaxf(c[nt][0], c[nt][1]));
                mb = fmaxf(mb, fmaxf(c[nt][2], c[nt][3]));
            }
            ma = fmaxf(ma, __shfl_xor_sync(0xffffffffu, ma, 1));
            ma = fmaxf(ma, __shfl_xor_sync(0xffffffffu, ma, 2));
            mb = fmaxf(mb, __shfl_xor_sync(0xffffffffu, mb, 1));
            mb = fmaxf(mb, __shfl_xor_sync(0xffffffffu, mb, 2));
            float mna = fmaxf(m_a, ma), mnb = fmaxf(m_b, mb);
            float aa = ex2(m_a - mna), ab = ex2(m_b - mnb);
            m_a = mna; m_b = mnb;
            #pragma unroll
            for (int nt = 0; nt < 8; nt++) {
                c[nt][0] = ex2(c[nt][0] - mna);
                c[nt][1] = ex2(c[nt][1] - mna);
                c[nt][2] = ex2(c[nt][2] - mnb);
                c[nt][3] = ex2(c[nt][3] - mnb);
            }
            #pragma unroll
            for (int nt = 0; nt < 9; nt++) {
                o[nt][0] *= aa; o[nt][1] *= aa;
                o[nt][2] *= ab; o[nt][3] *= ab;
            }

            // O += P V'   (V' col 64 = ones -> o[8][0]/[2] accumulate l)
            #pragma unroll
            for (int t = 0; t < 4; t++) {
                uint32_t pa[4];
                pa[0] = packh2(c[2 * t][0],     c[2 * t][1]);
                pa[1] = packh2(c[2 * t][2],     c[2 * t][3]);
                pa[2] = packh2(c[2 * t + 1][0], c[2 * t + 1][1]);
                pa[3] = packh2(c[2 * t + 1][2], c[2 * t + 1][3]);
                #pragma unroll
                for (int p = 0; p < 5; p++) {
                    uint32_t vb[4];
                    uint32_t vo = (uint32_t)((t * 16 + (mat & 1) * 8 + (l & 7)) * VPF
                                             + p * 16 + (mat >> 1) * 8) * 2;
                    LDSM_X4_T(vb, aV + vo);
                    MMA16816H(o[2 * p], pa, vb[0], vb[1]);
                    if (p < 4)
                        MMA16816H(o[2 * p + 1], pa, vb[2], vb[3]);
                }
            }
        }
    }

    // l lives in lane (l & ~3) of each quad (column 64): broadcast.
    float l_a = __shfl_sync(0xffffffffu, o[8][0], l & ~3);
    float l_b = __shfl_sync(0xffffffffu, o[8][2], l & ~3);

    // Epilogue: fp16 attn output (A operand of out-proj)
    const float ia = 1.f / l_a, ib = 1.f / l_b;
    const int row = (b * TT + qt * 128 + w * 16 + (l >> 2));
    const int col = h * 64 + (l & 3) * 2;
    #pragma unroll
    for (int nt = 0; nt < 8; nt++) {
        *(__half2*)(o16 + (size_t)row * DA + col + nt * 8) =
            __floats2half2_rn(o[nt][0] * ia, o[nt][1] * ia);
        *(__half2*)(o16 + (size_t)(row + 8) * DA + col + nt * 8) =
            __floats2half2_rn(o[nt][2] * ib, o[nt][3] * ib);
    }
}

// ---------------------------------------------------------------------------
// Launch
// ---------------------------------------------------------------------------
extern "C" void kernel_launch(void* const* d_in, const int* in_sizes, int n_in,
                              void* d_out, int out_size)
{
    const float* x    = (const float*)d_in[0];
    const float* Wqkv = (const float*)d_in[2];
    const float* bqkv = (const float*)d_in[3];
    const float* Wout = (const float*)d_in[4];
    const float* bout = (const float*)d_in[5];
    float* out = (float*)d_out;

    __half *a16, *b16, *q16, *k16, *vh;
    cudaGetSymbolAddress((void**)&a16, g_a16);
    cudaGetSymbolAddress((void**)&b16, g_b16);
    cudaGetSymbolAddress((void**)&q16, g_q16);
    cudaGetSymbolAddress((void**)&k16, g_k16);
    cudaGetSymbolAddress((void**)&vh, g_vh);

    cudaFuncSetAttribute(gemm_mma,
                         cudaFuncAttributeMaxDynamicSharedMemorySize, (int)GEMM_DYN);
    cudaFuncSetAttribute(gemm_qkv,
                         cudaFuncAttributeMaxDynamicSharedMemorySize, (int)GEMM_DYN);
    cudaFuncSetAttribute(flash_mma,
                         cudaFuncAttributeMaxDynamicSharedMemorySize, (int)FL_DYN);

    // Phase 1: QKV = x @ Wqkv + b (fp16 operands), fused fp16 epilogue
    conv_f16<<<(MM * CCH / 4 + 255) / 256, 256>>>(x, a16, MM * CCH / 4);
    transpose_f16<<<dim3(3 * DA / 32, CCH / 32), dim3(32, 8)>>>(Wqkv, b16, CCH, 3 * DA);
    gemm_qkv<<<dim3(3 * DA / 128, MM / 128), 256, GEMM_DYN>>>(
        a16, b16, bqkv, q16, k16, vh);

    // Phase 2: tensor-core flash (fp16, base-2 softmax, MMA-computed l)
    flash_mma<<<dim3(TT / 128, NH, BV), 256, FL_DYN>>>(
        q16, k16, vh, a16);

    // Phase 3: out = attn @ Wout + b (fp16 operands)
    transpose_f16<<<dim3(CCH / 32, DA / 32), dim3(32, 8)>>>(Wout, b16, DA, CCH);
    gemm_mma<<<dim3(CCH / 128, MM / 128), 256, GEMM_DYN>>>(
        a16, b16, bout, out, MM, CCH, DA);
}